// round 5
// baseline (speedup 1.0000x reference)
#include <cuda_runtime.h>
#include <math.h>

#define T_    4096
#define D_    1024
#define H_    16
#define E_    8
#define CAP_  1024
#define MLP_  4096

// ---------------- device scratch (no allocs allowed) ----------------
__device__ float g_h[(size_t)T_ * D_];
__device__ float g_xin[(size_t)E_ * CAP_ * D_];
__device__ float g_qkv[3ull * 4 * CAP_ * D_];
__device__ float g_attno[4ull * CAP_ * D_];
__device__ float g_expo[(size_t)E_ * CAP_ * D_];
__device__ float g_ffh[4ull * CAP_ * MLP_];
__device__ float g_probs[T_ * 8];
__device__ unsigned char g_maskb[T_];
__device__ int   g_slottok[E_ * CAP_];
__device__ int   g_slotof[E_ * T_];
__device__ float g_cw[T_ * 8];
__device__ int   g_nsel[E_];

// ---------------- embedding ----------------
__global__ void embed_kernel(const int* __restrict__ ids, const float* __restrict__ ew) {
    int t = blockIdx.x, tid = threadIdx.x;
    ((float4*)(g_h + (size_t)t * D_))[tid] =
        ((const float4*)(ew + (size_t)ids[t] * D_))[tid];
}

// ---------------- router: one warp per token ----------------
__global__ void router_kernel(const float* __restrict__ rw) {
    int gw = (blockIdx.x * blockDim.x + threadIdx.x) >> 5;
    int lane = threadIdx.x & 31;
    if (gw >= T_) return;
    const float* hr = g_h + (size_t)gw * D_;
    float acc[9];
#pragma unroll
    for (int e = 0; e < 9; e++) acc[e] = 0.f;
    for (int d = lane; d < D_; d += 32) {
        float hv = hr[d];
#pragma unroll
        for (int e = 0; e < 9; e++) acc[e] = fmaf(hv, rw[e * D_ + d], acc[e]);
    }
#pragma unroll
    for (int e = 0; e < 9; e++)
#pragma unroll
        for (int o = 16; o > 0; o >>= 1) acc[e] += __shfl_xor_sync(0xffffffffu, acc[e], o);
    if (lane == 0) {
        float mx = acc[0];
#pragma unroll
        for (int e = 1; e < 9; e++) mx = fmaxf(mx, acc[e]);
        float ex[9], s = 0.f;
#pragma unroll
        for (int e = 0; e < 9; e++) { ex[e] = expf(acc[e] - mx); s += ex[e]; }
        float inv = 1.f / s;
        int a1 = 0; float v1 = acc[0];
#pragma unroll
        for (int e = 1; e < 9; e++) if (acc[e] > v1) { v1 = acc[e]; a1 = e; }
        int a2 = -1; float v2 = -3.0e38f;
#pragma unroll
        for (int e = 0; e < 9; e++) if (e != a1 && acc[e] > v2) { v2 = acc[e]; a2 = e; }
        unsigned char m = 0;
        if (a1 < 8) m |= (unsigned char)(1 << a1);
        if (a2 < 8) m |= (unsigned char)(1 << a2);
        g_maskb[gw] = m;
#pragma unroll
        for (int e = 0; e < 8; e++) g_probs[gw * 8 + e] = ex[e] * inv;
    }
}

// ---------------- capacity select: bitonic top-1024 per expert ----------------
__global__ void __launch_bounds__(1024) capacity_kernel() {
    int e = blockIdx.x, tid = threadIdx.x;
    __shared__ unsigned long long keys[T_];
    __shared__ int s_count;
    if (tid == 0) s_count = 0;
    __syncthreads();
    int local = 0;
    for (int t = tid; t < T_; t += 1024) {
        unsigned long long key = 0ull;
        if (g_maskb[t] & (1 << e)) {
            unsigned pb = __float_as_uint(g_probs[t * 8 + e]);
            key = ((unsigned long long)pb << 32) | (unsigned)(0xFFFFFFFFu - (unsigned)t);
            local++;
        }
        keys[t] = key;
    }
#pragma unroll
    for (int o = 16; o > 0; o >>= 1) local += __shfl_xor_sync(0xffffffffu, local, o);
    if ((tid & 31) == 0) atomicAdd(&s_count, local);
    __syncthreads();
    for (int k = 2; k <= T_; k <<= 1)
        for (int j = k >> 1; j > 0; j >>= 1) {
            for (int i = tid; i < T_; i += 1024) {
                int ixj = i ^ j;
                if (ixj > i) {
                    unsigned long long a = keys[i], b = keys[ixj];
                    bool desc = ((i & k) == 0);
                    if (desc ? (a < b) : (a > b)) { keys[i] = b; keys[ixj] = a; }
                }
            }
            __syncthreads();
        }
    int nsel = min(s_count, CAP_);
    if (tid == 0) g_nsel[e] = nsel;
    for (int t = tid; t < T_; t += 1024) { g_slotof[e * T_ + t] = -1; g_cw[t * 8 + e] = 0.f; }
    __syncthreads();
    int c = tid; // CAP_ == blockDim
    if (c < nsel) {
        unsigned long long key = keys[c];
        int tok = (int)(0xFFFFFFFFu - (unsigned)(key & 0xFFFFFFFFull));
        g_slottok[e * CAP_ + c] = tok;
        g_slotof[e * T_ + tok] = c;
        g_cw[tok * 8 + e] = __uint_as_float((unsigned)(key >> 32));
    } else if (c < CAP_) {
        g_slottok[e * CAP_ + c] = 0;
    }
}

// ---------------- gather expert inputs (zero pad) ----------------
__global__ void gather_kernel() {
    int row = blockIdx.x, e = row >> 10, c = row & 1023, tid = threadIdx.x;
    float4* dst = (float4*)(g_xin + (size_t)row * D_);
    if (c < g_nsel[e])
        dst[tid] = ((const float4*)(g_h + (size_t)g_slottok[row] * D_))[tid];
    else
        dst[tid] = make_float4(0.f, 0.f, 0.f, 0.f);
}

// ---------------- SGEMM 128x128x8, 8x8 microtiles, 256 thr ----------------
#define BM 128
#define BN 128
#define BK 8

__device__ __forceinline__ float gelu_f(float x) {
    float x3 = x * x * x;
    return 0.5f * x * (1.f + tanhf(0.7978845608028654f * (x + 0.044715f * x3)));
}

__device__ __forceinline__ void sgemm_body(
    const float* __restrict__ A, const float* __restrict__ B, float* __restrict__ C,
    int N, int K, int act)
{
    __shared__ float As[BK][BM];
    __shared__ float Bs[BK][BN];
    int tid = threadIdx.x;
    int brow = blockIdx.y * BM, bcol = blockIdx.x * BN;
    int tr = (tid >> 4) * 8, tc = (tid & 15) * 8;
    int arow = tid >> 1, acol = (tid & 1) * 4;
    int brl = tid >> 5, bcl = (tid & 31) * 4;
    const float* Ap = A + (size_t)(brow + arow) * K + acol;
    const float* Bp = B + (size_t)brl * N + bcol + bcl;
    float acc[8][8];
#pragma unroll
    for (int i = 0; i < 8; i++)
#pragma unroll
        for (int j = 0; j < 8; j++) acc[i][j] = 0.f;
    for (int k0 = 0; k0 < K; k0 += BK) {
        float4 av = *(const float4*)(Ap + k0);
        As[acol + 0][arow] = av.x; As[acol + 1][arow] = av.y;
        As[acol + 2][arow] = av.z; As[acol + 3][arow] = av.w;
        *(float4*)&Bs[brl][bcl] = *(const float4*)(Bp + (size_t)k0 * N);
        __syncthreads();
#pragma unroll
        for (int kk = 0; kk < BK; kk++) {
            float ra[8], rb[8];
            *(float4*)&ra[0] = *(const float4*)&As[kk][tr];
            *(float4*)&ra[4] = *(const float4*)&As[kk][tr + 4];
            *(float4*)&rb[0] = *(const float4*)&Bs[kk][tc];
            *(float4*)&rb[4] = *(const float4*)&Bs[kk][tc + 4];
#pragma unroll
            for (int i = 0; i < 8; i++)
#pragma unroll
                for (int j = 0; j < 8; j++)
                    acc[i][j] = fmaf(ra[i], rb[j], acc[i][j]);
        }
        __syncthreads();
    }
#pragma unroll
    for (int i = 0; i < 8; i++) {
        size_t co = (size_t)(brow + tr + i) * N + bcol + tc;
#pragma unroll
        for (int j = 0; j < 8; j += 4) {
            float4 v = make_float4(acc[i][j], acc[i][j + 1], acc[i][j + 2], acc[i][j + 3]);
            if (act) { v.x = gelu_f(v.x); v.y = gelu_f(v.y); v.z = gelu_f(v.z); v.w = gelu_f(v.w); }
            *(float4*)(C + co + j) = v;
        }
    }
}

__global__ void __launch_bounds__(256) sgemm_kernel(
    const float* __restrict__ A, const float* __restrict__ B, float* __restrict__ C,
    int N, int K, long long sA, long long sB, long long sC, int act)
{
    sgemm_body(A + (size_t)blockIdx.z * sA, B + (size_t)blockIdx.z * sB,
               C + (size_t)blockIdx.z * sC, N, K, act);
}

__global__ void __launch_bounds__(256) sgemm_qkv_kernel(
    const float* __restrict__ wq, const float* __restrict__ wk, const float* __restrict__ wv)
{
    int z = blockIdx.z, which = z >> 2, g = z & 3;
    const float* A = g_xin + (size_t)g * 2 * CAP_ * D_;
    const float* B = (which == 0 ? wq : (which == 1 ? wk : wv)) + (size_t)g * D_ * D_;
    float* C = g_qkv + ((size_t)which * 4 + g) * CAP_ * D_;
    sgemm_body(A, B, C, D_, D_, 0);
}

// ---------------- RoPE in place on Q,K ----------------
__global__ void rope_kernel() {
    int row = blockIdx.x, g = row >> 10, c = row & 1023, tid = threadIdx.x;
    float pos = (float)g_slottok[(2 * g) * CAP_ + c];
    float* q = g_qkv + (size_t)row * D_;
    float* k = g_qkv + 4ull * CAP_ * D_ + (size_t)row * D_;
    for (int idx = tid; idx < 512; idx += 256) {
        int hh = idx >> 5, d0 = idx & 31;
        float invf = (float)exp(-(double)(2 * d0) / 64.0 * 9.210340371976184);
        float ang = pos * invf;
        float cs = cosf(ang), sn = sinf(ang);
        int b = hh * 64 + d0;
        float a0 = q[b], a1 = q[b + 32];
        q[b] = a0 * cs - a1 * sn; q[b + 32] = a1 * cs + a0 * sn;
        float b0 = k[b], b1 = k[b + 32];
        k[b] = b0 * cs - b1 * sn; k[b + 32] = b1 * cs + b0 * sn;
    }
}

// ---------------- fused flash attention, dense over 1024 padded keys ----------------
#define ALD 65
#define ATTN_SMEM ((4 * 64 * ALD + 3 * 64) * 4)

__global__ void __launch_bounds__(256) attn_kernel() {
    int qb = blockIdx.x, hh = blockIdx.y, g = blockIdx.z;
    extern __shared__ float sm[];
    float* Qs = sm;
    float* Ks = Qs + 64 * ALD;
    float* Vs = Ks + 64 * ALD;
    float* Ps = Vs + 64 * ALD;
    float* rm = Ps + 64 * ALD;
    float* rl = rm + 64;
    float* rc = rl + 64;
    int tid = threadIdx.x;
    int q0 = (tid >> 4) * 4, x0 = (tid & 15) * 4;
    const float* Qg = g_qkv + ((size_t)(g * CAP_ + qb * 64)) * D_ + hh * 64;
    for (int it = tid; it < 1024; it += 256) {
        int r = it >> 4, c4 = (it & 15) << 2;
        float4 v = *(const float4*)(Qg + (size_t)r * D_ + c4);
        float* d = &Qs[r * ALD + c4];
        d[0] = v.x; d[1] = v.y; d[2] = v.z; d[3] = v.w;
    }
    if (tid < 64) { rm[tid] = -3.0e38f; rl[tid] = 0.f; }
    float o[4][4];
#pragma unroll
    for (int i = 0; i < 4; i++)
#pragma unroll
        for (int j = 0; j < 4; j++) o[i][j] = 0.f;

    for (int kt = 0; kt < 16; kt++) {
        __syncthreads();
        const float* Kg = g_qkv + 4ull * CAP_ * D_ + ((size_t)(g * CAP_ + kt * 64)) * D_ + hh * 64;
        const float* Vg = g_qkv + 8ull * CAP_ * D_ + ((size_t)(g * CAP_ + kt * 64)) * D_ + hh * 64;
        for (int it = tid; it < 1024; it += 256) {
            int r = it >> 4, c4 = (it & 15) << 2;
            float4 v = *(const float4*)(Kg + (size_t)r * D_ + c4);
            float* d = &Ks[r * ALD + c4];
            d[0] = v.x; d[1] = v.y; d[2] = v.z; d[3] = v.w;
            float4 w = *(const float4*)(Vg + (size_t)r * D_ + c4);
            float* d2 = &Vs[r * ALD + c4];
            d2[0] = w.x; d2[1] = w.y; d2[2] = w.z; d2[3] = w.w;
        }
        __syncthreads();
        float s[4][4];
#pragma unroll
        for (int i = 0; i < 4; i++)
#pragma unroll
            for (int j = 0; j < 4; j++) s[i][j] = 0.f;
        for (int d = 0; d < 64; d++) {
            float ra[4], rb[4];
#pragma unroll
            for (int i = 0; i < 4; i++) ra[i] = Qs[(q0 + i) * ALD + d];
#pragma unroll
            for (int j = 0; j < 4; j++) rb[j] = Ks[(x0 + j) * ALD + d];
#pragma unroll
            for (int i = 0; i < 4; i++)
#pragma unroll
                for (int j = 0; j < 4; j++) s[i][j] = fmaf(ra[i], rb[j], s[i][j]);
        }
#pragma unroll
        for (int i = 0; i < 4; i++)
#pragma unroll
            for (int j = 0; j < 4; j++) Ps[(q0 + i) * ALD + x0 + j] = s[i][j] * 0.125f;
        __syncthreads();
        if (tid < 64) {
            float* pr = &Ps[tid * ALD];
            float tmax = pr[0];
            for (int k2 = 1; k2 < 64; k2++) tmax = fmaxf(tmax, pr[k2]);
            float mold = rm[tid], mnew = fmaxf(mold, tmax);
            float corr = expf(mold - mnew);
            float sum = 0.f;
            for (int k2 = 0; k2 < 64; k2++) { float p = expf(pr[k2] - mnew); pr[k2] = p; sum += p; }
            rl[tid] = rl[tid] * corr + sum;
            rm[tid] = mnew;
            rc[tid] = corr;
        }
        __syncthreads();
        float cr[4];
#pragma unroll
        for (int i = 0; i < 4; i++) cr[i] = rc[q0 + i];
#pragma unroll
        for (int i = 0; i < 4; i++)
#pragma unroll
            for (int j = 0; j < 4; j++) o[i][j] *= cr[i];
        for (int kk = 0; kk < 64; kk++) {
            float pa[4], vb[4];
#pragma unroll
            for (int i = 0; i < 4; i++) pa[i] = Ps[(q0 + i) * ALD + kk];
#pragma unroll
            for (int j = 0; j < 4; j++) vb[j] = Vs[kk * ALD + x0 + j];
#pragma unroll
            for (int i = 0; i < 4; i++)
#pragma unroll
                for (int j = 0; j < 4; j++) o[i][j] = fmaf(pa[i], vb[j], o[i][j]);
        }
    }
    __syncthreads();
    float* Og = g_attno + ((size_t)(g * CAP_ + qb * 64)) * D_ + hh * 64;
#pragma unroll
    for (int i = 0; i < 4; i++) {
        float inv = 1.f / rl[q0 + i];
        float4 v = make_float4(o[i][0] * inv, o[i][1] * inv, o[i][2] * inv, o[i][3] * inv);
        *(float4*)(Og + (size_t)(q0 + i) * D_ + x0) = v;
    }
}

// ---------------- combine: h = (1-rho)h + sum_e w_e expo[e,slot] ----------------
__global__ void combine_kernel() {
    int t = blockIdx.x, tid = threadIdx.x;
    __shared__ float scw[8];
    __shared__ int ssl[8];
    if (tid < 8) { scw[tid] = g_cw[t * 8 + tid]; ssl[tid] = g_slotof[tid * T_ + t]; }
    __syncthreads();
    float4* hr = (float4*)(g_h + (size_t)t * D_);
    float4 hv = hr[tid];
    float rho = 0.f;
    float4 acc = make_float4(0.f, 0.f, 0.f, 0.f);
#pragma unroll
    for (int e = 0; e < 8; e++) {
        int s = ssl[e];
        if (s >= 0) {
            float w = scw[e];
            rho += w;
            float4 ev = ((const float4*)(g_expo + ((size_t)e * CAP_ + s) * D_))[tid];
            acc.x = fmaf(w, ev.x, acc.x); acc.y = fmaf(w, ev.y, acc.y);
            acc.z = fmaf(w, ev.z, acc.z); acc.w = fmaf(w, ev.w, acc.w);
        }
    }
    float om = 1.f - rho;
    hv.x = hv.x * om + acc.x; hv.y = hv.y * om + acc.y;
    hv.z = hv.z * om + acc.z; hv.w = hv.w * om + acc.w;
    hr[tid] = hv;
}

// ---------------- final RMSNorm ----------------
__global__ void rmsnorm_kernel(const float* __restrict__ lnw, float* __restrict__ out) {
    int t = blockIdx.x, tid = threadIdx.x;
    float4 v = ((const float4*)(g_h + (size_t)t * D_))[tid];
    float ss = v.x * v.x + v.y * v.y + v.z * v.z + v.w * v.w;
#pragma unroll
    for (int o = 16; o > 0; o >>= 1) ss += __shfl_xor_sync(0xffffffffu, ss, o);
    __shared__ float red[8];
    if ((tid & 31) == 0) red[tid >> 5] = ss;
    __syncthreads();
    if (tid == 0) {
        float s = 0.f;
        for (int i = 0; i < 8; i++) s += red[i];
        red[0] = rsqrtf(s / (float)D_ + 1e-6f);
    }
    __syncthreads();
    float sc = red[0];
    float4 w = ((const float4*)lnw)[tid];
    float4 o4 = make_float4(v.x * sc * w.x, v.y * sc * w.y, v.z * sc * w.z, v.w * sc * w.w);
    ((float4*)out)[(size_t)t * 256 + tid] = o4;
}

// ---------------- launch ----------------
extern "C" void kernel_launch(void* const* d_in, const int* in_sizes, int n_in,
                              void* d_out, int out_size) {
    const int*   ids      = (const int*)d_in[0];
    const float* embed_w  = (const float*)d_in[1];
    const float* router_w = (const float*)d_in[2];
    const float* wq       = (const float*)d_in[3];
    const float* wk       = (const float*)d_in[4];
    const float* wv       = (const float*)d_in[5];
    const float* wo       = (const float*)d_in[6];
    const float* w1       = (const float*)d_in[7];
    const float* w2       = (const float*)d_in[8];
    const float* lnw      = (const float*)d_in[9];
    float* out = (float*)d_out;

    float *p_xin, *p_attno, *p_expo, *p_ffh;
    cudaGetSymbolAddress((void**)&p_xin, g_xin);
    cudaGetSymbolAddress((void**)&p_attno, g_attno);
    cudaGetSymbolAddress((void**)&p_expo, g_expo);
    cudaGetSymbolAddress((void**)&p_ffh, g_ffh);
    cudaFuncSetAttribute(attn_kernel, cudaFuncAttributeMaxDynamicSharedMemorySize, ATTN_SMEM);

    embed_kernel<<<T_, 256>>>(ids, embed_w);
    for (int hop = 0; hop < 3; hop++) {
        router_kernel<<<T_ / 8, 256>>>(router_w + (size_t)hop * 9 * D_);
        capacity_kernel<<<E_, 1024>>>();
        gather_kernel<<<E_ * CAP_, 256>>>();
        // QKV for 4 attention groups (12 GEMMs fused in z)
        sgemm_qkv_kernel<<<dim3(D_ / BN, CAP_ / BM, 12), 256>>>(wq, wk, wv);
        rope_kernel<<<4 * CAP_, 256>>>();
        attn_kernel<<<dim3(16, 16, 4), 256, ATTN_SMEM>>>();
        // Wo: attno @ wo[g] -> expo[2g]
        sgemm_kernel<<<dim3(D_ / BN, CAP_ / BM, 4), 256>>>(
            p_attno, wo, p_expo, D_, D_,
            (long long)CAP_ * D_, (long long)D_ * D_, 2LL * CAP_ * D_, 0);
        // FFN1: xin[2g+1] @ w1[g] -> gelu -> ffh
        sgemm_kernel<<<dim3(MLP_ / BN, CAP_ / BM, 4), 256>>>(
            p_xin + (size_t)CAP_ * D_, w1, p_ffh, MLP_, D_,
            2LL * CAP_ * D_, (long long)D_ * MLP_, (long long)CAP_ * MLP_, 1);
        // FFN2: ffh @ w2[g] -> expo[2g+1]
        sgemm_kernel<<<dim3(D_ / BN, CAP_ / BM, 4), 256>>>(
            p_ffh, w2, p_expo + (size_t)CAP_ * D_, D_, MLP_,
            (long long)CAP_ * MLP_, (long long)MLP_ * D_, 2LL * CAP_ * D_, 0);
        combine_kernel<<<T_, 256>>>();
    }
    rmsnorm_kernel<<<T_, 256>>>(lnw, out);
}

// round 8
// speedup vs baseline: 1.7558x; 1.7558x over previous
#include <cuda_runtime.h>
#include <cuda_bf16.h>
#include <cstdint>
#include <stdint.h>
#include <math.h>

#define T_    4096
#define D_    1024
#define E_    8
#define CAP_  1024
#define MLP_  4096

// ---------------- device scratch ----------------
__device__ float g_h[(size_t)T_ * D_];
__device__ float g_qkv[12ull * CAP_ * D_];
__device__ float g_expo[(size_t)E_ * CAP_ * D_];
__device__ float g_probs[T_ * 8];
__device__ unsigned char g_maskb[T_];
__device__ int   g_slottok[E_ * CAP_];
__device__ int   g_slotof[E_ * T_];
__device__ float g_cw[T_ * 8];
__device__ int   g_nsel[E_];

__device__ __nv_bfloat16 g_xh[(size_t)E_ * CAP_ * D_];
__device__ __nv_bfloat16 g_xl[(size_t)E_ * CAP_ * D_];
__device__ __nv_bfloat16 g_ah[4ull * CAP_ * D_];
__device__ __nv_bfloat16 g_al[4ull * CAP_ * D_];
__device__ __nv_bfloat16 g_fh[4ull * CAP_ * MLP_];
__device__ __nv_bfloat16 g_fl[4ull * CAP_ * MLP_];

#define WQ_OFF 0ull
#define WK_OFF 4194304ull
#define WV_OFF 8388608ull
#define WO_OFF 12582912ull
#define W1_OFF 16777216ull
#define W2_OFF 33554432ull
#define WT_TOT 50331648ull
__device__ __nv_bfloat16 g_wth[WT_TOT];
__device__ __nv_bfloat16 g_wtl[WT_TOT];

// ---------------- helpers ----------------
__device__ __forceinline__ void split_bf(float x, __nv_bfloat16& h, __nv_bfloat16& l) {
    h = __float2bfloat16(x);
    l = __float2bfloat16(x - __bfloat162float(h));
}
__device__ __forceinline__ float gelu_f(float x) {
    float x3 = x * x * x;
    return 0.5f * x * (1.f + tanhf(0.7978845608028654f * (x + 0.044715f * x3)));
}
__device__ __forceinline__ void mma16816(float* d, const uint32_t* a, const uint32_t* b) {
    asm volatile(
        "mma.sync.aligned.m16n8k16.row.col.f32.bf16.bf16.f32 "
        "{%0,%1,%2,%3}, {%4,%5,%6,%7}, {%8,%9}, {%0,%1,%2,%3};"
        : "+f"(d[0]), "+f"(d[1]), "+f"(d[2]), "+f"(d[3])
        : "r"(a[0]), "r"(a[1]), "r"(a[2]), "r"(a[3]), "r"(b[0]), "r"(b[1]));
}
// swizzled shared tile: row r (0..127), 32 bf16/row in 4 x 16B chunks; chunk ch stored at ch^((r>>1)&3)
__device__ __forceinline__ uint32_t lds_frag(const __nv_bfloat16* base, int r, int c) {
    int ch = c >> 3;
    int sw = ch ^ ((r >> 1) & 3);
    return *(const uint32_t*)(base + r * 32 + sw * 8 + (c & 7));
}

// ---------------- embedding ----------------
__global__ void embed_kernel(const int* __restrict__ ids, const float* __restrict__ ew) {
    int t = blockIdx.x, tid = threadIdx.x;
    ((float4*)(g_h + (size_t)t * D_))[tid] =
        ((const float4*)(ew + (size_t)ids[t] * D_))[tid];
}

// ---------------- router ----------------
__global__ void router_kernel(const float* __restrict__ rw) {
    int gw = (blockIdx.x * blockDim.x + threadIdx.x) >> 5;
    int lane = threadIdx.x & 31;
    if (gw >= T_) return;
    const float* hr = g_h + (size_t)gw * D_;
    float acc[9];
#pragma unroll
    for (int e = 0; e < 9; e++) acc[e] = 0.f;
    for (int d = lane; d < D_; d += 32) {
        float hv = hr[d];
#pragma unroll
        for (int e = 0; e < 9; e++) acc[e] = fmaf(hv, rw[e * D_ + d], acc[e]);
    }
#pragma unroll
    for (int e = 0; e < 9; e++)
#pragma unroll
        for (int o = 16; o > 0; o >>= 1) acc[e] += __shfl_xor_sync(0xffffffffu, acc[e], o);
    if (lane == 0) {
        float mx = acc[0];
#pragma unroll
        for (int e = 1; e < 9; e++) mx = fmaxf(mx, acc[e]);
        float ex[9], s = 0.f;
#pragma unroll
        for (int e = 0; e < 9; e++) { ex[e] = expf(acc[e] - mx); s += ex[e]; }
        float inv = 1.f / s;
        int a1 = 0; float v1 = acc[0];
#pragma unroll
        for (int e = 1; e < 9; e++) if (acc[e] > v1) { v1 = acc[e]; a1 = e; }
        int a2 = -1; float v2 = -3.0e38f;
#pragma unroll
        for (int e = 0; e < 9; e++) if (e != a1 && acc[e] > v2) { v2 = acc[e]; a2 = e; }
        unsigned char m = 0;
        if (a1 < 8) m |= (unsigned char)(1 << a1);
        if (a2 < 8) m |= (unsigned char)(1 << a2);
        g_maskb[gw] = m;
#pragma unroll
        for (int e = 0; e < 8; e++) g_probs[gw * 8 + e] = ex[e] * inv;
    }
}

// ---------------- capacity select ----------------
__global__ void __launch_bounds__(1024) capacity_kernel() {
    int e = blockIdx.x, tid = threadIdx.x;
    __shared__ unsigned long long keys[T_];
    __shared__ int s_count;
    if (tid == 0) s_count = 0;
    __syncthreads();
    int local = 0;
    for (int t = tid; t < T_; t += 1024) {
        unsigned long long key = 0ull;
        if (g_maskb[t] & (1 << e)) {
            unsigned pb = __float_as_uint(g_probs[t * 8 + e]);
            key = ((unsigned long long)pb << 32) | (unsigned)(0xFFFFFFFFu - (unsigned)t);
            local++;
        }
        keys[t] = key;
    }
#pragma unroll
    for (int o = 16; o > 0; o >>= 1) local += __shfl_xor_sync(0xffffffffu, local, o);
    if ((tid & 31) == 0) atomicAdd(&s_count, local);
    __syncthreads();
    for (int k = 2; k <= T_; k <<= 1)
        for (int j = k >> 1; j > 0; j >>= 1) {
            for (int i = tid; i < T_; i += 1024) {
                int ixj = i ^ j;
                if (ixj > i) {
                    unsigned long long a = keys[i], b = keys[ixj];
                    bool desc = ((i & k) == 0);
                    if (desc ? (a < b) : (a > b)) { keys[i] = b; keys[ixj] = a; }
                }
            }
            __syncthreads();
        }
    int nsel = min(s_count, CAP_);
    if (tid == 0) g_nsel[e] = nsel;
    for (int t = tid; t < T_; t += 1024) { g_slotof[e * T_ + t] = -1; g_cw[t * 8 + e] = 0.f; }
    __syncthreads();
    int c = tid;
    if (c < nsel) {
        unsigned long long key = keys[c];
        int tok = (int)(0xFFFFFFFFu - (unsigned)(key & 0xFFFFFFFFull));
        g_slottok[e * CAP_ + c] = tok;
        g_slotof[e * T_ + tok] = c;
        g_cw[tok * 8 + e] = __uint_as_float((unsigned)(key >> 32));
    } else if (c < CAP_) {
        g_slottok[e * CAP_ + c] = 0;
    }
}

// ---------------- gather -> bf16 hi/lo ----------------
__global__ void gather_kernel() {
    int row = blockIdx.x, e = row >> 10, c = row & 1023, tid = threadIdx.x;
    float4 v = make_float4(0.f, 0.f, 0.f, 0.f);
    if (c < g_nsel[e])
        v = ((const float4*)(g_h + (size_t)g_slottok[row] * D_))[tid];
    __nv_bfloat16 h0, h1, h2, h3, l0, l1, l2, l3;
    split_bf(v.x, h0, l0); split_bf(v.y, h1, l1);
    split_bf(v.z, h2, l2); split_bf(v.w, h3, l3);
    __nv_bfloat162* dh = (__nv_bfloat162*)(g_xh + (size_t)row * D_) + 2 * tid;
    __nv_bfloat162* dl = (__nv_bfloat162*)(g_xl + (size_t)row * D_) + 2 * tid;
    dh[0] = __halves2bfloat162(h0, h1); dh[1] = __halves2bfloat162(h2, h3);
    dl[0] = __halves2bfloat162(l0, l1); dl[1] = __halves2bfloat162(l2, l3);
}

// ---------------- weight transpose + bf16 split: W[K][N] -> WT[N][K] ----------------
__global__ void wconv_kernel(const float* __restrict__ W, __nv_bfloat16* __restrict__ Th,
                             __nv_bfloat16* __restrict__ Tl, int K, int N) {
    __shared__ float t[32][33];
    int z = blockIdx.z;
    size_t base = (size_t)z * K * N;
    int n0 = blockIdx.x * 32, k0 = blockIdx.y * 32;
    int tx = threadIdx.x & 31, ty = threadIdx.x >> 5;
#pragma unroll
    for (int r = 0; r < 32; r += 8)
        t[ty + r][tx] = W[base + (size_t)(k0 + ty + r) * N + n0 + tx];
    __syncthreads();
#pragma unroll
    for (int r = 0; r < 32; r += 8) {
        float v = t[tx][ty + r];
        __nv_bfloat16 h, l; split_bf(v, h, l);
        size_t o = base + (size_t)(n0 + ty + r) * K + k0 + tx;
        Th[o] = h; Tl[o] = l;
    }
}

// ---------------- mma.sync GEMM: C[128,128] = A[M,K] @ BT[N,K]^T, 3-split bf16 ----------------
// 256 threads = 8 warps (2m x 4n), warp tile 64x32, BK=32.
__device__ __forceinline__ void store_tile(__nv_bfloat16* s, const __nv_bfloat16* __restrict__ g,
                                           int K, int k0, int tid) {
#pragma unroll
    for (int q = 0; q < 2; q++) {
        int i = tid * 2 + q;              // 0..511
        int r = i >> 2, ch = i & 3;
        int sw = ch ^ ((r >> 1) & 3);
        *(uint4*)(s + r * 32 + sw * 8) =
            *(const uint4*)(g + (size_t)r * K + k0 + ch * 8);
    }
}

__device__ __forceinline__ void gemm_mma_body(
    const __nv_bfloat16* __restrict__ Ah, const __nv_bfloat16* __restrict__ Al,
    const __nv_bfloat16* __restrict__ Bh, const __nv_bfloat16* __restrict__ Bl,
    float* Cf, __nv_bfloat16* Ch, __nv_bfloat16* Cl, int N, int K, int act)
{
    __shared__ __nv_bfloat16 sAh[128 * 32], sAl[128 * 32], sBh[128 * 32], sBl[128 * 32];
    int tid = threadIdx.x, lane = tid & 31, warp = tid >> 5;
    int wm = (warp & 1) * 64, wn = (warp >> 1) * 32;
    int brow = blockIdx.y * 128, bcol = blockIdx.x * 128;
    const __nv_bfloat16* pAh = Ah + (size_t)brow * K;
    const __nv_bfloat16* pAl = Al + (size_t)brow * K;
    const __nv_bfloat16* pBh = Bh + (size_t)bcol * K;
    const __nv_bfloat16* pBl = Bl + (size_t)bcol * K;

    float acc[4][4][4];
#pragma unroll
    for (int i = 0; i < 4; i++)
#pragma unroll
        for (int j = 0; j < 4; j++)
#pragma unroll
            for (int d = 0; d < 4; d++) acc[i][j][d] = 0.f;

    int g = lane >> 2, t4 = lane & 3;

    for (int k0 = 0; k0 < K; k0 += 32) {
        __syncthreads();
        store_tile(sAh, pAh, K, k0, tid);
        store_tile(sAl, pAl, K, k0, tid);
        store_tile(sBh, pBh, K, k0, tid);
        store_tile(sBl, pBl, K, k0, tid);
        __syncthreads();
#pragma unroll
        for (int kc = 0; kc < 2; kc++) {
            int cb = kc * 16 + t4 * 2;
            uint32_t bh[4][2], bl[4][2];
#pragma unroll
            for (int tn = 0; tn < 4; tn++) {
                int n = wn + tn * 8 + g;
                bh[tn][0] = lds_frag(sBh, n, cb);
                bh[tn][1] = lds_frag(sBh, n, cb + 8);
                bl[tn][0] = lds_frag(sBl, n, cb);
                bl[tn][1] = lds_frag(sBl, n, cb + 8);
            }
#pragma unroll
            for (int tm = 0; tm < 4; tm++) {
                int r = wm + tm * 16 + g;
                uint32_t ah[4], al[4];
                ah[0] = lds_frag(sAh, r, cb);     ah[1] = lds_frag(sAh, r + 8, cb);
                ah[2] = lds_frag(sAh, r, cb + 8); ah[3] = lds_frag(sAh, r + 8, cb + 8);
                al[0] = lds_frag(sAl, r, cb);     al[1] = lds_frag(sAl, r + 8, cb);
                al[2] = lds_frag(sAl, r, cb + 8); al[3] = lds_frag(sAl, r + 8, cb + 8);
#pragma unroll
                for (int tn = 0; tn < 4; tn++) {
                    mma16816(acc[tm][tn], ah, bh[tn]);
                    mma16816(acc[tm][tn], ah, bl[tn]);
                    mma16816(acc[tm][tn], al, bh[tn]);
                }
            }
        }
    }

    // epilogue: d0,d1 -> (r, c),(r,c+1); d2,d3 -> (r+8, c),(r+8,c+1)
#pragma unroll
    for (int tm = 0; tm < 4; tm++) {
        int r = brow + wm + tm * 16 + g;
#pragma unroll
        for (int tn = 0; tn < 4; tn++) {
            int c = bcol + wn + tn * 8 + t4 * 2;
            float v0 = acc[tm][tn][0], v1 = acc[tm][tn][1];
            float v2 = acc[tm][tn][2], v3 = acc[tm][tn][3];
            if (Cf) {
                *(float2*)(Cf + (size_t)r * N + c) = make_float2(v0, v1);
                *(float2*)(Cf + (size_t)(r + 8) * N + c) = make_float2(v2, v3);
            } else {
                if (act) { v0 = gelu_f(v0); v1 = gelu_f(v1); v2 = gelu_f(v2); v3 = gelu_f(v3); }
                __nv_bfloat16 h0, l0, h1, l1, h2, l2, h3, l3;
                split_bf(v0, h0, l0); split_bf(v1, h1, l1);
                split_bf(v2, h2, l2); split_bf(v3, h3, l3);
                *(__nv_bfloat162*)(Ch + (size_t)r * N + c) = __halves2bfloat162(h0, h1);
                *(__nv_bfloat162*)(Cl + (size_t)r * N + c) = __halves2bfloat162(l0, l1);
                *(__nv_bfloat162*)(Ch + (size_t)(r + 8) * N + c) = __halves2bfloat162(h2, h3);
                *(__nv_bfloat162*)(Cl + (size_t)(r + 8) * N + c) = __halves2bfloat162(l2, l3);
            }
        }
    }
}

__global__ void __launch_bounds__(256, 2) gemm_mma(
    const __nv_bfloat16* Ah, const __nv_bfloat16* Al,
    const __nv_bfloat16* Bh, const __nv_bfloat16* Bl,
    float* Cf, __nv_bfloat16* Ch, __nv_bfloat16* Cl,
    int N, int K, long long sA, long long sB, long long sC, int act)
{
    long long z = blockIdx.z;
    gemm_mma_body(Ah + z * sA, Al + z * sA, Bh + z * sB, Bl + z * sB,
                  Cf ? Cf + z * sC : (float*)0,
                  Ch ? Ch + z * sC : (__nv_bfloat16*)0,
                  Cl ? Cl + z * sC : (__nv_bfloat16*)0, N, K, act);
}

__global__ void __launch_bounds__(256, 2) gemm_qkv_mma() {
    int z = blockIdx.z, which = z >> 2, g = z & 3;
    size_t ao = (size_t)(2 * g) * CAP_ * D_;
    size_t wo = (size_t)which * 4194304ull + (size_t)g * 1048576ull;
    gemm_mma_body(g_xh + ao, g_xl + ao, g_wth + wo, g_wtl + wo,
                  g_qkv + ((size_t)which * 4 + g) * CAP_ * D_,
                  (__nv_bfloat16*)0, (__nv_bfloat16*)0, D_, D_, 0);
}

// ---------------- RoPE ----------------
__global__ void rope_kernel() {
    int row = blockIdx.x, g = row >> 10, c = row & 1023, tid = threadIdx.x;
    float pos = (float)g_slottok[(2 * g) * CAP_ + c];
    float* q = g_qkv + (size_t)row * D_;
    float* k = g_qkv + 4ull * CAP_ * D_ + (size_t)row * D_;
    for (int idx = tid; idx < 512; idx += 256) {
        int hh = idx >> 5, d0 = idx & 31;
        float invf = (float)exp(-(double)(2 * d0) / 64.0 * 9.210340371976184);
        float ang = pos * invf;
        float cs = cosf(ang), sn = sinf(ang);
        int b = hh * 64 + d0;
        float a0 = q[b], a1 = q[b + 32];
        q[b] = a0 * cs - a1 * sn; q[b + 32] = a1 * cs + a0 * sn;
        float b0 = k[b], b1 = k[b + 32];
        k[b] = b0 * cs - b1 * sn; k[b + 32] = b1 * cs + b0 * sn;
    }
}

// ---------------- fp32 flash attention (writes bf16 hi/lo) ----------------
#define ALD 65
#define ATTN_SMEM ((4 * 64 * ALD + 3 * 64) * 4)

__global__ void __launch_bounds__(256) attn_kernel() {
    int qb = blockIdx.x, hh = blockIdx.y, g = blockIdx.z;
    extern __shared__ float sm[];
    float* Qs = sm;
    float* Ks = Qs + 64 * ALD;
    float* Vs = Ks + 64 * ALD;
    float* Ps = Vs + 64 * ALD;
    float* rm = Ps + 64 * ALD;
    float* rl = rm + 64;
    float* rc = rl + 64;
    int tid = threadIdx.x;
    int q0 = (tid >> 4) * 4, x0 = (tid & 15) * 4;
    const float* Qg = g_qkv + ((size_t)(g * CAP_ + qb * 64)) * D_ + hh * 64;
    for (int it = tid; it < 1024; it += 256) {
        int r = it >> 4, c4 = (it & 15) << 2;
        float4 v = *(const float4*)(Qg + (size_t)r * D_ + c4);
        float* d = &Qs[r * ALD + c4];
        d[0] = v.x; d[1] = v.y; d[2] = v.z; d[3] = v.w;
    }
    if (tid < 64) { rm[tid] = -3.0e38f; rl[tid] = 0.f; }
    float o[4][4];
#pragma unroll
    for (int i = 0; i < 4; i++)
#pragma unroll
        for (int j = 0; j < 4; j++) o[i][j] = 0.f;

    for (int kt = 0; kt < 16; kt++) {
        __syncthreads();
        const float* Kg = g_qkv + 4ull * CAP_ * D_ + ((size_t)(g * CAP_ + kt * 64)) * D_ + hh * 64;
        const float* Vg = g_qkv + 8ull * CAP_ * D_ + ((size_t)(g * CAP_ + kt * 64)) * D_ + hh * 64;
        for (int it = tid; it < 1024; it += 256) {
            int r = it >> 4, c4 = (it & 15) << 2;
            float4 v = *(const float4*)(Kg + (size_t)r * D_ + c4);
            float* d = &Ks[r * ALD + c4];
            d[0] = v.x; d[1] = v.y; d[2] = v.z; d[3] = v.w;
            float4 w = *(const float4*)(Vg + (size_t)r * D_ + c4);
            float* d2 = &Vs[r * ALD + c4];
            d2[0] = w.x; d2[1] = w.y; d2[2] = w.z; d2[3] = w.w;
        }
        __syncthreads();
        float s[4][4];
#pragma unroll
        for (int i = 0; i < 4; i++)
#pragma unroll
            for (int j = 0; j < 4; j++) s[i][j] = 0.f;
        for (int d = 0; d < 64; d++) {
            float ra[4], rb[4];
#pragma unroll
            for (int i = 0; i < 4; i++) ra[i] = Qs[(q0 + i) * ALD + d];
#pragma unroll
            for (int j = 0; j < 4; j++) rb[j] = Ks[(x0 + j) * ALD + d];
#pragma unroll
            for (int i = 0; i < 4; i++)
#pragma unroll
                for (int j = 0; j < 4; j++) s[i][j] = fmaf(ra[i], rb[j], s[i][j]);
        }
#pragma unroll
        for (int i = 0; i < 4; i++)
#pragma unroll
            for (int j = 0; j < 4; j++) Ps[(q0 + i) * ALD + x0 + j] = s[i][j] * 0.125f;
        __syncthreads();
        if (tid < 64) {
            float* pr = &Ps[tid * ALD];
            float tmax = pr[0];
            for (int k2 = 1; k2 < 64; k2++) tmax = fmaxf(tmax, pr[k2]);
            float mold = rm[tid], mnew = fmaxf(mold, tmax);
            float corr = expf(mold - mnew);
            float sum = 0.f;
            for (int k2 = 0; k2 < 64; k2++) { float p = expf(pr[k2] - mnew); pr[k2] = p; sum += p; }
            rl[tid] = rl[tid] * corr + sum;
            rm[tid] = mnew;
            rc[tid] = corr;
        }
        __syncthreads();
        float cr[4];
#pragma unroll
        for (int i = 0; i < 4; i++) cr[i] = rc[q0 + i];
#pragma unroll
        for (int i = 0; i < 4; i++)
#pragma unroll
            for (int j = 0; j < 4; j++) o[i][j] *= cr[i];
        for (int kk = 0; kk < 64; kk++) {
            float pa[4], vb[4];
#pragma unroll
            for (int i = 0; i < 4; i++) pa[i] = Ps[(q0 + i) * ALD + kk];
#pragma unroll
            for (int j = 0; j < 4; j++) vb[j] = Vs[kk * ALD + x0 + j];
#pragma unroll
            for (int i = 0; i < 4; i++)
#pragma unroll
                for (int j = 0; j < 4; j++) o[i][j] = fmaf(pa[i], vb[j], o[i][j]);
        }
    }
    __syncthreads();
    size_t obase = ((size_t)(g * CAP_ + qb * 64)) * D_ + hh * 64;
#pragma unroll
    for (int i = 0; i < 4; i++) {
        float inv = 1.f / rl[q0 + i];
        __nv_bfloat16 h0, l0, h1, l1, h2, l2, h3, l3;
        split_bf(o[i][0] * inv, h0, l0); split_bf(o[i][1] * inv, h1, l1);
        split_bf(o[i][2] * inv, h2, l2); split_bf(o[i][3] * inv, h3, l3);
        size_t off = obase + (size_t)(q0 + i) * D_ + x0;
        __nv_bfloat162* dh = (__nv_bfloat162*)(g_ah + off);
        __nv_bfloat162* dl = (__nv_bfloat162*)(g_al + off);
        dh[0] = __halves2bfloat162(h0, h1); dh[1] = __halves2bfloat162(h2, h3);
        dl[0] = __halves2bfloat162(l0, l1); dl[1] = __halves2bfloat162(l2, l3);
    }
}

// ---------------- combine ----------------
__global__ void combine_kernel() {
    int t = blockIdx.x, tid = threadIdx.x;
    __shared__ float scw[8];
    __shared__ int ssl[8];
    if (tid < 8) { scw[tid] = g_cw[t * 8 + tid]; ssl[tid] = g_slotof[tid * T_ + t]; }
    __syncthreads();
    float4* hr = (float4*)(g_h + (size_t)t * D_);
    float4 hv = hr[tid];
    float rho = 0.f;
    float4 acc = make_float4(0.f, 0.f, 0.f, 0.f);
#pragma unroll
    for (int e = 0; e < 8; e++) {
        int s = ssl[e];
        if (s >= 0) {
            float w = scw[e];
            rho += w;
            float4 ev = ((const float4*)(g_expo + ((size_t)e * CAP_ + s) * D_))[tid];
            acc.x = fmaf(w, ev.x, acc.x); acc.y = fmaf(w, ev.y, acc.y);
            acc.z = fmaf(w, ev.z, acc.z); acc.w = fmaf(w, ev.w, acc.w);
        }
    }
    float om = 1.f - rho;
    hv.x = hv.x * om + acc.x; hv.y = hv.y * om + acc.y;
    hv.z = hv.z * om + acc.z; hv.w = hv.w * om + acc.w;
    hr[tid] = hv;
}

// ---------------- final RMSNorm ----------------
__global__ void rmsnorm_kernel(const float* __restrict__ lnw, float* __restrict__ out) {
    int t = blockIdx.x, tid = threadIdx.x;
    float4 v = ((const float4*)(g_h + (size_t)t * D_))[tid];
    float ss = v.x * v.x + v.y * v.y + v.z * v.z + v.w * v.w;
#pragma unroll
    for (int o = 16; o > 0; o >>= 1) ss += __shfl_xor_sync(0xffffffffu, ss, o);
    __shared__ float red[8];
    if ((tid & 31) == 0) red[tid >> 5] = ss;
    __syncthreads();
    if (tid == 0) {
        float s = 0.f;
        for (int i = 0; i < 8; i++) s += red[i];
        red[0] = rsqrtf(s / (float)D_ + 1e-6f);
    }
    __syncthreads();
    float sc = red[0];
    float4 w = ((const float4*)lnw)[tid];
    float4 o4 = make_float4(v.x * sc * w.x, v.y * sc * w.y, v.z * sc * w.z, v.w * sc * w.w);
    ((float4*)out)[(size_t)t * 256 + tid] = o4;
}

// ---------------- launch ----------------
extern "C" void kernel_launch(void* const* d_in, const int* in_sizes, int n_in,
                              void* d_out, int out_size) {
    const int*   ids      = (const int*)d_in[0];
    const float* embed_w  = (const float*)d_in[1];
    const float* router_w = (const float*)d_in[2];
    const float* wq       = (const float*)d_in[3];
    const float* wk       = (const float*)d_in[4];
    const float* wv       = (const float*)d_in[5];
    const float* wo       = (const float*)d_in[6];
    const float* w1       = (const float*)d_in[7];
    const float* w2       = (const float*)d_in[8];
    const float* lnw      = (const float*)d_in[9];
    float* out = (float*)d_out;

    __nv_bfloat16 *p_wth, *p_wtl, *p_xh, *p_xl, *p_ah, *p_al, *p_fh, *p_fl;
    float *p_expo;
    cudaGetSymbolAddress((void**)&p_wth, g_wth);
    cudaGetSymbolAddress((void**)&p_wtl, g_wtl);
    cudaGetSymbolAddress((void**)&p_xh,  g_xh);
    cudaGetSymbolAddress((void**)&p_xl,  g_xl);
    cudaGetSymbolAddress((void**)&p_ah,  g_ah);
    cudaGetSymbolAddress((void**)&p_al,  g_al);
    cudaGetSymbolAddress((void**)&p_fh,  g_fh);
    cudaGetSymbolAddress((void**)&p_fl,  g_fl);
    cudaGetSymbolAddress((void**)&p_expo, g_expo);

    cudaFuncSetAttribute(attn_kernel, cudaFuncAttributeMaxDynamicSharedMemorySize, ATTN_SMEM);

    // weight transpose + split (once per launch)
    wconv_kernel<<<dim3(32, 32, 4), 256>>>(wq, p_wth + WQ_OFF, p_wtl + WQ_OFF, D_, D_);
    wconv_kernel<<<dim3(32, 32, 4), 256>>>(wk, p_wth + WK_OFF, p_wtl + WK_OFF, D_, D_);
    wconv_kernel<<<dim3(32, 32, 4), 256>>>(wv, p_wth + WV_OFF, p_wtl + WV_OFF, D_, D_);
    wconv_kernel<<<dim3(32, 32, 4), 256>>>(wo, p_wth + WO_OFF, p_wtl + WO_OFF, D_, D_);
    wconv_kernel<<<dim3(128, 32, 4), 256>>>(w1, p_wth + W1_OFF, p_wtl + W1_OFF, D_, MLP_);
    wconv_kernel<<<dim3(32, 128, 4), 256>>>(w2, p_wth + W2_OFF, p_wtl + W2_OFF, MLP_, D_);

    embed_kernel<<<T_, 256>>>(ids, embed_w);
    for (int hop = 0; hop < 3; hop++) {
        router_kernel<<<T_ / 8, 256>>>(router_w + (size_t)hop * 9 * D_);
        capacity_kernel<<<E_, 1024>>>();
        gather_kernel<<<E_ * CAP_, 256>>>();
        gemm_qkv_mma<<<dim3(8, 8, 12), 256>>>();
        rope_kernel<<<4 * CAP_, 256>>>();
        attn_kernel<<<dim3(16, 16, 4), 256, ATTN_SMEM>>>();
        // Wo: attno(bf16 hi/lo) @ woT[g] -> expo[2g]  (fp32)
        gemm_mma<<<dim3(8, 8, 4), 256>>>(
            p_ah, p_al, p_wth + WO_OFF, p_wtl + WO_OFF,
            p_expo, (__nv_bfloat16*)0, (__nv_bfloat16*)0,
            D_, D_, (long long)CAP_ * D_, (long long)D_ * D_, 2LL * CAP_ * D_, 0);
        // FFN1: xin[2g+1] @ w1T[g] -> gelu -> ffh (bf16 hi/lo)
        gemm_mma<<<dim3(32, 8, 4), 256>>>(
            p_xh + (size_t)CAP_ * D_, p_xl + (size_t)CAP_ * D_,
            p_wth + W1_OFF, p_wtl + W1_OFF,
            (float*)0, p_fh, p_fl,
            MLP_, D_, 2LL * CAP_ * D_, (long long)D_ * MLP_, (long long)CAP_ * MLP_, 1);
        // FFN2: ffh @ w2T[g] -> expo[2g+1]  (fp32)
        gemm_mma<<<dim3(8, 8, 4), 256>>>(
            p_fh, p_fl, p_wth + W2_OFF, p_wtl + W2_OFF,
            p_expo + (size_t)CAP_ * D_, (__nv_bfloat16*)0, (__nv_bfloat16*)0,
            D_, MLP_, (long long)CAP_ * MLP_, (long long)MLP_ * D_, 2LL * CAP_ * D_, 0);
        combine_kernel<<<T_, 256>>>();
    }
    rmsnorm_kernel<<<T_, 256>>>(lnw, out);
}

// round 9
// speedup vs baseline: 2.0736x; 1.1809x over previous
#include <cuda_runtime.h>
#include <cuda_bf16.h>
#include <cstdint>
#include <stdint.h>
#include <math.h>

#define T_    4096
#define D_    1024
#define E_    8
#define CAP_  1024
#define MLP_  4096

// ---------------- device scratch ----------------
__device__ float g_h[(size_t)T_ * D_];
__device__ float g_qkv[12ull * CAP_ * D_];
__device__ float g_expo[(size_t)E_ * CAP_ * D_];
__device__ float g_probs[T_ * 8];
__device__ unsigned char g_maskb[T_];
__device__ int   g_slottok[E_ * CAP_];
__device__ int   g_slotof[E_ * T_];
__device__ float g_cw[T_ * 8];
__device__ int   g_nsel[E_];

__device__ __nv_bfloat16 g_xh[(size_t)E_ * CAP_ * D_];
__device__ __nv_bfloat16 g_xl[(size_t)E_ * CAP_ * D_];
__device__ __nv_bfloat16 g_ah[4ull * CAP_ * D_];
__device__ __nv_bfloat16 g_al[4ull * CAP_ * D_];
__device__ __nv_bfloat16 g_fh[4ull * CAP_ * MLP_];
__device__ __nv_bfloat16 g_fl[4ull * CAP_ * MLP_];

#define WQ_OFF 0ull
#define WK_OFF 4194304ull
#define WV_OFF 8388608ull
#define WO_OFF 12582912ull
#define W1_OFF 16777216ull
#define W2_OFF 33554432ull
#define WT_TOT 50331648ull
__device__ __nv_bfloat16 g_wth[WT_TOT];
__device__ __nv_bfloat16 g_wtl[WT_TOT];

// ---------------- helpers ----------------
__device__ __forceinline__ void split_bf(float x, __nv_bfloat16& h, __nv_bfloat16& l) {
    h = __float2bfloat16(x);
    l = __float2bfloat16(x - __bfloat162float(h));
}
__device__ __forceinline__ float gelu_f(float x) {
    float x3 = x * x * x;
    return 0.5f * x * (1.f + tanhf(0.7978845608028654f * (x + 0.044715f * x3)));
}
__device__ __forceinline__ void mma16816(float* d, const uint32_t* a, const uint32_t* b) {
    asm volatile(
        "mma.sync.aligned.m16n8k16.row.col.f32.bf16.bf16.f32 "
        "{%0,%1,%2,%3}, {%4,%5,%6,%7}, {%8,%9}, {%0,%1,%2,%3};"
        : "+f"(d[0]), "+f"(d[1]), "+f"(d[2]), "+f"(d[3])
        : "r"(a[0]), "r"(a[1]), "r"(a[2]), "r"(a[3]), "r"(b[0]), "r"(b[1]));
}
// 32 bf16/row tile (GEMM), chunk ch stored at ch^((r>>1)&3)
__device__ __forceinline__ uint32_t lds_frag(const __nv_bfloat16* base, int r, int c) {
    int ch = c >> 3;
    int sw = ch ^ ((r >> 1) & 3);
    return *(const uint32_t*)(base + r * 32 + sw * 8 + (c & 7));
}
// 64 bf16/row tile (attention), chunk ch stored at ch^(r&7)
__device__ __forceinline__ uint32_t lds_sw64(const __nv_bfloat16* base, int r, int c) {
    int ch = c >> 3;
    int sw = ch ^ (r & 7);
    return *(const uint32_t*)(base + r * 64 + sw * 8 + (c & 7));
}

// ---------------- embedding ----------------
__global__ void embed_kernel(const int* __restrict__ ids, const float* __restrict__ ew) {
    int t = blockIdx.x, tid = threadIdx.x;
    ((float4*)(g_h + (size_t)t * D_))[tid] =
        ((const float4*)(ew + (size_t)ids[t] * D_))[tid];
}

// ---------------- router ----------------
__global__ void router_kernel(const float* __restrict__ rw) {
    int gw = (blockIdx.x * blockDim.x + threadIdx.x) >> 5;
    int lane = threadIdx.x & 31;
    if (gw >= T_) return;
    const float* hr = g_h + (size_t)gw * D_;
    float acc[9];
#pragma unroll
    for (int e = 0; e < 9; e++) acc[e] = 0.f;
    for (int d = lane; d < D_; d += 32) {
        float hv = hr[d];
#pragma unroll
        for (int e = 0; e < 9; e++) acc[e] = fmaf(hv, rw[e * D_ + d], acc[e]);
    }
#pragma unroll
    for (int e = 0; e < 9; e++)
#pragma unroll
        for (int o = 16; o > 0; o >>= 1) acc[e] += __shfl_xor_sync(0xffffffffu, acc[e], o);
    if (lane == 0) {
        float mx = acc[0];
#pragma unroll
        for (int e = 1; e < 9; e++) mx = fmaxf(mx, acc[e]);
        float ex[9], s = 0.f;
#pragma unroll
        for (int e = 0; e < 9; e++) { ex[e] = expf(acc[e] - mx); s += ex[e]; }
        float inv = 1.f / s;
        int a1 = 0; float v1 = acc[0];
#pragma unroll
        for (int e = 1; e < 9; e++) if (acc[e] > v1) { v1 = acc[e]; a1 = e; }
        int a2 = -1; float v2 = -3.0e38f;
#pragma unroll
        for (int e = 0; e < 9; e++) if (e != a1 && acc[e] > v2) { v2 = acc[e]; a2 = e; }
        unsigned char m = 0;
        if (a1 < 8) m |= (unsigned char)(1 << a1);
        if (a2 < 8) m |= (unsigned char)(1 << a2);
        g_maskb[gw] = m;
#pragma unroll
        for (int e = 0; e < 8; e++) g_probs[gw * 8 + e] = ex[e] * inv;
    }
}

// ---------------- capacity select ----------------
__global__ void __launch_bounds__(1024) capacity_kernel() {
    int e = blockIdx.x, tid = threadIdx.x;
    __shared__ unsigned long long keys[T_];
    __shared__ int s_count;
    if (tid == 0) s_count = 0;
    __syncthreads();
    int local = 0;
    for (int t = tid; t < T_; t += 1024) {
        unsigned long long key = 0ull;
        if (g_maskb[t] & (1 << e)) {
            unsigned pb = __float_as_uint(g_probs[t * 8 + e]);
            key = ((unsigned long long)pb << 32) | (unsigned)(0xFFFFFFFFu - (unsigned)t);
            local++;
        }
        keys[t] = key;
    }
#pragma unroll
    for (int o = 16; o > 0; o >>= 1) local += __shfl_xor_sync(0xffffffffu, local, o);
    if ((tid & 31) == 0) atomicAdd(&s_count, local);
    __syncthreads();
    for (int k = 2; k <= T_; k <<= 1)
        for (int j = k >> 1; j > 0; j >>= 1) {
            for (int i = tid; i < T_; i += 1024) {
                int ixj = i ^ j;
                if (ixj > i) {
                    unsigned long long a = keys[i], b = keys[ixj];
                    bool desc = ((i & k) == 0);
                    if (desc ? (a < b) : (a > b)) { keys[i] = b; keys[ixj] = a; }
                }
            }
            __syncthreads();
        }
    int nsel = min(s_count, CAP_);
    if (tid == 0) g_nsel[e] = nsel;
    for (int t = tid; t < T_; t += 1024) { g_slotof[e * T_ + t] = -1; g_cw[t * 8 + e] = 0.f; }
    __syncthreads();
    int c = tid;
    if (c < nsel) {
        unsigned long long key = keys[c];
        int tok = (int)(0xFFFFFFFFu - (unsigned)(key & 0xFFFFFFFFull));
        g_slottok[e * CAP_ + c] = tok;
        g_slotof[e * T_ + tok] = c;
        g_cw[tok * 8 + e] = __uint_as_float((unsigned)(key >> 32));
    } else if (c < CAP_) {
        g_slottok[e * CAP_ + c] = 0;
    }
}

// ---------------- gather -> bf16 hi/lo ----------------
__global__ void gather_kernel() {
    int row = blockIdx.x, e = row >> 10, c = row & 1023, tid = threadIdx.x;
    float4 v = make_float4(0.f, 0.f, 0.f, 0.f);
    if (c < g_nsel[e])
        v = ((const float4*)(g_h + (size_t)g_slottok[row] * D_))[tid];
    __nv_bfloat16 h0, h1, h2, h3, l0, l1, l2, l3;
    split_bf(v.x, h0, l0); split_bf(v.y, h1, l1);
    split_bf(v.z, h2, l2); split_bf(v.w, h3, l3);
    __nv_bfloat162* dh = (__nv_bfloat162*)(g_xh + (size_t)row * D_) + 2 * tid;
    __nv_bfloat162* dl = (__nv_bfloat162*)(g_xl + (size_t)row * D_) + 2 * tid;
    dh[0] = __halves2bfloat162(h0, h1); dh[1] = __halves2bfloat162(h2, h3);
    dl[0] = __halves2bfloat162(l0, l1); dl[1] = __halves2bfloat162(l2, l3);
}

// ---------------- weight transpose + bf16 split: W[K][N] -> WT[N][K] ----------------
__global__ void wconv_kernel(const float* __restrict__ W, __nv_bfloat16* __restrict__ Th,
                             __nv_bfloat16* __restrict__ Tl, int K, int N) {
    __shared__ float t[32][33];
    int z = blockIdx.z;
    size_t base = (size_t)z * K * N;
    int n0 = blockIdx.x * 32, k0 = blockIdx.y * 32;
    int tx = threadIdx.x & 31, ty = threadIdx.x >> 5;
#pragma unroll
    for (int r = 0; r < 32; r += 8)
        t[ty + r][tx] = W[base + (size_t)(k0 + ty + r) * N + n0 + tx];
    __syncthreads();
#pragma unroll
    for (int r = 0; r < 32; r += 8) {
        float v = t[tx][ty + r];
        __nv_bfloat16 h, l; split_bf(v, h, l);
        size_t o = base + (size_t)(n0 + ty + r) * K + k0 + tx;
        Th[o] = h; Tl[o] = l;
    }
}

// ---------------- mma.sync GEMM (unchanged from R8) ----------------
__device__ __forceinline__ void store_tile(__nv_bfloat16* s, const __nv_bfloat16* __restrict__ g,
                                           int K, int k0, int tid) {
#pragma unroll
    for (int q = 0; q < 2; q++) {
        int i = tid * 2 + q;
        int r = i >> 2, ch = i & 3;
        int sw = ch ^ ((r >> 1) & 3);
        *(uint4*)(s + r * 32 + sw * 8) =
            *(const uint4*)(g + (size_t)r * K + k0 + ch * 8);
    }
}

__device__ __forceinline__ void gemm_mma_body(
    const __nv_bfloat16* __restrict__ Ah, const __nv_bfloat16* __restrict__ Al,
    const __nv_bfloat16* __restrict__ Bh, const __nv_bfloat16* __restrict__ Bl,
    float* Cf, __nv_bfloat16* Ch, __nv_bfloat16* Cl, int N, int K, int act)
{
    __shared__ __nv_bfloat16 sAh[128 * 32], sAl[128 * 32], sBh[128 * 32], sBl[128 * 32];
    int tid = threadIdx.x, lane = tid & 31, warp = tid >> 5;
    int wm = (warp & 1) * 64, wn = (warp >> 1) * 32;
    int brow = blockIdx.y * 128, bcol = blockIdx.x * 128;
    const __nv_bfloat16* pAh = Ah + (size_t)brow * K;
    const __nv_bfloat16* pAl = Al + (size_t)brow * K;
    const __nv_bfloat16* pBh = Bh + (size_t)bcol * K;
    const __nv_bfloat16* pBl = Bl + (size_t)bcol * K;

    float acc[4][4][4];
#pragma unroll
    for (int i = 0; i < 4; i++)
#pragma unroll
        for (int j = 0; j < 4; j++)
#pragma unroll
            for (int d = 0; d < 4; d++) acc[i][j][d] = 0.f;

    int g = lane >> 2, t4 = lane & 3;

    for (int k0 = 0; k0 < K; k0 += 32) {
        __syncthreads();
        store_tile(sAh, pAh, K, k0, tid);
        store_tile(sAl, pAl, K, k0, tid);
        store_tile(sBh, pBh, K, k0, tid);
        store_tile(sBl, pBl, K, k0, tid);
        __syncthreads();
#pragma unroll
        for (int kc = 0; kc < 2; kc++) {
            int cb = kc * 16 + t4 * 2;
            uint32_t bh[4][2], bl[4][2];
#pragma unroll
            for (int tn = 0; tn < 4; tn++) {
                int n = wn + tn * 8 + g;
                bh[tn][0] = lds_frag(sBh, n, cb);
                bh[tn][1] = lds_frag(sBh, n, cb + 8);
                bl[tn][0] = lds_frag(sBl, n, cb);
                bl[tn][1] = lds_frag(sBl, n, cb + 8);
            }
#pragma unroll
            for (int tm = 0; tm < 4; tm++) {
                int r = wm + tm * 16 + g;
                uint32_t ah[4], al[4];
                ah[0] = lds_frag(sAh, r, cb);     ah[1] = lds_frag(sAh, r + 8, cb);
                ah[2] = lds_frag(sAh, r, cb + 8); ah[3] = lds_frag(sAh, r + 8, cb + 8);
                al[0] = lds_frag(sAl, r, cb);     al[1] = lds_frag(sAl, r + 8, cb);
                al[2] = lds_frag(sAl, r, cb + 8); al[3] = lds_frag(sAl, r + 8, cb + 8);
#pragma unroll
                for (int tn = 0; tn < 4; tn++) {
                    mma16816(acc[tm][tn], ah, bh[tn]);
                    mma16816(acc[tm][tn], ah, bl[tn]);
                    mma16816(acc[tm][tn], al, bh[tn]);
                }
            }
        }
    }

#pragma unroll
    for (int tm = 0; tm < 4; tm++) {
        int r = brow + wm + tm * 16 + g;
#pragma unroll
        for (int tn = 0; tn < 4; tn++) {
            int c = bcol + wn + tn * 8 + t4 * 2;
            float v0 = acc[tm][tn][0], v1 = acc[tm][tn][1];
            float v2 = acc[tm][tn][2], v3 = acc[tm][tn][3];
            if (Cf) {
                *(float2*)(Cf + (size_t)r * N + c) = make_float2(v0, v1);
                *(float2*)(Cf + (size_t)(r + 8) * N + c) = make_float2(v2, v3);
            } else {
                if (act) { v0 = gelu_f(v0); v1 = gelu_f(v1); v2 = gelu_f(v2); v3 = gelu_f(v3); }
                __nv_bfloat16 h0, l0, h1, l1, h2, l2, h3, l3;
                split_bf(v0, h0, l0); split_bf(v1, h1, l1);
                split_bf(v2, h2, l2); split_bf(v3, h3, l3);
                *(__nv_bfloat162*)(Ch + (size_t)r * N + c) = __halves2bfloat162(h0, h1);
                *(__nv_bfloat162*)(Cl + (size_t)r * N + c) = __halves2bfloat162(l0, l1);
                *(__nv_bfloat162*)(Ch + (size_t)(r + 8) * N + c) = __halves2bfloat162(h2, h3);
                *(__nv_bfloat162*)(Cl + (size_t)(r + 8) * N + c) = __halves2bfloat162(l2, l3);
            }
        }
    }
}

__global__ void __launch_bounds__(256, 2) gemm_mma(
    const __nv_bfloat16* Ah, const __nv_bfloat16* Al,
    const __nv_bfloat16* Bh, const __nv_bfloat16* Bl,
    float* Cf, __nv_bfloat16* Ch, __nv_bfloat16* Cl,
    int N, int K, long long sA, long long sB, long long sC, int act)
{
    long long z = blockIdx.z;
    gemm_mma_body(Ah + z * sA, Al + z * sA, Bh + z * sB, Bl + z * sB,
                  Cf ? Cf + z * sC : (float*)0,
                  Ch ? Ch + z * sC : (__nv_bfloat16*)0,
                  Cl ? Cl + z * sC : (__nv_bfloat16*)0, N, K, act);
}

__global__ void __launch_bounds__(256, 2) gemm_qkv_mma() {
    int z = blockIdx.z, which = z >> 2, g = z & 3;
    size_t ao = (size_t)(2 * g) * CAP_ * D_;
    size_t wo = (size_t)which * 4194304ull + (size_t)g * 1048576ull;
    gemm_mma_body(g_xh + ao, g_xl + ao, g_wth + wo, g_wtl + wo,
                  g_qkv + ((size_t)which * 4 + g) * CAP_ * D_,
                  (__nv_bfloat16*)0, (__nv_bfloat16*)0, D_, D_, 0);
}

// ---------------- RoPE ----------------
__global__ void rope_kernel() {
    int row = blockIdx.x, g = row >> 10, c = row & 1023, tid = threadIdx.x;
    float pos = (float)g_slottok[(2 * g) * CAP_ + c];
    float* q = g_qkv + (size_t)row * D_;
    float* k = g_qkv + 4ull * CAP_ * D_ + (size_t)row * D_;
    for (int idx = tid; idx < 512; idx += 256) {
        int hh = idx >> 5, d0 = idx & 31;
        float invf = (float)exp(-(double)(2 * d0) / 64.0 * 9.210340371976184);
        float ang = pos * invf;
        float cs = cosf(ang), sn = sinf(ang);
        int b = hh * 64 + d0;
        float a0 = q[b], a1 = q[b + 32];
        q[b] = a0 * cs - a1 * sn; q[b + 32] = a1 * cs + a0 * sn;
        float b0 = k[b], b1 = k[b + 32];
        k[b] = b0 * cs - b1 * sn; k[b + 32] = b1 * cs + b0 * sn;
    }
}

// ---------------- HMMA flash attention ----------------
// block = (qb 64 queries, head, group); 256 threads = 8 warps (4q x 2d/k tiles of 16x32)
#define A_QH  0
#define A_QL  8192
#define A_KH  16384
#define A_KL  24576
#define A_PH  32768
#define A_PL  40960
#define A_VTH 49152
#define A_VTL 57600
#define A_PS  66048
#define A_RM  82688
#define A_RL  82944
#define A_RC  83200
#define ATTN_SMEM 83456

// load 64x64 fp32 tile (row stride ldg) -> swizzled bf16 hi/lo tiles
__device__ __forceinline__ void attn_load64(__nv_bfloat16* th, __nv_bfloat16* tl,
                                            const float* __restrict__ gsrc, int ldg, int tid) {
#pragma unroll
    for (int it = 0; it < 4; it++) {
        int idx = tid + it * 256;
        int r = idx >> 4, c4 = (idx & 15) << 2;
        float4 v = *(const float4*)(gsrc + (size_t)r * ldg + c4);
        __nv_bfloat16 h0, l0, h1, l1, h2, l2, h3, l3;
        split_bf(v.x, h0, l0); split_bf(v.y, h1, l1);
        split_bf(v.z, h2, l2); split_bf(v.w, h3, l3);
        int ch = c4 >> 3, sw = ch ^ (r & 7);
        int off = r * 64 + sw * 8 + (c4 & 7);
        *(__nv_bfloat162*)(th + off) = __halves2bfloat162(h0, h1);
        *(__nv_bfloat162*)(th + off + 2) = __halves2bfloat162(h2, h3);
        *(__nv_bfloat162*)(tl + off) = __halves2bfloat162(l0, l1);
        *(__nv_bfloat162*)(tl + off + 2) = __halves2bfloat162(l2, l3);
    }
}

__global__ void __launch_bounds__(256, 2) attn_kernel() {
    int qb = blockIdx.x, hh = blockIdx.y, g = blockIdx.z;
    extern __shared__ char sm[];
    __nv_bfloat16* Qh = (__nv_bfloat16*)(sm + A_QH);
    __nv_bfloat16* Ql = (__nv_bfloat16*)(sm + A_QL);
    __nv_bfloat16* Kh = (__nv_bfloat16*)(sm + A_KH);
    __nv_bfloat16* Kl = (__nv_bfloat16*)(sm + A_KL);
    __nv_bfloat16* Ph = (__nv_bfloat16*)(sm + A_PH);
    __nv_bfloat16* Pl = (__nv_bfloat16*)(sm + A_PL);
    __nv_bfloat16* Vth = (__nv_bfloat16*)(sm + A_VTH);   // [64 d][66 k] padded
    __nv_bfloat16* Vtl = (__nv_bfloat16*)(sm + A_VTL);
    float* Ps = (float*)(sm + A_PS);                      // [64][65]
    float* rm = (float*)(sm + A_RM);
    float* rl = (float*)(sm + A_RL);
    float* rc = (float*)(sm + A_RC);

    int tid = threadIdx.x, lane = tid & 31, warp = tid >> 5;
    int gq = lane >> 2, t4 = lane & 3;
    int wq = (warp & 3) * 16;          // q-tile (4)
    int wx = (warp >> 2) * 32;         // k/d-tile (2)

    const float* Qg = g_qkv + ((size_t)(g * CAP_ + qb * 64)) * D_ + hh * 64;
    attn_load64(Qh, Ql, Qg, D_, tid);
    if (tid < 64) { rm[tid] = -3.0e38f; rl[tid] = 0.f; }

    float o[4][4];
#pragma unroll
    for (int i = 0; i < 4; i++)
#pragma unroll
        for (int j = 0; j < 4; j++) o[i][j] = 0.f;

    for (int kt = 0; kt < 16; kt++) {
        __syncthreads();
        // load K tile (swizzled) and V tile transposed (padded-66)
        const float* Kg = g_qkv + 4ull * CAP_ * D_ + ((size_t)(g * CAP_ + kt * 64)) * D_ + hh * 64;
        const float* Vg = g_qkv + 8ull * CAP_ * D_ + ((size_t)(g * CAP_ + kt * 64)) * D_ + hh * 64;
        attn_load64(Kh, Kl, Kg, D_, tid);
#pragma unroll
        for (int it = 0; it < 4; it++) {
            int idx = tid + it * 256;
            int k = idx >> 4, c4 = (idx & 15) << 2;
            float4 v = *(const float4*)(Vg + (size_t)k * D_ + c4);
            __nv_bfloat16 h, l;
            split_bf(v.x, h, l); Vth[(c4 + 0) * 66 + k] = h; Vtl[(c4 + 0) * 66 + k] = l;
            split_bf(v.y, h, l); Vth[(c4 + 1) * 66 + k] = h; Vtl[(c4 + 1) * 66 + k] = l;
            split_bf(v.z, h, l); Vth[(c4 + 2) * 66 + k] = h; Vtl[(c4 + 2) * 66 + k] = l;
            split_bf(v.w, h, l); Vth[(c4 + 3) * 66 + k] = h; Vtl[(c4 + 3) * 66 + k] = l;
        }
        __syncthreads();

        // S = Q K^T * 0.125  (3-split HMMA), warp tile 16q x 32k
        float s[4][4];
#pragma unroll
        for (int i = 0; i < 4; i++)
#pragma unroll
            for (int j = 0; j < 4; j++) s[i][j] = 0.f;
#pragma unroll
        for (int ks = 0; ks < 4; ks++) {
            int cb = ks * 16 + t4 * 2;
            uint32_t ah[4], al[4];
            ah[0] = lds_sw64(Qh, wq + gq, cb);     ah[1] = lds_sw64(Qh, wq + gq + 8, cb);
            ah[2] = lds_sw64(Qh, wq + gq, cb + 8); ah[3] = lds_sw64(Qh, wq + gq + 8, cb + 8);
            al[0] = lds_sw64(Ql, wq + gq, cb);     al[1] = lds_sw64(Ql, wq + gq + 8, cb);
            al[2] = lds_sw64(Ql, wq + gq, cb + 8); al[3] = lds_sw64(Ql, wq + gq + 8, cb + 8);
#pragma unroll
            for (int tn = 0; tn < 4; tn++) {
                int n = wx + tn * 8 + gq;
                uint32_t bh[2], bl[2];
                bh[0] = lds_sw64(Kh, n, cb); bh[1] = lds_sw64(Kh, n, cb + 8);
                bl[0] = lds_sw64(Kl, n, cb); bl[1] = lds_sw64(Kl, n, cb + 8);
                mma16816(s[tn], ah, bh);
                mma16816(s[tn], ah, bl);
                mma16816(s[tn], al, bh);
            }
        }
#pragma unroll
        for (int tn = 0; tn < 4; tn++) {
            int c = wx + tn * 8 + t4 * 2;
            Ps[(wq + gq) * 65 + c] = s[tn][0] * 0.125f;
            Ps[(wq + gq) * 65 + c + 1] = s[tn][1] * 0.125f;
            Ps[(wq + gq + 8) * 65 + c] = s[tn][2] * 0.125f;
            Ps[(wq + gq + 8) * 65 + c + 1] = s[tn][3] * 0.125f;
        }
        __syncthreads();

        // softmax: 4 threads per row; writes Ph/Pl (bf16 hi/lo) + rc/rl/rm
        {
            int row = tid >> 2, part = tid & 3;
            float* pr = Ps + row * 65 + part * 16;
            float tmax = pr[0];
#pragma unroll
            for (int i = 1; i < 16; i++) tmax = fmaxf(tmax, pr[i]);
            tmax = fmaxf(tmax, __shfl_xor_sync(0xffffffffu, tmax, 1));
            tmax = fmaxf(tmax, __shfl_xor_sync(0xffffffffu, tmax, 2));
            float mold = rm[row];
            float mnew = fmaxf(mold, tmax);
            float sum = 0.f;
#pragma unroll
            for (int i = 0; i < 16; i += 2) {
                float p0 = expf(pr[i] - mnew);
                float p1 = expf(pr[i + 1] - mnew);
                sum += p0 + p1;
                __nv_bfloat16 h0, l0, h1, l1;
                split_bf(p0, h0, l0); split_bf(p1, h1, l1);
                int c = part * 16 + i;
                int ch = c >> 3, sw = ch ^ (row & 7);
                int off = row * 64 + sw * 8 + (c & 7);
                *(__nv_bfloat162*)(Ph + off) = __halves2bfloat162(h0, h1);
                *(__nv_bfloat162*)(Pl + off) = __halves2bfloat162(l0, l1);
            }
            sum += __shfl_xor_sync(0xffffffffu, sum, 1);
            sum += __shfl_xor_sync(0xffffffffu, sum, 2);
            __syncwarp();
            if (part == 0) {
                float corr = expf(mold - mnew);
                rc[row] = corr;
                rl[row] = rl[row] * corr + sum;
                rm[row] = mnew;
            }
        }
        __syncthreads();

        // O = O*corr + P V  (warp tile 16q x 32d)
        float cr0 = rc[wq + gq], cr1 = rc[wq + gq + 8];
#pragma unroll
        for (int tn = 0; tn < 4; tn++) {
            o[tn][0] *= cr0; o[tn][1] *= cr0;
            o[tn][2] *= cr1; o[tn][3] *= cr1;
        }
#pragma unroll
        for (int ks = 0; ks < 4; ks++) {
            int cb = ks * 16 + t4 * 2;
            uint32_t ah[4], al[4];
            ah[0] = lds_sw64(Ph, wq + gq, cb);     ah[1] = lds_sw64(Ph, wq + gq + 8, cb);
            ah[2] = lds_sw64(Ph, wq + gq, cb + 8); ah[3] = lds_sw64(Ph, wq + gq + 8, cb + 8);
            al[0] = lds_sw64(Pl, wq + gq, cb);     al[1] = lds_sw64(Pl, wq + gq + 8, cb);
            al[2] = lds_sw64(Pl, wq + gq, cb + 8); al[3] = lds_sw64(Pl, wq + gq + 8, cb + 8);
#pragma unroll
            for (int tn = 0; tn < 4; tn++) {
                int n = wx + tn * 8 + gq;     // d index
                uint32_t bh[2], bl[2];
                bh[0] = *(const uint32_t*)(Vth + n * 66 + cb);
                bh[1] = *(const uint32_t*)(Vth + n * 66 + cb + 8);
                bl[0] = *(const uint32_t*)(Vtl + n * 66 + cb);
                bl[1] = *(const uint32_t*)(Vtl + n * 66 + cb + 8);
                mma16816(o[tn], ah, bh);
                mma16816(o[tn], ah, bl);
                mma16816(o[tn], al, bh);
            }
        }
    }
    __syncthreads();

    // write O / l  as bf16 hi/lo
    float inv0 = 1.f / rl[wq + gq], inv1 = 1.f / rl[wq + gq + 8];
    size_t obase = ((size_t)(g * CAP_ + qb * 64)) * D_ + hh * 64;
#pragma unroll
    for (int tn = 0; tn < 4; tn++) {
        int c = wx + tn * 8 + t4 * 2;
        __nv_bfloat16 h0, l0, h1, l1;
        split_bf(o[tn][0] * inv0, h0, l0); split_bf(o[tn][1] * inv0, h1, l1);
        size_t off = obase + (size_t)(wq + gq) * D_ + c;
        *(__nv_bfloat162*)(g_ah + off) = __halves2bfloat162(h0, h1);
        *(__nv_bfloat162*)(g_al + off) = __halves2bfloat162(l0, l1);
        split_bf(o[tn][2] * inv1, h0, l0); split_bf(o[tn][3] * inv1, h1, l1);
        off = obase + (size_t)(wq + gq + 8) * D_ + c;
        *(__nv_bfloat162*)(g_ah + off) = __halves2bfloat162(h0, h1);
        *(__nv_bfloat162*)(g_al + off) = __halves2bfloat162(l0, l1);
    }
}

// ---------------- combine ----------------
__global__ void combine_kernel() {
    int t = blockIdx.x, tid = threadIdx.x;
    __shared__ float scw[8];
    __shared__ int ssl[8];
    if (tid < 8) { scw[tid] = g_cw[t * 8 + tid]; ssl[tid] = g_slotof[tid * T_ + t]; }
    __syncthreads();
    float4* hr = (float4*)(g_h + (size_t)t * D_);
    float4 hv = hr[tid];
    float rho = 0.f;
    float4 acc = make_float4(0.f, 0.f, 0.f, 0.f);
#pragma unroll
    for (int e = 0; e < 8; e++) {
        int s = ssl[e];
        if (s >= 0) {
            float w = scw[e];
            rho += w;
            float4 ev = ((const float4*)(g_expo + ((size_t)e * CAP_ + s) * D_))[tid];
            acc.x = fmaf(w, ev.x, acc.x); acc.y = fmaf(w, ev.y, acc.y);
            acc.z = fmaf(w, ev.z, acc.z); acc.w = fmaf(w, ev.w, acc.w);
        }
    }
    float om = 1.f - rho;
    hv.x = hv.x * om + acc.x; hv.y = hv.y * om + acc.y;
    hv.z = hv.z * om + acc.z; hv.w = hv.w * om + acc.w;
    hr[tid] = hv;
}

// ---------------- final RMSNorm ----------------
__global__ void rmsnorm_kernel(const float* __restrict__ lnw, float* __restrict__ out) {
    int t = blockIdx.x, tid = threadIdx.x;
    float4 v = ((const float4*)(g_h + (size_t)t * D_))[tid];
    float ss = v.x * v.x + v.y * v.y + v.z * v.z + v.w * v.w;
#pragma unroll
    for (int o = 16; o > 0; o >>= 1) ss += __shfl_xor_sync(0xffffffffu, ss, o);
    __shared__ float red[8];
    if ((tid & 31) == 0) red[tid >> 5] = ss;
    __syncthreads();
    if (tid == 0) {
        float s = 0.f;
        for (int i = 0; i < 8; i++) s += red[i];
        red[0] = rsqrtf(s / (float)D_ + 1e-6f);
    }
    __syncthreads();
    float sc = red[0];
    float4 w = ((const float4*)lnw)[tid];
    float4 o4 = make_float4(v.x * sc * w.x, v.y * sc * w.y, v.z * sc * w.z, v.w * sc * w.w);
    ((float4*)out)[(size_t)t * 256 + tid] = o4;
}

// ---------------- launch ----------------
extern "C" void kernel_launch(void* const* d_in, const int* in_sizes, int n_in,
                              void* d_out, int out_size) {
    const int*   ids      = (const int*)d_in[0];
    const float* embed_w  = (const float*)d_in[1];
    const float* router_w = (const float*)d_in[2];
    const float* wq       = (const float*)d_in[3];
    const float* wk       = (const float*)d_in[4];
    const float* wv       = (const float*)d_in[5];
    const float* wo       = (const float*)d_in[6];
    const float* w1       = (const float*)d_in[7];
    const float* w2       = (const float*)d_in[8];
    const float* lnw      = (const float*)d_in[9];
    float* out = (float*)d_out;

    __nv_bfloat16 *p_wth, *p_wtl, *p_xh, *p_xl, *p_ah, *p_al, *p_fh, *p_fl;
    float *p_expo;
    cudaGetSymbolAddress((void**)&p_wth, g_wth);
    cudaGetSymbolAddress((void**)&p_wtl, g_wtl);
    cudaGetSymbolAddress((void**)&p_xh,  g_xh);
    cudaGetSymbolAddress((void**)&p_xl,  g_xl);
    cudaGetSymbolAddress((void**)&p_ah,  g_ah);
    cudaGetSymbolAddress((void**)&p_al,  g_al);
    cudaGetSymbolAddress((void**)&p_fh,  g_fh);
    cudaGetSymbolAddress((void**)&p_fl,  g_fl);
    cudaGetSymbolAddress((void**)&p_expo, g_expo);

    cudaFuncSetAttribute(attn_kernel, cudaFuncAttributeMaxDynamicSharedMemorySize, ATTN_SMEM);

    // weight transpose + split (once per launch)
    wconv_kernel<<<dim3(32, 32, 4), 256>>>(wq, p_wth + WQ_OFF, p_wtl + WQ_OFF, D_, D_);
    wconv_kernel<<<dim3(32, 32, 4), 256>>>(wk, p_wth + WK_OFF, p_wtl + WK_OFF, D_, D_);
    wconv_kernel<<<dim3(32, 32, 4), 256>>>(wv, p_wth + WV_OFF, p_wtl + WV_OFF, D_, D_);
    wconv_kernel<<<dim3(32, 32, 4), 256>>>(wo, p_wth + WO_OFF, p_wtl + WO_OFF, D_, D_);
    wconv_kernel<<<dim3(128, 32, 4), 256>>>(w1, p_wth + W1_OFF, p_wtl + W1_OFF, D_, MLP_);
    wconv_kernel<<<dim3(32, 128, 4), 256>>>(w2, p_wth + W2_OFF, p_wtl + W2_OFF, MLP_, D_);

    embed_kernel<<<T_, 256>>>(ids, embed_w);
    for (int hop = 0; hop < 3; hop++) {
        router_kernel<<<T_ / 8, 256>>>(router_w + (size_t)hop * 9 * D_);
        capacity_kernel<<<E_, 1024>>>();
        gather_kernel<<<E_ * CAP_, 256>>>();
        gemm_qkv_mma<<<dim3(8, 8, 12), 256>>>();
        rope_kernel<<<4 * CAP_, 256>>>();
        attn_kernel<<<dim3(16, 16, 4), 256, ATTN_SMEM>>>();
        gemm_mma<<<dim3(8, 8, 4), 256>>>(
            p_ah, p_al, p_wth + WO_OFF, p_wtl + WO_OFF,
            p_expo, (__nv_bfloat16*)0, (__nv_bfloat16*)0,
            D_, D_, (long long)CAP_ * D_, (long long)D_ * D_, 2LL * CAP_ * D_, 0);
        gemm_mma<<<dim3(32, 8, 4), 256>>>(
            p_xh + (size_t)CAP_ * D_, p_xl + (size_t)CAP_ * D_,
            p_wth + W1_OFF, p_wtl + W1_OFF,
            (float*)0, p_fh, p_fl,
            MLP_, D_, 2LL * CAP_ * D_, (long long)D_ * MLP_, (long long)CAP_ * MLP_, 1);
        gemm_mma<<<dim3(8, 8, 4), 256>>>(
            p_fh, p_fl, p_wth + W2_OFF, p_wtl + W2_OFF,
            p_expo + (size_t)CAP_ * D_, (__nv_bfloat16*)0, (__nv_bfloat16*)0,
            D_, MLP_, (long long)CAP_ * MLP_, (long long)MLP_ * D_, 2LL * CAP_ * D_, 0);
        combine_kernel<<<T_, 256>>>();
    }
    rmsnorm_kernel<<<T_, 256>>>(lnw, out);
}

// round 10
// speedup vs baseline: 2.1740x; 1.0484x over previous
#include <cuda_runtime.h>
#include <cuda_bf16.h>
#include <cstdint>
#include <stdint.h>
#include <math.h>

#define T_    4096
#define D_    1024
#define E_    8
#define CAP_  1024
#define MLP_  4096

// ---------------- device scratch ----------------
__device__ float g_h[(size_t)T_ * D_];
__device__ float g_qkv[12ull * CAP_ * D_];
__device__ float g_expo[(size_t)E_ * CAP_ * D_];
__device__ float g_probs[T_ * 8];
__device__ unsigned char g_maskb[T_];
__device__ int   g_slottok[E_ * CAP_];
__device__ int   g_slotof[E_ * T_];
__device__ float g_cw[T_ * 8];
__device__ int   g_nsel[E_];

__device__ __nv_bfloat16 g_xh[(size_t)E_ * CAP_ * D_];
__device__ __nv_bfloat16 g_xl[(size_t)E_ * CAP_ * D_];
__device__ __nv_bfloat16 g_ah[4ull * CAP_ * D_];
__device__ __nv_bfloat16 g_al[4ull * CAP_ * D_];
__device__ __nv_bfloat16 g_fh[4ull * CAP_ * MLP_];
__device__ __nv_bfloat16 g_fl[4ull * CAP_ * MLP_];

#define WQ_OFF 0ull
#define WK_OFF 4194304ull
#define WV_OFF 8388608ull
#define WO_OFF 12582912ull
#define W1_OFF 16777216ull
#define W2_OFF 33554432ull
#define WT_TOT 50331648ull
__device__ __nv_bfloat16 g_wth[WT_TOT];
__device__ __nv_bfloat16 g_wtl[WT_TOT];

// ---------------- helpers ----------------
__device__ __forceinline__ uint32_t smem_u32(const void* p) {
    uint32_t a;
    asm("{ .reg .u64 t; cvta.to.shared.u64 t, %1; cvt.u32.u64 %0, t; }" : "=r"(a) : "l"(p));
    return a;
}
__device__ __forceinline__ void cp_async16(uint32_t saddr, const void* gptr) {
    asm volatile("cp.async.cg.shared.global [%0], [%1], 16;" :: "r"(saddr), "l"(gptr));
}
#define CP_COMMIT() asm volatile("cp.async.commit_group;")
#define CP_WAIT(n)  asm volatile("cp.async.wait_group %0;" :: "n"(n))

__device__ __forceinline__ void split_bf(float x, __nv_bfloat16& h, __nv_bfloat16& l) {
    h = __float2bfloat16(x);
    l = __float2bfloat16(x - __bfloat162float(h));
}
__device__ __forceinline__ float gelu_f(float x) {
    float x3 = x * x * x;
    return 0.5f * x * (1.f + tanhf(0.7978845608028654f * (x + 0.044715f * x3)));
}
__device__ __forceinline__ void mma16816(float* d, const uint32_t* a, const uint32_t* b) {
    asm volatile(
        "mma.sync.aligned.m16n8k16.row.col.f32.bf16.bf16.f32 "
        "{%0,%1,%2,%3}, {%4,%5,%6,%7}, {%8,%9}, {%0,%1,%2,%3};"
        : "+f"(d[0]), "+f"(d[1]), "+f"(d[2]), "+f"(d[3])
        : "r"(a[0]), "r"(a[1]), "r"(a[2]), "r"(a[3]), "r"(b[0]), "r"(b[1]));
}
// 32 bf16/row tile (GEMM), chunk ch stored at ch^((r>>1)&3)
__device__ __forceinline__ uint32_t lds_frag(const __nv_bfloat16* base, int r, int c) {
    int ch = c >> 3;
    int sw = ch ^ ((r >> 1) & 3);
    return *(const uint32_t*)(base + r * 32 + sw * 8 + (c & 7));
}
// 64 bf16/row tile (attention), chunk ch stored at ch^(r&7)
__device__ __forceinline__ uint32_t lds_sw64(const __nv_bfloat16* base, int r, int c) {
    int ch = c >> 3;
    int sw = ch ^ (r & 7);
    return *(const uint32_t*)(base + r * 64 + sw * 8 + (c & 7));
}

// ---------------- embedding ----------------
__global__ void embed_kernel(const int* __restrict__ ids, const float* __restrict__ ew) {
    int t = blockIdx.x, tid = threadIdx.x;
    ((float4*)(g_h + (size_t)t * D_))[tid] =
        ((const float4*)(ew + (size_t)ids[t] * D_))[tid];
}

// ---------------- router ----------------
__global__ void router_kernel(const float* __restrict__ rw) {
    int gw = (blockIdx.x * blockDim.x + threadIdx.x) >> 5;
    int lane = threadIdx.x & 31;
    if (gw >= T_) return;
    const float* hr = g_h + (size_t)gw * D_;
    float acc[9];
#pragma unroll
    for (int e = 0; e < 9; e++) acc[e] = 0.f;
    for (int d = lane; d < D_; d += 32) {
        float hv = hr[d];
#pragma unroll
        for (int e = 0; e < 9; e++) acc[e] = fmaf(hv, rw[e * D_ + d], acc[e]);
    }
#pragma unroll
    for (int e = 0; e < 9; e++)
#pragma unroll
        for (int o = 16; o > 0; o >>= 1) acc[e] += __shfl_xor_sync(0xffffffffu, acc[e], o);
    if (lane == 0) {
        float mx = acc[0];
#pragma unroll
        for (int e = 1; e < 9; e++) mx = fmaxf(mx, acc[e]);
        float ex[9], s = 0.f;
#pragma unroll
        for (int e = 0; e < 9; e++) { ex[e] = expf(acc[e] - mx); s += ex[e]; }
        float inv = 1.f / s;
        int a1 = 0; float v1 = acc[0];
#pragma unroll
        for (int e = 1; e < 9; e++) if (acc[e] > v1) { v1 = acc[e]; a1 = e; }
        int a2 = -1; float v2 = -3.0e38f;
#pragma unroll
        for (int e = 0; e < 9; e++) if (e != a1 && acc[e] > v2) { v2 = acc[e]; a2 = e; }
        unsigned char m = 0;
        if (a1 < 8) m |= (unsigned char)(1 << a1);
        if (a2 < 8) m |= (unsigned char)(1 << a2);
        g_maskb[gw] = m;
#pragma unroll
        for (int e = 0; e < 8; e++) g_probs[gw * 8 + e] = ex[e] * inv;
    }
}

// ---------------- capacity select ----------------
__global__ void __launch_bounds__(1024) capacity_kernel() {
    int e = blockIdx.x, tid = threadIdx.x;
    __shared__ unsigned long long keys[T_];
    __shared__ int s_count;
    if (tid == 0) s_count = 0;
    __syncthreads();
    int local = 0;
    for (int t = tid; t < T_; t += 1024) {
        unsigned long long key = 0ull;
        if (g_maskb[t] & (1 << e)) {
            unsigned pb = __float_as_uint(g_probs[t * 8 + e]);
            key = ((unsigned long long)pb << 32) | (unsigned)(0xFFFFFFFFu - (unsigned)t);
            local++;
        }
        keys[t] = key;
    }
#pragma unroll
    for (int o = 16; o > 0; o >>= 1) local += __shfl_xor_sync(0xffffffffu, local, o);
    if ((tid & 31) == 0) atomicAdd(&s_count, local);
    __syncthreads();
    for (int k = 2; k <= T_; k <<= 1)
        for (int j = k >> 1; j > 0; j >>= 1) {
            for (int i = tid; i < T_; i += 1024) {
                int ixj = i ^ j;
                if (ixj > i) {
                    unsigned long long a = keys[i], b = keys[ixj];
                    bool desc = ((i & k) == 0);
                    if (desc ? (a < b) : (a > b)) { keys[i] = b; keys[ixj] = a; }
                }
            }
            __syncthreads();
        }
    int nsel = min(s_count, CAP_);
    if (tid == 0) g_nsel[e] = nsel;
    for (int t = tid; t < T_; t += 1024) { g_slotof[e * T_ + t] = -1; g_cw[t * 8 + e] = 0.f; }
    __syncthreads();
    int c = tid;
    if (c < nsel) {
        unsigned long long key = keys[c];
        int tok = (int)(0xFFFFFFFFu - (unsigned)(key & 0xFFFFFFFFull));
        g_slottok[e * CAP_ + c] = tok;
        g_slotof[e * T_ + tok] = c;
        g_cw[tok * 8 + e] = __uint_as_float((unsigned)(key >> 32));
    } else if (c < CAP_) {
        g_slottok[e * CAP_ + c] = 0;
    }
}

// ---------------- gather -> bf16 hi/lo ----------------
__global__ void gather_kernel() {
    int row = blockIdx.x, e = row >> 10, c = row & 1023, tid = threadIdx.x;
    float4 v = make_float4(0.f, 0.f, 0.f, 0.f);
    if (c < g_nsel[e])
        v = ((const float4*)(g_h + (size_t)g_slottok[row] * D_))[tid];
    __nv_bfloat16 h0, h1, h2, h3, l0, l1, l2, l3;
    split_bf(v.x, h0, l0); split_bf(v.y, h1, l1);
    split_bf(v.z, h2, l2); split_bf(v.w, h3, l3);
    __nv_bfloat162* dh = (__nv_bfloat162*)(g_xh + (size_t)row * D_) + 2 * tid;
    __nv_bfloat162* dl = (__nv_bfloat162*)(g_xl + (size_t)row * D_) + 2 * tid;
    dh[0] = __halves2bfloat162(h0, h1); dh[1] = __halves2bfloat162(h2, h3);
    dl[0] = __halves2bfloat162(l0, l1); dl[1] = __halves2bfloat162(l2, l3);
}

// ---------------- weight transpose + bf16 split: W[K][N] -> WT[N][K] ----------------
__global__ void wconv_kernel(const float* __restrict__ W, __nv_bfloat16* __restrict__ Th,
                             __nv_bfloat16* __restrict__ Tl, int K, int N) {
    __shared__ float t[32][33];
    int z = blockIdx.z;
    size_t base = (size_t)z * K * N;
    int n0 = blockIdx.x * 32, k0 = blockIdx.y * 32;
    int tx = threadIdx.x & 31, ty = threadIdx.x >> 5;
#pragma unroll
    for (int r = 0; r < 32; r += 8)
        t[ty + r][tx] = W[base + (size_t)(k0 + ty + r) * N + n0 + tx];
    __syncthreads();
#pragma unroll
    for (int r = 0; r < 32; r += 8) {
        float v = t[tx][ty + r];
        __nv_bfloat16 h, l; split_bf(v, h, l);
        size_t o = base + (size_t)(n0 + ty + r) * K + k0 + tx;
        Th[o] = h; Tl[o] = l;
    }
}

// ---------------- cp.async double-buffered mma.sync GEMM ----------------
// dynamic smem: 2 buffers x 4 tiles x 8192B = 65536B
#define GSMEM 65536

__device__ __forceinline__ void issue_tile(uint32_t sbase, const __nv_bfloat16* __restrict__ g,
                                           int K, int k0, int tid) {
#pragma unroll
    for (int q = 0; q < 2; q++) {
        int i = tid * 2 + q;
        int r = i >> 2, ch = i & 3;
        int sw = ch ^ ((r >> 1) & 3);
        cp_async16(sbase + (uint32_t)(r * 32 + sw * 8) * 2,
                   g + (size_t)r * K + k0 + ch * 8);
    }
}

__device__ __forceinline__ void gemm_mma_body(
    const __nv_bfloat16* __restrict__ Ah, const __nv_bfloat16* __restrict__ Al,
    const __nv_bfloat16* __restrict__ Bh, const __nv_bfloat16* __restrict__ Bl,
    float* Cf, __nv_bfloat16* Ch, __nv_bfloat16* Cl, int N, int K, int act)
{
    extern __shared__ char gsm[];
    uint32_t sb = smem_u32(gsm);
    int tid = threadIdx.x, lane = tid & 31, warp = tid >> 5;
    int wm = (warp & 1) * 64, wn = (warp >> 1) * 32;
    int brow = blockIdx.y * 128, bcol = blockIdx.x * 128;
    const __nv_bfloat16* pAh = Ah + (size_t)brow * K;
    const __nv_bfloat16* pAl = Al + (size_t)brow * K;
    const __nv_bfloat16* pBh = Bh + (size_t)bcol * K;
    const __nv_bfloat16* pBl = Bl + (size_t)bcol * K;

    float acc[4][4][4];
#pragma unroll
    for (int i = 0; i < 4; i++)
#pragma unroll
        for (int j = 0; j < 4; j++)
#pragma unroll
            for (int d = 0; d < 4; d++) acc[i][j][d] = 0.f;

    int g = lane >> 2, t4 = lane & 3;
    int NC = K >> 5;

    // prologue: issue tile 0 into buffer 0
    issue_tile(sb,         pAh, K, 0, tid);
    issue_tile(sb + 8192,  pAl, K, 0, tid);
    issue_tile(sb + 16384, pBh, K, 0, tid);
    issue_tile(sb + 24576, pBl, K, 0, tid);
    CP_COMMIT();

    for (int c = 0; c < NC; c++) {
        if (c + 1 < NC) {
            uint32_t nb = sb + ((c + 1) & 1) * 32768;
            int k0 = (c + 1) << 5;
            issue_tile(nb,         pAh, K, k0, tid);
            issue_tile(nb + 8192,  pAl, K, k0, tid);
            issue_tile(nb + 16384, pBh, K, k0, tid);
            issue_tile(nb + 24576, pBl, K, k0, tid);
            CP_COMMIT();
            CP_WAIT(1);
        } else {
            CP_WAIT(0);
        }
        __syncthreads();
        const __nv_bfloat16* sAh = (const __nv_bfloat16*)(gsm + (c & 1) * 32768);
        const __nv_bfloat16* sAl = sAh + 4096;
        const __nv_bfloat16* sBh = sAh + 8192;
        const __nv_bfloat16* sBl = sAh + 12288;
#pragma unroll
        for (int kc = 0; kc < 2; kc++) {
            int cb = kc * 16 + t4 * 2;
            uint32_t bh[4][2], bl[4][2];
#pragma unroll
            for (int tn = 0; tn < 4; tn++) {
                int n = wn + tn * 8 + g;
                bh[tn][0] = lds_frag(sBh, n, cb);
                bh[tn][1] = lds_frag(sBh, n, cb + 8);
                bl[tn][0] = lds_frag(sBl, n, cb);
                bl[tn][1] = lds_frag(sBl, n, cb + 8);
            }
#pragma unroll
            for (int tm = 0; tm < 4; tm++) {
                int r = wm + tm * 16 + g;
                uint32_t ah[4], al[4];
                ah[0] = lds_frag(sAh, r, cb);     ah[1] = lds_frag(sAh, r + 8, cb);
                ah[2] = lds_frag(sAh, r, cb + 8); ah[3] = lds_frag(sAh, r + 8, cb + 8);
                al[0] = lds_frag(sAl, r, cb);     al[1] = lds_frag(sAl, r + 8, cb);
                al[2] = lds_frag(sAl, r, cb + 8); al[3] = lds_frag(sAl, r + 8, cb + 8);
#pragma unroll
                for (int tn = 0; tn < 4; tn++) {
                    mma16816(acc[tm][tn], ah, bh[tn]);
                    mma16816(acc[tm][tn], ah, bl[tn]);
                    mma16816(acc[tm][tn], al, bh[tn]);
                }
            }
        }
        __syncthreads();
    }

#pragma unroll
    for (int tm = 0; tm < 4; tm++) {
        int r = brow + wm + tm * 16 + g;
#pragma unroll
        for (int tn = 0; tn < 4; tn++) {
            int c = bcol + wn + tn * 8 + t4 * 2;
            float v0 = acc[tm][tn][0], v1 = acc[tm][tn][1];
            float v2 = acc[tm][tn][2], v3 = acc[tm][tn][3];
            if (Cf) {
                *(float2*)(Cf + (size_t)r * N + c) = make_float2(v0, v1);
                *(float2*)(Cf + (size_t)(r + 8) * N + c) = make_float2(v2, v3);
            } else {
                if (act) { v0 = gelu_f(v0); v1 = gelu_f(v1); v2 = gelu_f(v2); v3 = gelu_f(v3); }
                __nv_bfloat16 h0, l0, h1, l1, h2, l2, h3, l3;
                split_bf(v0, h0, l0); split_bf(v1, h1, l1);
                split_bf(v2, h2, l2); split_bf(v3, h3, l3);
                *(__nv_bfloat162*)(Ch + (size_t)r * N + c) = __halves2bfloat162(h0, h1);
                *(__nv_bfloat162*)(Cl + (size_t)r * N + c) = __halves2bfloat162(l0, l1);
                *(__nv_bfloat162*)(Ch + (size_t)(r + 8) * N + c) = __halves2bfloat162(h2, h3);
                *(__nv_bfloat162*)(Cl + (size_t)(r + 8) * N + c) = __halves2bfloat162(l2, l3);
            }
        }
    }
}

__global__ void __launch_bounds__(256, 2) gemm_mma(
    const __nv_bfloat16* Ah, const __nv_bfloat16* Al,
    const __nv_bfloat16* Bh, const __nv_bfloat16* Bl,
    float* Cf, __nv_bfloat16* Ch, __nv_bfloat16* Cl,
    int N, int K, long long sA, long long sB, long long sC, int act)
{
    long long z = blockIdx.z;
    gemm_mma_body(Ah + z * sA, Al + z * sA, Bh + z * sB, Bl + z * sB,
                  Cf ? Cf + z * sC : (float*)0,
                  Ch ? Ch + z * sC : (__nv_bfloat16*)0,
                  Cl ? Cl + z * sC : (__nv_bfloat16*)0, N, K, act);
}

__global__ void __launch_bounds__(256, 2) gemm_qkv_mma() {
    int z = blockIdx.z, which = z >> 2, g = z & 3;
    size_t ao = (size_t)(2 * g) * CAP_ * D_;
    size_t wo = (size_t)which * 4194304ull + (size_t)g * 1048576ull;
    gemm_mma_body(g_xh + ao, g_xl + ao, g_wth + wo, g_wtl + wo,
                  g_qkv + ((size_t)which * 4 + g) * CAP_ * D_,
                  (__nv_bfloat16*)0, (__nv_bfloat16*)0, D_, D_, 0);
}

// ---------------- RoPE ----------------
__global__ void rope_kernel() {
    int row = blockIdx.x, g = row >> 10, c = row & 1023, tid = threadIdx.x;
    float pos = (float)g_slottok[(2 * g) * CAP_ + c];
    float* q = g_qkv + (size_t)row * D_;
    float* k = g_qkv + 4ull * CAP_ * D_ + (size_t)row * D_;
    for (int idx = tid; idx < 512; idx += 256) {
        int hh = idx >> 5, d0 = idx & 31;
        float invf = (float)exp(-(double)(2 * d0) / 64.0 * 9.210340371976184);
        float ang = pos * invf;
        float cs = cosf(ang), sn = sinf(ang);
        int b = hh * 64 + d0;
        float a0 = q[b], a1 = q[b + 32];
        q[b] = a0 * cs - a1 * sn; q[b + 32] = a1 * cs + a0 * sn;
        float b0 = k[b], b1 = k[b + 32];
        k[b] = b0 * cs - b1 * sn; k[b + 32] = b1 * cs + b0 * sn;
    }
}

// ---------------- HMMA flash attention (unchanged from R9) ----------------
#define A_QH  0
#define A_QL  8192
#define A_KH  16384
#define A_KL  24576
#define A_PH  32768
#define A_PL  40960
#define A_VTH 49152
#define A_VTL 57600
#define A_PS  66048
#define A_RM  82688
#define A_RL  82944
#define A_RC  83200
#define ATTN_SMEM 83456

__device__ __forceinline__ void attn_load64(__nv_bfloat16* th, __nv_bfloat16* tl,
                                            const float* __restrict__ gsrc, int ldg, int tid) {
#pragma unroll
    for (int it = 0; it < 4; it++) {
        int idx = tid + it * 256;
        int r = idx >> 4, c4 = (idx & 15) << 2;
        float4 v = *(const float4*)(gsrc + (size_t)r * ldg + c4);
        __nv_bfloat16 h0, l0, h1, l1, h2, l2, h3, l3;
        split_bf(v.x, h0, l0); split_bf(v.y, h1, l1);
        split_bf(v.z, h2, l2); split_bf(v.w, h3, l3);
        int ch = c4 >> 3, sw = ch ^ (r & 7);
        int off = r * 64 + sw * 8 + (c4 & 7);
        *(__nv_bfloat162*)(th + off) = __halves2bfloat162(h0, h1);
        *(__nv_bfloat162*)(th + off + 2) = __halves2bfloat162(h2, h3);
        *(__nv_bfloat162*)(tl + off) = __halves2bfloat162(l0, l1);
        *(__nv_bfloat162*)(tl + off + 2) = __halves2bfloat162(l2, l3);
    }
}

__global__ void __launch_bounds__(256, 2) attn_kernel() {
    int qb = blockIdx.x, hh = blockIdx.y, g = blockIdx.z;
    extern __shared__ char sm[];
    __nv_bfloat16* Qh = (__nv_bfloat16*)(sm + A_QH);
    __nv_bfloat16* Ql = (__nv_bfloat16*)(sm + A_QL);
    __nv_bfloat16* Kh = (__nv_bfloat16*)(sm + A_KH);
    __nv_bfloat16* Kl = (__nv_bfloat16*)(sm + A_KL);
    __nv_bfloat16* Ph = (__nv_bfloat16*)(sm + A_PH);
    __nv_bfloat16* Pl = (__nv_bfloat16*)(sm + A_PL);
    __nv_bfloat16* Vth = (__nv_bfloat16*)(sm + A_VTH);
    __nv_bfloat16* Vtl = (__nv_bfloat16*)(sm + A_VTL);
    float* Ps = (float*)(sm + A_PS);
    float* rm = (float*)(sm + A_RM);
    float* rl = (float*)(sm + A_RL);
    float* rc = (float*)(sm + A_RC);

    int tid = threadIdx.x, lane = tid & 31, warp = tid >> 5;
    int gq = lane >> 2, t4 = lane & 3;
    int wq = (warp & 3) * 16;
    int wx = (warp >> 2) * 32;

    const float* Qg = g_qkv + ((size_t)(g * CAP_ + qb * 64)) * D_ + hh * 64;
    attn_load64(Qh, Ql, Qg, D_, tid);
    if (tid < 64) { rm[tid] = -3.0e38f; rl[tid] = 0.f; }

    float o[4][4];
#pragma unroll
    for (int i = 0; i < 4; i++)
#pragma unroll
        for (int j = 0; j < 4; j++) o[i][j] = 0.f;

    for (int kt = 0; kt < 16; kt++) {
        __syncthreads();
        const float* Kg = g_qkv + 4ull * CAP_ * D_ + ((size_t)(g * CAP_ + kt * 64)) * D_ + hh * 64;
        const float* Vg = g_qkv + 8ull * CAP_ * D_ + ((size_t)(g * CAP_ + kt * 64)) * D_ + hh * 64;
        attn_load64(Kh, Kl, Kg, D_, tid);
#pragma unroll
        for (int it = 0; it < 4; it++) {
            int idx = tid + it * 256;
            int k = idx >> 4, c4 = (idx & 15) << 2;
            float4 v = *(const float4*)(Vg + (size_t)k * D_ + c4);
            __nv_bfloat16 h, l;
            split_bf(v.x, h, l); Vth[(c4 + 0) * 66 + k] = h; Vtl[(c4 + 0) * 66 + k] = l;
            split_bf(v.y, h, l); Vth[(c4 + 1) * 66 + k] = h; Vtl[(c4 + 1) * 66 + k] = l;
            split_bf(v.z, h, l); Vth[(c4 + 2) * 66 + k] = h; Vtl[(c4 + 2) * 66 + k] = l;
            split_bf(v.w, h, l); Vth[(c4 + 3) * 66 + k] = h; Vtl[(c4 + 3) * 66 + k] = l;
        }
        __syncthreads();

        float s[4][4];
#pragma unroll
        for (int i = 0; i < 4; i++)
#pragma unroll
            for (int j = 0; j < 4; j++) s[i][j] = 0.f;
#pragma unroll
        for (int ks = 0; ks < 4; ks++) {
            int cb = ks * 16 + t4 * 2;
            uint32_t ah[4], al[4];
            ah[0] = lds_sw64(Qh, wq + gq, cb);     ah[1] = lds_sw64(Qh, wq + gq + 8, cb);
            ah[2] = lds_sw64(Qh, wq + gq, cb + 8); ah[3] = lds_sw64(Qh, wq + gq + 8, cb + 8);
            al[0] = lds_sw64(Ql, wq + gq, cb);     al[1] = lds_sw64(Ql, wq + gq + 8, cb);
            al[2] = lds_sw64(Ql, wq + gq, cb + 8); al[3] = lds_sw64(Ql, wq + gq + 8, cb + 8);
#pragma unroll
            for (int tn = 0; tn < 4; tn++) {
                int n = wx + tn * 8 + gq;
                uint32_t bh[2], bl[2];
                bh[0] = lds_sw64(Kh, n, cb); bh[1] = lds_sw64(Kh, n, cb + 8);
                bl[0] = lds_sw64(Kl, n, cb); bl[1] = lds_sw64(Kl, n, cb + 8);
                mma16816(s[tn], ah, bh);
                mma16816(s[tn], ah, bl);
                mma16816(s[tn], al, bh);
            }
        }
#pragma unroll
        for (int tn = 0; tn < 4; tn++) {
            int c = wx + tn * 8 + t4 * 2;
            Ps[(wq + gq) * 65 + c] = s[tn][0] * 0.125f;
            Ps[(wq + gq) * 65 + c + 1] = s[tn][1] * 0.125f;
            Ps[(wq + gq + 8) * 65 + c] = s[tn][2] * 0.125f;
            Ps[(wq + gq + 8) * 65 + c + 1] = s[tn][3] * 0.125f;
        }
        __syncthreads();

        {
            int row = tid >> 2, part = tid & 3;
            float* pr = Ps + row * 65 + part * 16;
            float tmax = pr[0];
#pragma unroll
            for (int i = 1; i < 16; i++) tmax = fmaxf(tmax, pr[i]);
            tmax = fmaxf(tmax, __shfl_xor_sync(0xffffffffu, tmax, 1));
            tmax = fmaxf(tmax, __shfl_xor_sync(0xffffffffu, tmax, 2));
            float mold = rm[row];
            float mnew = fmaxf(mold, tmax);
            float sum = 0.f;
#pragma unroll
            for (int i = 0; i < 16; i += 2) {
                float p0 = expf(pr[i] - mnew);
                float p1 = expf(pr[i + 1] - mnew);
                sum += p0 + p1;
                __nv_bfloat16 h0, l0, h1, l1;
                split_bf(p0, h0, l0); split_bf(p1, h1, l1);
                int c = part * 16 + i;
                int ch = c >> 3, sw = ch ^ (row & 7);
                int off = row * 64 + sw * 8 + (c & 7);
                *(__nv_bfloat162*)(Ph + off) = __halves2bfloat162(h0, h1);
                *(__nv_bfloat162*)(Pl + off) = __halves2bfloat162(l0, l1);
            }
            sum += __shfl_xor_sync(0xffffffffu, sum, 1);
            sum += __shfl_xor_sync(0xffffffffu, sum, 2);
            __syncwarp();
            if (part == 0) {
                float corr = expf(mold - mnew);
                rc[row] = corr;
                rl[row] = rl[row] * corr + sum;
                rm[row] = mnew;
            }
        }
        __syncthreads();

        float cr0 = rc[wq + gq], cr1 = rc[wq + gq + 8];
#pragma unroll
        for (int tn = 0; tn < 4; tn++) {
            o[tn][0] *= cr0; o[tn][1] *= cr0;
            o[tn][2] *= cr1; o[tn][3] *= cr1;
        }
#pragma unroll
        for (int ks = 0; ks < 4; ks++) {
            int cb = ks * 16 + t4 * 2;
            uint32_t ah[4], al[4];
            ah[0] = lds_sw64(Ph, wq + gq, cb);     ah[1] = lds_sw64(Ph, wq + gq + 8, cb);
            ah[2] = lds_sw64(Ph, wq + gq, cb + 8); ah[3] = lds_sw64(Ph, wq + gq + 8, cb + 8);
            al[0] = lds_sw64(Pl, wq + gq, cb);     al[1] = lds_sw64(Pl, wq + gq + 8, cb);
            al[2] = lds_sw64(Pl, wq + gq, cb + 8); al[3] = lds_sw64(Pl, wq + gq + 8, cb + 8);
#pragma unroll
            for (int tn = 0; tn < 4; tn++) {
                int n = wx + tn * 8 + gq;
                uint32_t bh[2], bl[2];
                bh[0] = *(const uint32_t*)(Vth + n * 66 + cb);
                bh[1] = *(const uint32_t*)(Vth + n * 66 + cb + 8);
                bl[0] = *(const uint32_t*)(Vtl + n * 66 + cb);
                bl[1] = *(const uint32_t*)(Vtl + n * 66 + cb + 8);
                mma16816(o[tn], ah, bh);
                mma16816(o[tn], ah, bl);
                mma16816(o[tn], al, bh);
            }
        }
    }
    __syncthreads();

    float inv0 = 1.f / rl[wq + gq], inv1 = 1.f / rl[wq + gq + 8];
    size_t obase = ((size_t)(g * CAP_ + qb * 64)) * D_ + hh * 64;
#pragma unroll
    for (int tn = 0; tn < 4; tn++) {
        int c = wx + tn * 8 + t4 * 2;
        __nv_bfloat16 h0, l0, h1, l1;
        split_bf(o[tn][0] * inv0, h0, l0); split_bf(o[tn][1] * inv0, h1, l1);
        size_t off = obase + (size_t)(wq + gq) * D_ + c;
        *(__nv_bfloat162*)(g_ah + off) = __halves2bfloat162(h0, h1);
        *(__nv_bfloat162*)(g_al + off) = __halves2bfloat162(l0, l1);
        split_bf(o[tn][2] * inv1, h0, l0); split_bf(o[tn][3] * inv1, h1, l1);
        off = obase + (size_t)(wq + gq + 8) * D_ + c;
        *(__nv_bfloat162*)(g_ah + off) = __halves2bfloat162(h0, h1);
        *(__nv_bfloat162*)(g_al + off) = __halves2bfloat162(l0, l1);
    }
}

// ---------------- combine ----------------
__global__ void combine_kernel() {
    int t = blockIdx.x, tid = threadIdx.x;
    __shared__ float scw[8];
    __shared__ int ssl[8];
    if (tid < 8) { scw[tid] = g_cw[t * 8 + tid]; ssl[tid] = g_slotof[tid * T_ + t]; }
    __syncthreads();
    float4* hr = (float4*)(g_h + (size_t)t * D_);
    float4 hv = hr[tid];
    float rho = 0.f;
    float4 acc = make_float4(0.f, 0.f, 0.f, 0.f);
#pragma unroll
    for (int e = 0; e < 8; e++) {
        int s = ssl[e];
        if (s >= 0) {
            float w = scw[e];
            rho += w;
            float4 ev = ((const float4*)(g_expo + ((size_t)e * CAP_ + s) * D_))[tid];
            acc.x = fmaf(w, ev.x, acc.x); acc.y = fmaf(w, ev.y, acc.y);
            acc.z = fmaf(w, ev.z, acc.z); acc.w = fmaf(w, ev.w, acc.w);
        }
    }
    float om = 1.f - rho;
    hv.x = hv.x * om + acc.x; hv.y = hv.y * om + acc.y;
    hv.z = hv.z * om + acc.z; hv.w = hv.w * om + acc.w;
    hr[tid] = hv;
}

// ---------------- final RMSNorm ----------------
__global__ void rmsnorm_kernel(const float* __restrict__ lnw, float* __restrict__ out) {
    int t = blockIdx.x, tid = threadIdx.x;
    float4 v = ((const float4*)(g_h + (size_t)t * D_))[tid];
    float ss = v.x * v.x + v.y * v.y + v.z * v.z + v.w * v.w;
#pragma unroll
    for (int o = 16; o > 0; o >>= 1) ss += __shfl_xor_sync(0xffffffffu, ss, o);
    __shared__ float red[8];
    if ((tid & 31) == 0) red[tid >> 5] = ss;
    __syncthreads();
    if (tid == 0) {
        float s = 0.f;
        for (int i = 0; i < 8; i++) s += red[i];
        red[0] = rsqrtf(s / (float)D_ + 1e-6f);
    }
    __syncthreads();
    float sc = red[0];
    float4 w = ((const float4*)lnw)[tid];
    float4 o4 = make_float4(v.x * sc * w.x, v.y * sc * w.y, v.z * sc * w.z, v.w * sc * w.w);
    ((float4*)out)[(size_t)t * 256 + tid] = o4;
}

// ---------------- launch ----------------
extern "C" void kernel_launch(void* const* d_in, const int* in_sizes, int n_in,
                              void* d_out, int out_size) {
    const int*   ids      = (const int*)d_in[0];
    const float* embed_w  = (const float*)d_in[1];
    const float* router_w = (const float*)d_in[2];
    const float* wq       = (const float*)d_in[3];
    const float* wk       = (const float*)d_in[4];
    const float* wv       = (const float*)d_in[5];
    const float* wo       = (const float*)d_in[6];
    const float* w1       = (const float*)d_in[7];
    const float* w2       = (const float*)d_in[8];
    const float* lnw      = (const float*)d_in[9];
    float* out = (float*)d_out;

    __nv_bfloat16 *p_wth, *p_wtl, *p_xh, *p_xl, *p_ah, *p_al, *p_fh, *p_fl;
    float *p_expo;
    cudaGetSymbolAddress((void**)&p_wth, g_wth);
    cudaGetSymbolAddress((void**)&p_wtl, g_wtl);
    cudaGetSymbolAddress((void**)&p_xh,  g_xh);
    cudaGetSymbolAddress((void**)&p_xl,  g_xl);
    cudaGetSymbolAddress((void**)&p_ah,  g_ah);
    cudaGetSymbolAddress((void**)&p_al,  g_al);
    cudaGetSymbolAddress((void**)&p_fh,  g_fh);
    cudaGetSymbolAddress((void**)&p_fl,  g_fl);
    cudaGetSymbolAddress((void**)&p_expo, g_expo);

    cudaFuncSetAttribute(attn_kernel, cudaFuncAttributeMaxDynamicSharedMemorySize, ATTN_SMEM);
    cudaFuncSetAttribute(gemm_mma, cudaFuncAttributeMaxDynamicSharedMemorySize, GSMEM);
    cudaFuncSetAttribute(gemm_qkv_mma, cudaFuncAttributeMaxDynamicSharedMemorySize, GSMEM);

    // weight transpose + split (once per launch)
    wconv_kernel<<<dim3(32, 32, 4), 256>>>(wq, p_wth + WQ_OFF, p_wtl + WQ_OFF, D_, D_);
    wconv_kernel<<<dim3(32, 32, 4), 256>>>(wk, p_wth + WK_OFF, p_wtl + WK_OFF, D_, D_);
    wconv_kernel<<<dim3(32, 32, 4), 256>>>(wv, p_wth + WV_OFF, p_wtl + WV_OFF, D_, D_);
    wconv_kernel<<<dim3(32, 32, 4), 256>>>(wo, p_wth + WO_OFF, p_wtl + WO_OFF, D_, D_);
    wconv_kernel<<<dim3(128, 32, 4), 256>>>(w1, p_wth + W1_OFF, p_wtl + W1_OFF, D_, MLP_);
    wconv_kernel<<<dim3(32, 128, 4), 256>>>(w2, p_wth + W2_OFF, p_wtl + W2_OFF, MLP_, D_);

    embed_kernel<<<T_, 256>>>(ids, embed_w);
    for (int hop = 0; hop < 3; hop++) {
        router_kernel<<<T_ / 8, 256>>>(router_w + (size_t)hop * 9 * D_);
        capacity_kernel<<<E_, 1024>>>();
        gather_kernel<<<E_ * CAP_, 256>>>();
        gemm_qkv_mma<<<dim3(8, 8, 12), 256, GSMEM>>>();
        rope_kernel<<<4 * CAP_, 256>>>();
        attn_kernel<<<dim3(16, 16, 4), 256, ATTN_SMEM>>>();
        gemm_mma<<<dim3(8, 8, 4), 256, GSMEM>>>(
            p_ah, p_al, p_wth + WO_OFF, p_wtl + WO_OFF,
            p_expo, (__nv_bfloat16*)0, (__nv_bfloat16*)0,
            D_, D_, (long long)CAP_ * D_, (long long)D_ * D_, 2LL * CAP_ * D_, 0);
        gemm_mma<<<dim3(32, 8, 4), 256, GSMEM>>>(
            p_xh + (size_t)CAP_ * D_, p_xl + (size_t)CAP_ * D_,
            p_wth + W1_OFF, p_wtl + W1_OFF,
            (float*)0, p_fh, p_fl,
            MLP_, D_, 2LL * CAP_ * D_, (long long)D_ * MLP_, (long long)CAP_ * MLP_, 1);
        gemm_mma<<<dim3(8, 8, 4), 256, GSMEM>>>(
            p_fh, p_fl, p_wth + W2_OFF, p_wtl + W2_OFF,
            p_expo + (size_t)CAP_ * D_, (__nv_bfloat16*)0, (__nv_bfloat16*)0,
            D_, MLP_, (long long)CAP_ * MLP_, (long long)MLP_ * D_, 2LL * CAP_ * D_, 0);
        combine_kernel<<<T_, 256>>>();
    }
    rmsnorm_kernel<<<T_, 256>>>(lnw, out);
}

// round 11
// speedup vs baseline: 2.1776x; 1.0017x over previous
#include <cuda_runtime.h>
#include <cuda_bf16.h>
#include <cstdint>
#include <stdint.h>
#include <math.h>

#define T_    4096
#define D_    1024
#define E_    8
#define CAP_  1024
#define MLP_  4096

// ---------------- device scratch ----------------
__device__ float g_h[(size_t)T_ * D_];
__device__ float g_qkv[8ull * CAP_ * D_];          // fp32 q (0-3), k (4-7)
__device__ float g_expo[(size_t)E_ * CAP_ * D_];
__device__ float g_probs[T_ * 8];
__device__ unsigned char g_maskb[T_];
__device__ int   g_slottok[E_ * CAP_];
__device__ int   g_slotof[E_ * T_];
__device__ float g_cw[T_ * 8];
__device__ int   g_nsel[E_];

__device__ __nv_bfloat16 g_xh[(size_t)E_ * CAP_ * D_];
__device__ __nv_bfloat16 g_xl[(size_t)E_ * CAP_ * D_];
__device__ __nv_bfloat16 g_qh[4ull * CAP_ * D_];
__device__ __nv_bfloat16 g_ql[4ull * CAP_ * D_];
__device__ __nv_bfloat16 g_kh[4ull * CAP_ * D_];
__device__ __nv_bfloat16 g_kl[4ull * CAP_ * D_];
__device__ __nv_bfloat16 g_vh[4ull * CAP_ * D_];
__device__ __nv_bfloat16 g_vl[4ull * CAP_ * D_];
__device__ __nv_bfloat16 g_ah[4ull * CAP_ * D_];
__device__ __nv_bfloat16 g_al[4ull * CAP_ * D_];
__device__ __nv_bfloat16 g_fh[4ull * CAP_ * MLP_];
__device__ __nv_bfloat16 g_fl[4ull * CAP_ * MLP_];

#define WQ_OFF 0ull
#define WK_OFF 4194304ull
#define WV_OFF 8388608ull
#define WO_OFF 12582912ull
#define W1_OFF 16777216ull
#define W2_OFF 33554432ull
#define WT_TOT 50331648ull
__device__ __nv_bfloat16 g_wth[WT_TOT];
__device__ __nv_bfloat16 g_wtl[WT_TOT];

// ---------------- helpers ----------------
__device__ __forceinline__ uint32_t smem_u32(const void* p) {
    uint32_t a;
    asm("{ .reg .u64 t; cvta.to.shared.u64 t, %1; cvt.u32.u64 %0, t; }" : "=r"(a) : "l"(p));
    return a;
}
__device__ __forceinline__ void cp_async16(uint32_t saddr, const void* gptr) {
    asm volatile("cp.async.cg.shared.global [%0], [%1], 16;" :: "r"(saddr), "l"(gptr));
}
#define CP_COMMIT() asm volatile("cp.async.commit_group;")
#define CP_WAIT(n)  asm volatile("cp.async.wait_group %0;" :: "n"(n))

__device__ __forceinline__ void split_bf(float x, __nv_bfloat16& h, __nv_bfloat16& l) {
    h = __float2bfloat16(x);
    l = __float2bfloat16(x - __bfloat162float(h));
}
__device__ __forceinline__ float gelu_f(float x) {
    float x3 = x * x * x;
    return 0.5f * x * (1.f + tanhf(0.7978845608028654f * (x + 0.044715f * x3)));
}
__device__ __forceinline__ void mma16816(float* d, const uint32_t* a, const uint32_t* b) {
    asm volatile(
        "mma.sync.aligned.m16n8k16.row.col.f32.bf16.bf16.f32 "
        "{%0,%1,%2,%3}, {%4,%5,%6,%7}, {%8,%9}, {%0,%1,%2,%3};"
        : "+f"(d[0]), "+f"(d[1]), "+f"(d[2]), "+f"(d[3])
        : "r"(a[0]), "r"(a[1]), "r"(a[2]), "r"(a[3]), "r"(b[0]), "r"(b[1]));
}
__device__ __forceinline__ uint32_t lds_frag(const __nv_bfloat16* base, int r, int c) {
    int ch = c >> 3;
    int sw = ch ^ ((r >> 1) & 3);
    return *(const uint32_t*)(base + r * 32 + sw * 8 + (c & 7));
}
__device__ __forceinline__ uint32_t lds_sw64(const __nv_bfloat16* base, int r, int c) {
    int ch = c >> 3;
    int sw = ch ^ (r & 7);
    return *(const uint32_t*)(base + r * 64 + sw * 8 + (c & 7));
}

// ---------------- embedding ----------------
__global__ void embed_kernel(const int* __restrict__ ids, const float* __restrict__ ew) {
    int t = blockIdx.x, tid = threadIdx.x;
    ((float4*)(g_h + (size_t)t * D_))[tid] =
        ((const float4*)(ew + (size_t)ids[t] * D_))[tid];
}

// ---------------- router ----------------
__global__ void router_kernel(const float* __restrict__ rw) {
    int gw = (blockIdx.x * blockDim.x + threadIdx.x) >> 5;
    int lane = threadIdx.x & 31;
    if (gw >= T_) return;
    const float* hr = g_h + (size_t)gw * D_;
    float acc[9];
#pragma unroll
    for (int e = 0; e < 9; e++) acc[e] = 0.f;
    for (int d = lane; d < D_; d += 32) {
        float hv = hr[d];
#pragma unroll
        for (int e = 0; e < 9; e++) acc[e] = fmaf(hv, rw[e * D_ + d], acc[e]);
    }
#pragma unroll
    for (int e = 0; e < 9; e++)
#pragma unroll
        for (int o = 16; o > 0; o >>= 1) acc[e] += __shfl_xor_sync(0xffffffffu, acc[e], o);
    if (lane == 0) {
        float mx = acc[0];
#pragma unroll
        for (int e = 1; e < 9; e++) mx = fmaxf(mx, acc[e]);
        float ex[9], s = 0.f;
#pragma unroll
        for (int e = 0; e < 9; e++) { ex[e] = expf(acc[e] - mx); s += ex[e]; }
        float inv = 1.f / s;
        int a1 = 0; float v1 = acc[0];
#pragma unroll
        for (int e = 1; e < 9; e++) if (acc[e] > v1) { v1 = acc[e]; a1 = e; }
        int a2 = -1; float v2 = -3.0e38f;
#pragma unroll
        for (int e = 0; e < 9; e++) if (e != a1 && acc[e] > v2) { v2 = acc[e]; a2 = e; }
        unsigned char m = 0;
        if (a1 < 8) m |= (unsigned char)(1 << a1);
        if (a2 < 8) m |= (unsigned char)(1 << a2);
        g_maskb[gw] = m;
#pragma unroll
        for (int e = 0; e < 8; e++) g_probs[gw * 8 + e] = ex[e] * inv;
    }
}

// ---------------- capacity select ----------------
__global__ void __launch_bounds__(1024) capacity_kernel() {
    int e = blockIdx.x, tid = threadIdx.x;
    __shared__ unsigned long long keys[T_];
    __shared__ int s_count;
    if (tid == 0) s_count = 0;
    __syncthreads();
    int local = 0;
    for (int t = tid; t < T_; t += 1024) {
        unsigned long long key = 0ull;
        if (g_maskb[t] & (1 << e)) {
            unsigned pb = __float_as_uint(g_probs[t * 8 + e]);
            key = ((unsigned long long)pb << 32) | (unsigned)(0xFFFFFFFFu - (unsigned)t);
            local++;
        }
        keys[t] = key;
    }
#pragma unroll
    for (int o = 16; o > 0; o >>= 1) local += __shfl_xor_sync(0xffffffffu, local, o);
    if ((tid & 31) == 0) atomicAdd(&s_count, local);
    __syncthreads();
    for (int k = 2; k <= T_; k <<= 1)
        for (int j = k >> 1; j > 0; j >>= 1) {
            for (int i = tid; i < T_; i += 1024) {
                int ixj = i ^ j;
                if (ixj > i) {
                    unsigned long long a = keys[i], b = keys[ixj];
                    bool desc = ((i & k) == 0);
                    if (desc ? (a < b) : (a > b)) { keys[i] = b; keys[ixj] = a; }
                }
            }
            __syncthreads();
        }
    int nsel = min(s_count, CAP_);
    if (tid == 0) g_nsel[e] = nsel;
    for (int t = tid; t < T_; t += 1024) { g_slotof[e * T_ + t] = -1; g_cw[t * 8 + e] = 0.f; }
    __syncthreads();
    int c = tid;
    if (c < nsel) {
        unsigned long long key = keys[c];
        int tok = (int)(0xFFFFFFFFu - (unsigned)(key & 0xFFFFFFFFull));
        g_slottok[e * CAP_ + c] = tok;
        g_slotof[e * T_ + tok] = c;
        g_cw[tok * 8 + e] = __uint_as_float((unsigned)(key >> 32));
    } else if (c < CAP_) {
        g_slottok[e * CAP_ + c] = 0;
    }
}

// ---------------- gather -> bf16 hi/lo ----------------
__global__ void gather_kernel() {
    int row = blockIdx.x, e = row >> 10, c = row & 1023, tid = threadIdx.x;
    float4 v = make_float4(0.f, 0.f, 0.f, 0.f);
    if (c < g_nsel[e])
        v = ((const float4*)(g_h + (size_t)g_slottok[row] * D_))[tid];
    __nv_bfloat16 h0, h1, h2, h3, l0, l1, l2, l3;
    split_bf(v.x, h0, l0); split_bf(v.y, h1, l1);
    split_bf(v.z, h2, l2); split_bf(v.w, h3, l3);
    __nv_bfloat162* dh = (__nv_bfloat162*)(g_xh + (size_t)row * D_) + 2 * tid;
    __nv_bfloat162* dl = (__nv_bfloat162*)(g_xl + (size_t)row * D_) + 2 * tid;
    dh[0] = __halves2bfloat162(h0, h1); dh[1] = __halves2bfloat162(h2, h3);
    dl[0] = __halves2bfloat162(l0, l1); dl[1] = __halves2bfloat162(l2, l3);
}

// ---------------- weight transpose + bf16 split ----------------
__global__ void wconv_kernel(const float* __restrict__ W, __nv_bfloat16* __restrict__ Th,
                             __nv_bfloat16* __restrict__ Tl, int K, int N) {
    __shared__ float t[32][33];
    int z = blockIdx.z;
    size_t base = (size_t)z * K * N;
    int n0 = blockIdx.x * 32, k0 = blockIdx.y * 32;
    int tx = threadIdx.x & 31, ty = threadIdx.x >> 5;
#pragma unroll
    for (int r = 0; r < 32; r += 8)
        t[ty + r][tx] = W[base + (size_t)(k0 + ty + r) * N + n0 + tx];
    __syncthreads();
#pragma unroll
    for (int r = 0; r < 32; r += 8) {
        float v = t[tx][ty + r];
        __nv_bfloat16 h, l; split_bf(v, h, l);
        size_t o = base + (size_t)(n0 + ty + r) * K + k0 + tx;
        Th[o] = h; Tl[o] = l;
    }
}

// ---------------- cp.async double-buffered mma.sync GEMM ----------------
#define GSMEM 65536

__device__ __forceinline__ void issue_tile(uint32_t sbase, const __nv_bfloat16* __restrict__ g,
                                           int K, int k0, int tid) {
#pragma unroll
    for (int q = 0; q < 2; q++) {
        int i = tid * 2 + q;
        int r = i >> 2, ch = i & 3;
        int sw = ch ^ ((r >> 1) & 3);
        cp_async16(sbase + (uint32_t)(r * 32 + sw * 8) * 2,
                   g + (size_t)r * K + k0 + ch * 8);
    }
}

__device__ __forceinline__ void gemm_mma_body(
    const __nv_bfloat16* __restrict__ Ah, const __nv_bfloat16* __restrict__ Al,
    const __nv_bfloat16* __restrict__ Bh, const __nv_bfloat16* __restrict__ Bl,
    float* Cf, __nv_bfloat16* Ch, __nv_bfloat16* Cl, int N, int K, int act)
{
    extern __shared__ char gsm[];
    uint32_t sb = smem_u32(gsm);
    int tid = threadIdx.x, lane = tid & 31, warp = tid >> 5;
    int wm = (warp & 1) * 64, wn = (warp >> 1) * 32;
    int brow = blockIdx.y * 128, bcol = blockIdx.x * 128;
    const __nv_bfloat16* pAh = Ah + (size_t)brow * K;
    const __nv_bfloat16* pAl = Al + (size_t)brow * K;
    const __nv_bfloat16* pBh = Bh + (size_t)bcol * K;
    const __nv_bfloat16* pBl = Bl + (size_t)bcol * K;

    float acc[4][4][4];
#pragma unroll
    for (int i = 0; i < 4; i++)
#pragma unroll
        for (int j = 0; j < 4; j++)
#pragma unroll
            for (int d = 0; d < 4; d++) acc[i][j][d] = 0.f;

    int g = lane >> 2, t4 = lane & 3;
    int NC = K >> 5;

    issue_tile(sb,         pAh, K, 0, tid);
    issue_tile(sb + 8192,  pAl, K, 0, tid);
    issue_tile(sb + 16384, pBh, K, 0, tid);
    issue_tile(sb + 24576, pBl, K, 0, tid);
    CP_COMMIT();

    for (int c = 0; c < NC; c++) {
        if (c + 1 < NC) {
            uint32_t nb = sb + ((c + 1) & 1) * 32768;
            int k0 = (c + 1) << 5;
            issue_tile(nb,         pAh, K, k0, tid);
            issue_tile(nb + 8192,  pAl, K, k0, tid);
            issue_tile(nb + 16384, pBh, K, k0, tid);
            issue_tile(nb + 24576, pBl, K, k0, tid);
            CP_COMMIT();
            CP_WAIT(1);
        } else {
            CP_WAIT(0);
        }
        __syncthreads();
        const __nv_bfloat16* sAh = (const __nv_bfloat16*)(gsm + (c & 1) * 32768);
        const __nv_bfloat16* sAl = sAh + 4096;
        const __nv_bfloat16* sBh = sAh + 8192;
        const __nv_bfloat16* sBl = sAh + 12288;
#pragma unroll
        for (int kc = 0; kc < 2; kc++) {
            int cb = kc * 16 + t4 * 2;
            uint32_t bh[4][2], bl[4][2];
#pragma unroll
            for (int tn = 0; tn < 4; tn++) {
                int n = wn + tn * 8 + g;
                bh[tn][0] = lds_frag(sBh, n, cb);
                bh[tn][1] = lds_frag(sBh, n, cb + 8);
                bl[tn][0] = lds_frag(sBl, n, cb);
                bl[tn][1] = lds_frag(sBl, n, cb + 8);
            }
#pragma unroll
            for (int tm = 0; tm < 4; tm++) {
                int r = wm + tm * 16 + g;
                uint32_t ah[4], al[4];
                ah[0] = lds_frag(sAh, r, cb);     ah[1] = lds_frag(sAh, r + 8, cb);
                ah[2] = lds_frag(sAh, r, cb + 8); ah[3] = lds_frag(sAh, r + 8, cb + 8);
                al[0] = lds_frag(sAl, r, cb);     al[1] = lds_frag(sAl, r + 8, cb);
                al[2] = lds_frag(sAl, r, cb + 8); al[3] = lds_frag(sAl, r + 8, cb + 8);
#pragma unroll
                for (int tn = 0; tn < 4; tn++) {
                    mma16816(acc[tm][tn], ah, bh[tn]);
                    mma16816(acc[tm][tn], ah, bl[tn]);
                    mma16816(acc[tm][tn], al, bh[tn]);
                }
            }
        }
        __syncthreads();
    }

#pragma unroll
    for (int tm = 0; tm < 4; tm++) {
        int r = brow + wm + tm * 16 + g;
#pragma unroll
        for (int tn = 0; tn < 4; tn++) {
            int c = bcol + wn + tn * 8 + t4 * 2;
            float v0 = acc[tm][tn][0], v1 = acc[tm][tn][1];
            float v2 = acc[tm][tn][2], v3 = acc[tm][tn][3];
            if (Cf) {
                *(float2*)(Cf + (size_t)r * N + c) = make_float2(v0, v1);
                *(float2*)(Cf + (size_t)(r + 8) * N + c) = make_float2(v2, v3);
            } else {
                if (act) { v0 = gelu_f(v0); v1 = gelu_f(v1); v2 = gelu_f(v2); v3 = gelu_f(v3); }
                __nv_bfloat16 h0, l0, h1, l1, h2, l2, h3, l3;
                split_bf(v0, h0, l0); split_bf(v1, h1, l1);
                split_bf(v2, h2, l2); split_bf(v3, h3, l3);
                *(__nv_bfloat162*)(Ch + (size_t)r * N + c) = __halves2bfloat162(h0, h1);
                *(__nv_bfloat162*)(Cl + (size_t)r * N + c) = __halves2bfloat162(l0, l1);
                *(__nv_bfloat162*)(Ch + (size_t)(r + 8) * N + c) = __halves2bfloat162(h2, h3);
                *(__nv_bfloat162*)(Cl + (size_t)(r + 8) * N + c) = __halves2bfloat162(l2, l3);
            }
        }
    }
}

__global__ void __launch_bounds__(256, 2) gemm_mma(
    const __nv_bfloat16* Ah, const __nv_bfloat16* Al,
    const __nv_bfloat16* Bh, const __nv_bfloat16* Bl,
    float* Cf, __nv_bfloat16* Ch, __nv_bfloat16* Cl,
    int N, int K, long long sA, long long sB, long long sC, int act)
{
    long long z = blockIdx.z;
    gemm_mma_body(Ah + z * sA, Al + z * sA, Bh + z * sB, Bl + z * sB,
                  Cf ? Cf + z * sC : (float*)0,
                  Ch ? Ch + z * sC : (__nv_bfloat16*)0,
                  Cl ? Cl + z * sC : (__nv_bfloat16*)0, N, K, act);
}

// q,k -> fp32 g_qkv; v -> bf16 hi/lo directly
__global__ void __launch_bounds__(256, 2) gemm_qkv_mma() {
    int z = blockIdx.z, which = z >> 2, g = z & 3;
    size_t ao = (size_t)(2 * g) * CAP_ * D_;
    size_t wo = (size_t)which * 4194304ull + (size_t)g * 1048576ull;
    if (which < 2) {
        gemm_mma_body(g_xh + ao, g_xl + ao, g_wth + wo, g_wtl + wo,
                      g_qkv + ((size_t)which * 4 + g) * CAP_ * D_,
                      (__nv_bfloat16*)0, (__nv_bfloat16*)0, D_, D_, 0);
    } else {
        gemm_mma_body(g_xh + ao, g_xl + ao, g_wth + wo, g_wtl + wo,
                      (float*)0, g_vh + (size_t)g * CAP_ * D_, g_vl + (size_t)g * CAP_ * D_,
                      D_, D_, 0);
    }
}

// ---------------- RoPE: fp32 q,k -> rotated bf16 hi/lo ----------------
__global__ void rope_kernel() {
    int row = blockIdx.x, g = row >> 10, c = row & 1023, tid = threadIdx.x;
    float pos = (float)g_slottok[(2 * g) * CAP_ + c];
    const float* q = g_qkv + (size_t)row * D_;
    const float* k = g_qkv + 4ull * CAP_ * D_ + (size_t)row * D_;
    size_t ob = (size_t)row * D_;
    for (int idx = tid; idx < 512; idx += 256) {
        int hh = idx >> 5, d0 = idx & 31;
        float invf = (float)exp(-(double)(2 * d0) / 64.0 * 9.210340371976184);
        float ang = pos * invf;
        float cs = cosf(ang), sn = sinf(ang);
        int b = hh * 64 + d0;
        float a0 = q[b], a1 = q[b + 32];
        float q0 = a0 * cs - a1 * sn, q1 = a1 * cs + a0 * sn;
        float b0 = k[b], b1 = k[b + 32];
        float k0 = b0 * cs - b1 * sn, k1 = b1 * cs + b0 * sn;
        __nv_bfloat16 h, l;
        split_bf(q0, h, l); g_qh[ob + b] = h;      g_ql[ob + b] = l;
        split_bf(q1, h, l); g_qh[ob + b + 32] = h; g_ql[ob + b + 32] = l;
        split_bf(k0, h, l); g_kh[ob + b] = h;      g_kl[ob + b] = l;
        split_bf(k1, h, l); g_kh[ob + b + 32] = h; g_kl[ob + b + 32] = l;
    }
}

// ---------------- HMMA flash attention (pre-split bf16 QKV, cp.async) ----------------
#define A_QH  0
#define A_QL  8192
#define A_KH  16384
#define A_KL  24576
#define A_VH  32768
#define A_VL  40960
#define A_PH  49152
#define A_PL  57344
#define A_VTH 65536
#define A_VTL 73984
#define A_PS  82432
#define A_RM  99072
#define A_RL  99328
#define A_RC  99584
#define ATTN_SMEM 99840

__global__ void __launch_bounds__(256, 2) attn_kernel() {
    int qb = blockIdx.x, hh = blockIdx.y, g = blockIdx.z;
    extern __shared__ char sm[];
    uint32_t sb = smem_u32(sm);
    __nv_bfloat16* Qh = (__nv_bfloat16*)(sm + A_QH);
    __nv_bfloat16* Ql = (__nv_bfloat16*)(sm + A_QL);
    __nv_bfloat16* Kh = (__nv_bfloat16*)(sm + A_KH);
    __nv_bfloat16* Kl = (__nv_bfloat16*)(sm + A_KL);
    __nv_bfloat16* Vhs = (__nv_bfloat16*)(sm + A_VH);
    __nv_bfloat16* Vls = (__nv_bfloat16*)(sm + A_VL);
    __nv_bfloat16* Ph = (__nv_bfloat16*)(sm + A_PH);
    __nv_bfloat16* Pl = (__nv_bfloat16*)(sm + A_PL);
    __nv_bfloat16* Vth = (__nv_bfloat16*)(sm + A_VTH);   // [64 d][66 k]
    __nv_bfloat16* Vtl = (__nv_bfloat16*)(sm + A_VTL);
    float* Ps = (float*)(sm + A_PS);                      // [64][65]
    float* rm = (float*)(sm + A_RM);
    float* rl = (float*)(sm + A_RL);
    float* rc = (float*)(sm + A_RC);

    int tid = threadIdx.x, lane = tid & 31, warp = tid >> 5;
    int gq = lane >> 2, t4 = lane & 3;
    int wq = (warp & 3) * 16;
    int wx = (warp >> 2) * 32;

    size_t qoff = ((size_t)(g * CAP_ + qb * 64)) * D_ + hh * 64;
    // Q prologue (512 chunks per tile, 2 tiles -> 4 cp.async/thread)
#pragma unroll
    for (int it = 0; it < 2; it++) {
        int idx = tid + it * 256;
        int r = idx >> 3, ch = idx & 7, sw = ch ^ (r & 7);
        uint32_t off = (uint32_t)(r * 64 + sw * 8) * 2;
        cp_async16(sb + A_QH + off, g_qh + qoff + (size_t)r * D_ + ch * 8);
        cp_async16(sb + A_QL + off, g_ql + qoff + (size_t)r * D_ + ch * 8);
    }
    CP_COMMIT();
    if (tid < 64) { rm[tid] = -3.0e38f; rl[tid] = 0.f; }

    float o[4][4];
#pragma unroll
    for (int i = 0; i < 4; i++)
#pragma unroll
        for (int j = 0; j < 4; j++) o[i][j] = 0.f;

    for (int kt = 0; kt < 16; kt++) {
        __syncthreads();
        size_t koff = ((size_t)(g * CAP_ + kt * 64)) * D_ + hh * 64;
#pragma unroll
        for (int it = 0; it < 2; it++) {
            int idx = tid + it * 256;
            int r = idx >> 3, ch = idx & 7, sw = ch ^ (r & 7);
            uint32_t off = (uint32_t)(r * 64 + sw * 8) * 2;
            const size_t gsrc = koff + (size_t)r * D_ + ch * 8;
            cp_async16(sb + A_KH + off, g_kh + gsrc);
            cp_async16(sb + A_KL + off, g_kl + gsrc);
            cp_async16(sb + A_VH + off, g_vh + gsrc);
            cp_async16(sb + A_VL + off, g_vl + gsrc);
        }
        CP_COMMIT();
        CP_WAIT(0);
        __syncthreads();

        // V transpose into Vt (padded 66), bf16 only
#pragma unroll
        for (int it = 0; it < 2; it++) {
            int idx = tid + it * 256;
            int r = idx >> 3, ch = idx & 7, sw = ch ^ (r & 7);
            uint4 vh = *(const uint4*)(Vhs + r * 64 + sw * 8);
            uint4 vl = *(const uint4*)(Vls + r * 64 + sw * 8);
            const unsigned short* sh = (const unsigned short*)&vh;
            const unsigned short* sl = (const unsigned short*)&vl;
#pragma unroll
            for (int j = 0; j < 8; j++) {
                ((unsigned short*)Vth)[(ch * 8 + j) * 66 + r] = sh[j];
                ((unsigned short*)Vtl)[(ch * 8 + j) * 66 + r] = sl[j];
            }
        }

        // S = Q K^T * 0.125
        float s[4][4];
#pragma unroll
        for (int i = 0; i < 4; i++)
#pragma unroll
            for (int j = 0; j < 4; j++) s[i][j] = 0.f;
#pragma unroll
        for (int ks = 0; ks < 4; ks++) {
            int cb = ks * 16 + t4 * 2;
            uint32_t ah[4], al[4];
            ah[0] = lds_sw64(Qh, wq + gq, cb);     ah[1] = lds_sw64(Qh, wq + gq + 8, cb);
            ah[2] = lds_sw64(Qh, wq + gq, cb + 8); ah[3] = lds_sw64(Qh, wq + gq + 8, cb + 8);
            al[0] = lds_sw64(Ql, wq + gq, cb);     al[1] = lds_sw64(Ql, wq + gq + 8, cb);
            al[2] = lds_sw64(Ql, wq + gq, cb + 8); al[3] = lds_sw64(Ql, wq + gq + 8, cb + 8);
#pragma unroll
            for (int tn = 0; tn < 4; tn++) {
                int n = wx + tn * 8 + gq;
                uint32_t bh[2], bl[2];
                bh[0] = lds_sw64(Kh, n, cb); bh[1] = lds_sw64(Kh, n, cb + 8);
                bl[0] = lds_sw64(Kl, n, cb); bl[1] = lds_sw64(Kl, n, cb + 8);
                mma16816(s[tn], ah, bh);
                mma16816(s[tn], ah, bl);
                mma16816(s[tn], al, bh);
            }
        }
#pragma unroll
        for (int tn = 0; tn < 4; tn++) {
            int c = wx + tn * 8 + t4 * 2;
            Ps[(wq + gq) * 65 + c] = s[tn][0] * 0.125f;
            Ps[(wq + gq) * 65 + c + 1] = s[tn][1] * 0.125f;
            Ps[(wq + gq + 8) * 65 + c] = s[tn][2] * 0.125f;
            Ps[(wq + gq + 8) * 65 + c + 1] = s[tn][3] * 0.125f;
        }
        __syncthreads();

        {
            int row = tid >> 2, part = tid & 3;
            float* pr = Ps + row * 65 + part * 16;
            float tmax = pr[0];
#pragma unroll
            for (int i = 1; i < 16; i++) tmax = fmaxf(tmax, pr[i]);
            tmax = fmaxf(tmax, __shfl_xor_sync(0xffffffffu, tmax, 1));
            tmax = fmaxf(tmax, __shfl_xor_sync(0xffffffffu, tmax, 2));
            float mold = rm[row];
            float mnew = fmaxf(mold, tmax);
            float sum = 0.f;
#pragma unroll
            for (int i = 0; i < 16; i += 2) {
                float p0 = expf(pr[i] - mnew);
                float p1 = expf(pr[i + 1] - mnew);
                sum += p0 + p1;
                __nv_bfloat16 h0, l0, h1, l1;
                split_bf(p0, h0, l0); split_bf(p1, h1, l1);
                int c = part * 16 + i;
                int ch = c >> 3, sw = ch ^ (row & 7);
                int off = row * 64 + sw * 8 + (c & 7);
                *(__nv_bfloat162*)(Ph + off) = __halves2bfloat162(h0, h1);
                *(__nv_bfloat162*)(Pl + off) = __halves2bfloat162(l0, l1);
            }
            sum += __shfl_xor_sync(0xffffffffu, sum, 1);
            sum += __shfl_xor_sync(0xffffffffu, sum, 2);
            __syncwarp();
            if (part == 0) {
                float corr = expf(mold - mnew);
                rc[row] = corr;
                rl[row] = rl[row] * corr + sum;
                rm[row] = mnew;
            }
        }
        __syncthreads();

        float cr0 = rc[wq + gq], cr1 = rc[wq + gq + 8];
#pragma unroll
        for (int tn = 0; tn < 4; tn++) {
            o[tn][0] *= cr0; o[tn][1] *= cr0;
            o[tn][2] *= cr1; o[tn][3] *= cr1;
        }
#pragma unroll
        for (int ks = 0; ks < 4; ks++) {
            int cb = ks * 16 + t4 * 2;
            uint32_t ah[4], al[4];
            ah[0] = lds_sw64(Ph, wq + gq, cb);     ah[1] = lds_sw64(Ph, wq + gq + 8, cb);
            ah[2] = lds_sw64(Ph, wq + gq, cb + 8); ah[3] = lds_sw64(Ph, wq + gq + 8, cb + 8);
            al[0] = lds_sw64(Pl, wq + gq, cb);     al[1] = lds_sw64(Pl, wq + gq + 8, cb);
            al[2] = lds_sw64(Pl, wq + gq, cb + 8); al[3] = lds_sw64(Pl, wq + gq + 8, cb + 8);
#pragma unroll
            for (int tn = 0; tn < 4; tn++) {
                int n = wx + tn * 8 + gq;
                uint32_t bh[2], bl[2];
                bh[0] = *(const uint32_t*)(Vth + n * 66 + cb);
                bh[1] = *(const uint32_t*)(Vth + n * 66 + cb + 8);
                bl[0] = *(const uint32_t*)(Vtl + n * 66 + cb);
                bl[1] = *(const uint32_t*)(Vtl + n * 66 + cb + 8);
                mma16816(o[tn], ah, bh);
                mma16816(o[tn], ah, bl);
                mma16816(o[tn], al, bh);
            }
        }
    }
    __syncthreads();

    float inv0 = 1.f / rl[wq + gq], inv1 = 1.f / rl[wq + gq + 8];
    size_t obase = ((size_t)(g * CAP_ + qb * 64)) * D_ + hh * 64;
#pragma unroll
    for (int tn = 0; tn < 4; tn++) {
        int c = wx + tn * 8 + t4 * 2;
        __nv_bfloat16 h0, l0, h1, l1;
        split_bf(o[tn][0] * inv0, h0, l0); split_bf(o[tn][1] * inv0, h1, l1);
        size_t off = obase + (size_t)(wq + gq) * D_ + c;
        *(__nv_bfloat162*)(g_ah + off) = __halves2bfloat162(h0, h1);
        *(__nv_bfloat162*)(g_al + off) = __halves2bfloat162(l0, l1);
        split_bf(o[tn][2] * inv1, h0, l0); split_bf(o[tn][3] * inv1, h1, l1);
        off = obase + (size_t)(wq + gq + 8) * D_ + c;
        *(__nv_bfloat162*)(g_ah + off) = __halves2bfloat162(h0, h1);
        *(__nv_bfloat162*)(g_al + off) = __halves2bfloat162(l0, l1);
    }
}

// ---------------- combine ----------------
__global__ void combine_kernel() {
    int t = blockIdx.x, tid = threadIdx.x;
    __shared__ float scw[8];
    __shared__ int ssl[8];
    if (tid < 8) { scw[tid] = g_cw[t * 8 + tid]; ssl[tid] = g_slotof[tid * T_ + t]; }
    __syncthreads();
    float4* hr = (float4*)(g_h + (size_t)t * D_);
    float4 hv = hr[tid];
    float rho = 0.f;
    float4 acc = make_float4(0.f, 0.f, 0.f, 0.f);
#pragma unroll
    for (int e = 0; e < 8; e++) {
        int s = ssl[e];
        if (s >= 0) {
            float w = scw[e];
            rho += w;
            float4 ev = ((const float4*)(g_expo + ((size_t)e * CAP_ + s) * D_))[tid];
            acc.x = fmaf(w, ev.x, acc.x); acc.y = fmaf(w, ev.y, acc.y);
            acc.z = fmaf(w, ev.z, acc.z); acc.w = fmaf(w, ev.w, acc.w);
        }
    }
    float om = 1.f - rho;
    hv.x = hv.x * om + acc.x; hv.y = hv.y * om + acc.y;
    hv.z = hv.z * om + acc.z; hv.w = hv.w * om + acc.w;
    hr[tid] = hv;
}

// ---------------- final RMSNorm ----------------
__global__ void rmsnorm_kernel(const float* __restrict__ lnw, float* __restrict__ out) {
    int t = blockIdx.x, tid = threadIdx.x;
    float4 v = ((const float4*)(g_h + (size_t)t * D_))[tid];
    float ss = v.x * v.x + v.y * v.y + v.z * v.z + v.w * v.w;
#pragma unroll
    for (int o = 16; o > 0; o >>= 1) ss += __shfl_xor_sync(0xffffffffu, ss, o);
    __shared__ float red[8];
    if ((tid & 31) == 0) red[tid >> 5] = ss;
    __syncthreads();
    if (tid == 0) {
        float s = 0.f;
        for (int i = 0; i < 8; i++) s += red[i];
        red[0] = rsqrtf(s / (float)D_ + 1e-6f);
    }
    __syncthreads();
    float sc = red[0];
    float4 w = ((const float4*)lnw)[tid];
    float4 o4 = make_float4(v.x * sc * w.x, v.y * sc * w.y, v.z * sc * w.z, v.w * sc * w.w);
    ((float4*)out)[(size_t)t * 256 + tid] = o4;
}

// ---------------- launch ----------------
extern "C" void kernel_launch(void* const* d_in, const int* in_sizes, int n_in,
                              void* d_out, int out_size) {
    const int*   ids      = (const int*)d_in[0];
    const float* embed_w  = (const float*)d_in[1];
    const float* router_w = (const float*)d_in[2];
    const float* wq       = (const float*)d_in[3];
    const float* wk       = (const float*)d_in[4];
    const float* wv       = (const float*)d_in[5];
    const float* wo       = (const float*)d_in[6];
    const float* w1       = (const float*)d_in[7];
    const float* w2       = (const float*)d_in[8];
    const float* lnw      = (const float*)d_in[9];
    float* out = (float*)d_out;

    __nv_bfloat16 *p_wth, *p_wtl, *p_xh, *p_xl, *p_ah, *p_al, *p_fh, *p_fl;
    float *p_expo;
    cudaGetSymbolAddress((void**)&p_wth, g_wth);
    cudaGetSymbolAddress((void**)&p_wtl, g_wtl);
    cudaGetSymbolAddress((void**)&p_xh,  g_xh);
    cudaGetSymbolAddress((void**)&p_xl,  g_xl);
    cudaGetSymbolAddress((void**)&p_ah,  g_ah);
    cudaGetSymbolAddress((void**)&p_al,  g_al);
    cudaGetSymbolAddress((void**)&p_fh,  g_fh);
    cudaGetSymbolAddress((void**)&p_fl,  g_fl);
    cudaGetSymbolAddress((void**)&p_expo, g_expo);

    cudaFuncSetAttribute(attn_kernel, cudaFuncAttributeMaxDynamicSharedMemorySize, ATTN_SMEM);
    cudaFuncSetAttribute(gemm_mma, cudaFuncAttributeMaxDynamicSharedMemorySize, GSMEM);
    cudaFuncSetAttribute(gemm_qkv_mma, cudaFuncAttributeMaxDynamicSharedMemorySize, GSMEM);

    wconv_kernel<<<dim3(32, 32, 4), 256>>>(wq, p_wth + WQ_OFF, p_wtl + WQ_OFF, D_, D_);
    wconv_kernel<<<dim3(32, 32, 4), 256>>>(wk, p_wth + WK_OFF, p_wtl + WK_OFF, D_, D_);
    wconv_kernel<<<dim3(32, 32, 4), 256>>>(wv, p_wth + WV_OFF, p_wtl + WV_OFF, D_, D_);
    wconv_kernel<<<dim3(32, 32, 4), 256>>>(wo, p_wth + WO_OFF, p_wtl + WO_OFF, D_, D_);
    wconv_kernel<<<dim3(128, 32, 4), 256>>>(w1, p_wth + W1_OFF, p_wtl + W1_OFF, D_, MLP_);
    wconv_kernel<<<dim3(32, 128, 4), 256>>>(w2, p_wth + W2_OFF, p_wtl + W2_OFF, MLP_, D_);

    embed_kernel<<<T_, 256>>>(ids, embed_w);
    for (int hop = 0; hop < 3; hop++) {
        router_kernel<<<T_ / 8, 256>>>(router_w + (size_t)hop * 9 * D_);
        capacity_kernel<<<E_, 1024>>>();
        gather_kernel<<<E_ * CAP_, 256>>>();
        gemm_qkv_mma<<<dim3(8, 8, 12), 256, GSMEM>>>();
        rope_kernel<<<4 * CAP_, 256>>>();
        attn_kernel<<<dim3(16, 16, 4), 256, ATTN_SMEM>>>();
        gemm_mma<<<dim3(8, 8, 4), 256, GSMEM>>>(
            p_ah, p_al, p_wth + WO_OFF, p_wtl + WO_OFF,
            p_expo, (__nv_bfloat16*)0, (__nv_bfloat16*)0,
            D_, D_, (long long)CAP_ * D_, (long long)D_ * D_, 2LL * CAP_ * D_, 0);
        gemm_mma<<<dim3(32, 8, 4), 256, GSMEM>>>(
            p_xh + (size_t)CAP_ * D_, p_xl + (size_t)CAP_ * D_,
            p_wth + W1_OFF, p_wtl + W1_OFF,
            (float*)0, p_fh, p_fl,
            MLP_, D_, 2LL * CAP_ * D_, (long long)D_ * MLP_, (long long)CAP_ * MLP_, 1);
        gemm_mma<<<dim3(8, 8, 4), 256, GSMEM>>>(
            p_fh, p_fl, p_wth + W2_OFF, p_wtl + W2_OFF,
            p_expo + (size_t)CAP_ * D_, (__nv_bfloat16*)0, (__nv_bfloat16*)0,
            D_, MLP_, (long long)CAP_ * MLP_, (long long)MLP_ * D_, 2LL * CAP_ * D_, 0);
        combine_kernel<<<T_, 256>>>();
    }
    rmsnorm_kernel<<<T_, 256>>>(lnw, out);
}

// round 12
// speedup vs baseline: 4.3788x; 2.0108x over previous
#include <cuda_runtime.h>
#include <cuda_fp16.h>
#include <cstdint>
#include <stdint.h>
#include <math.h>

#define T_    4096
#define D_    1024
#define E_    8
#define CAP_  1024
#define MLP_  4096

// ---------------- device scratch ----------------
__device__ float g_h[(size_t)T_ * D_];
__device__ float g_qkv[8ull * CAP_ * D_];          // fp32 q (0-3), k (4-7) pre-RoPE
__device__ float g_expo[(size_t)E_ * CAP_ * D_];
__device__ float g_probs[T_ * 8];
__device__ unsigned char g_maskb[T_];
__device__ int   g_slottok[E_ * CAP_];
__device__ int   g_slotof[E_ * T_];
__device__ float g_cw[T_ * 8];
__device__ int   g_nsel[E_];

__device__ __half g_x[(size_t)E_ * CAP_ * D_];
__device__ __half g_q[4ull * CAP_ * D_];
__device__ __half g_k[4ull * CAP_ * D_];
__device__ __half g_v[4ull * CAP_ * D_];
__device__ __half g_a[4ull * CAP_ * D_];
__device__ __half g_f[4ull * CAP_ * MLP_];

#define WQ_OFF 0ull
#define WK_OFF 4194304ull
#define WV_OFF 8388608ull
#define WO_OFF 12582912ull
#define W1_OFF 16777216ull
#define W2_OFF 33554432ull
#define WT_TOT 50331648ull
__device__ __half g_wt[WT_TOT];

// ---------------- helpers ----------------
__device__ __forceinline__ uint32_t smem_u32(const void* p) {
    uint32_t a;
    asm("{ .reg .u64 t; cvta.to.shared.u64 t, %1; cvt.u32.u64 %0, t; }" : "=r"(a) : "l"(p));
    return a;
}
__device__ __forceinline__ void cp_async16(uint32_t saddr, const void* gptr) {
    asm volatile("cp.async.cg.shared.global [%0], [%1], 16;" :: "r"(saddr), "l"(gptr));
}
#define CP_COMMIT() asm volatile("cp.async.commit_group;")
#define CP_WAIT(n)  asm volatile("cp.async.wait_group %0;" :: "n"(n))

__device__ __forceinline__ float gelu_f(float x) {
    float x3 = x * x * x;
    return 0.5f * x * (1.f + tanhf(0.7978845608028654f * (x + 0.044715f * x3)));
}
__device__ __forceinline__ void mma16816(float* d, const uint32_t* a, const uint32_t* b) {
    asm volatile(
        "mma.sync.aligned.m16n8k16.row.col.f32.f16.f16.f32 "
        "{%0,%1,%2,%3}, {%4,%5,%6,%7}, {%8,%9}, {%0,%1,%2,%3};"
        : "+f"(d[0]), "+f"(d[1]), "+f"(d[2]), "+f"(d[3])
        : "r"(a[0]), "r"(a[1]), "r"(a[2]), "r"(a[3]), "r"(b[0]), "r"(b[1]));
}
// 32 f16/row tile (GEMM), chunk ch stored at ch^((r>>1)&3)
__device__ __forceinline__ uint32_t lds_frag(const __half* base, int r, int c) {
    int ch = c >> 3;
    int sw = ch ^ ((r >> 1) & 3);
    return *(const uint32_t*)(base + r * 32 + sw * 8 + (c & 7));
}
// 64 f16/row tile (attention), chunk ch stored at ch^(r&7)
__device__ __forceinline__ uint32_t lds_sw64(const __half* base, int r, int c) {
    int ch = c >> 3;
    int sw = ch ^ (r & 7);
    return *(const uint32_t*)(base + r * 64 + sw * 8 + (c & 7));
}

// ---------------- embedding ----------------
__global__ void embed_kernel(const int* __restrict__ ids, const float* __restrict__ ew) {
    int t = blockIdx.x, tid = threadIdx.x;
    ((float4*)(g_h + (size_t)t * D_))[tid] =
        ((const float4*)(ew + (size_t)ids[t] * D_))[tid];
}

// ---------------- router ----------------
__global__ void router_kernel(const float* __restrict__ rw) {
    int gw = (blockIdx.x * blockDim.x + threadIdx.x) >> 5;
    int lane = threadIdx.x & 31;
    if (gw >= T_) return;
    const float* hr = g_h + (size_t)gw * D_;
    float acc[9];
#pragma unroll
    for (int e = 0; e < 9; e++) acc[e] = 0.f;
    for (int d = lane; d < D_; d += 32) {
        float hv = hr[d];
#pragma unroll
        for (int e = 0; e < 9; e++) acc[e] = fmaf(hv, rw[e * D_ + d], acc[e]);
    }
#pragma unroll
    for (int e = 0; e < 9; e++)
#pragma unroll
        for (int o = 16; o > 0; o >>= 1) acc[e] += __shfl_xor_sync(0xffffffffu, acc[e], o);
    if (lane == 0) {
        float mx = acc[0];
#pragma unroll
        for (int e = 1; e < 9; e++) mx = fmaxf(mx, acc[e]);
        float ex[9], s = 0.f;
#pragma unroll
        for (int e = 0; e < 9; e++) { ex[e] = expf(acc[e] - mx); s += ex[e]; }
        float inv = 1.f / s;
        int a1 = 0; float v1 = acc[0];
#pragma unroll
        for (int e = 1; e < 9; e++) if (acc[e] > v1) { v1 = acc[e]; a1 = e; }
        int a2 = -1; float v2 = -3.0e38f;
#pragma unroll
        for (int e = 0; e < 9; e++) if (e != a1 && acc[e] > v2) { v2 = acc[e]; a2 = e; }
        unsigned char m = 0;
        if (a1 < 8) m |= (unsigned char)(1 << a1);
        if (a2 < 8) m |= (unsigned char)(1 << a2);
        g_maskb[gw] = m;
#pragma unroll
        for (int e = 0; e < 8; e++) g_probs[gw * 8 + e] = ex[e] * inv;
    }
}

// ---------------- capacity select ----------------
__global__ void __launch_bounds__(1024) capacity_kernel() {
    int e = blockIdx.x, tid = threadIdx.x;
    __shared__ unsigned long long keys[T_];
    __shared__ int s_count;
    if (tid == 0) s_count = 0;
    __syncthreads();
    int local = 0;
    for (int t = tid; t < T_; t += 1024) {
        unsigned long long key = 0ull;
        if (g_maskb[t] & (1 << e)) {
            unsigned pb = __float_as_uint(g_probs[t * 8 + e]);
            key = ((unsigned long long)pb << 32) | (unsigned)(0xFFFFFFFFu - (unsigned)t);
            local++;
        }
        keys[t] = key;
    }
#pragma unroll
    for (int o = 16; o > 0; o >>= 1) local += __shfl_xor_sync(0xffffffffu, local, o);
    if ((tid & 31) == 0) atomicAdd(&s_count, local);
    __syncthreads();
    for (int k = 2; k <= T_; k <<= 1)
        for (int j = k >> 1; j > 0; j >>= 1) {
            for (int i = tid; i < T_; i += 1024) {
                int ixj = i ^ j;
                if (ixj > i) {
                    unsigned long long a = keys[i], b = keys[ixj];
                    bool desc = ((i & k) == 0);
                    if (desc ? (a < b) : (a > b)) { keys[i] = b; keys[ixj] = a; }
                }
            }
            __syncthreads();
        }
    int nsel = min(s_count, CAP_);
    if (tid == 0) g_nsel[e] = nsel;
    for (int t = tid; t < T_; t += 1024) { g_slotof[e * T_ + t] = -1; g_cw[t * 8 + e] = 0.f; }
    __syncthreads();
    int c = tid;
    if (c < nsel) {
        unsigned long long key = keys[c];
        int tok = (int)(0xFFFFFFFFu - (unsigned)(key & 0xFFFFFFFFull));
        g_slottok[e * CAP_ + c] = tok;
        g_slotof[e * T_ + tok] = c;
        g_cw[tok * 8 + e] = __uint_as_float((unsigned)(key >> 32));
    } else if (c < CAP_) {
        g_slottok[e * CAP_ + c] = 0;
    }
}

// ---------------- gather -> fp16 ----------------
__global__ void gather_kernel() {
    int row = blockIdx.x, e = row >> 10, c = row & 1023, tid = threadIdx.x;
    float4 v = make_float4(0.f, 0.f, 0.f, 0.f);
    if (c < g_nsel[e])
        v = ((const float4*)(g_h + (size_t)g_slottok[row] * D_))[tid];
    __half2* d = (__half2*)(g_x + (size_t)row * D_) + 2 * tid;
    d[0] = __halves2half2(__float2half_rn(v.x), __float2half_rn(v.y));
    d[1] = __halves2half2(__float2half_rn(v.z), __float2half_rn(v.w));
}

// ---------------- weight transpose + fp16: W[K][N] -> WT[N][K] ----------------
__global__ void wconv_kernel(const float* __restrict__ W, __half* __restrict__ Th, int K, int N) {
    __shared__ float t[32][33];
    int z = blockIdx.z;
    size_t base = (size_t)z * K * N;
    int n0 = blockIdx.x * 32, k0 = blockIdx.y * 32;
    int tx = threadIdx.x & 31, ty = threadIdx.x >> 5;
#pragma unroll
    for (int r = 0; r < 32; r += 8)
        t[ty + r][tx] = W[base + (size_t)(k0 + ty + r) * N + n0 + tx];
    __syncthreads();
#pragma unroll
    for (int r = 0; r < 32; r += 8)
        Th[base + (size_t)(n0 + ty + r) * K + k0 + tx] = __float2half_rn(t[tx][ty + r]);
}

// ---------------- cp.async 3-stage pipelined fp16 mma.sync GEMM ----------------
// stage = A tile (8KB) + B tile (8KB) = 16KB; 3 stages = 48KB
#define GSMEM 49152

__device__ __forceinline__ void issue_tile(uint32_t sbase, const __half* __restrict__ g,
                                           int K, int k0, int tid) {
#pragma unroll
    for (int q = 0; q < 2; q++) {
        int i = tid * 2 + q;
        int r = i >> 2, ch = i & 3;
        int sw = ch ^ ((r >> 1) & 3);
        cp_async16(sbase + (uint32_t)(r * 32 + sw * 8) * 2,
                   g + (size_t)r * K + k0 + ch * 8);
    }
}

__device__ __forceinline__ void gemm_mma_body(
    const __half* __restrict__ A, const __half* __restrict__ B,
    float* Cf, __half* Ch, int N, int K, int act)
{
    extern __shared__ char gsm[];
    uint32_t sb = smem_u32(gsm);
    int tid = threadIdx.x, lane = tid & 31, warp = tid >> 5;
    int wm = (warp & 1) * 64, wn = (warp >> 1) * 32;
    int brow = blockIdx.y * 128, bcol = blockIdx.x * 128;
    const __half* pA = A + (size_t)brow * K;
    const __half* pB = B + (size_t)bcol * K;

    float acc[4][4][4];
#pragma unroll
    for (int i = 0; i < 4; i++)
#pragma unroll
        for (int j = 0; j < 4; j++)
#pragma unroll
            for (int d = 0; d < 4; d++) acc[i][j][d] = 0.f;

    int g = lane >> 2, t4 = lane & 3;
    int NC = K >> 5;

    // prologue: stages 0 and 1
    issue_tile(sb,        pA, K, 0, tid);
    issue_tile(sb + 8192, pB, K, 0, tid);
    CP_COMMIT();
    if (NC > 1) {
        issue_tile(sb + 16384,        pA, K, 32, tid);
        issue_tile(sb + 16384 + 8192, pB, K, 32, tid);
    }
    CP_COMMIT();

    for (int c = 0; c < NC; c++) {
        if (c + 2 < NC) {
            uint32_t nb = sb + (uint32_t)((c + 2) % 3) * 16384;
            int k0 = (c + 2) << 5;
            issue_tile(nb,        pA, K, k0, tid);
            issue_tile(nb + 8192, pB, K, k0, tid);
        }
        CP_COMMIT();
        CP_WAIT(2);
        __syncthreads();
        const __half* sA = (const __half*)(gsm + (c % 3) * 16384);
        const __half* sB = sA + 4096;
#pragma unroll
        for (int kc = 0; kc < 2; kc++) {
            int cb = kc * 16 + t4 * 2;
            uint32_t bfr[4][2];
#pragma unroll
            for (int tn = 0; tn < 4; tn++) {
                int n = wn + tn * 8 + g;
                bfr[tn][0] = lds_frag(sB, n, cb);
                bfr[tn][1] = lds_frag(sB, n, cb + 8);
            }
#pragma unroll
            for (int tm = 0; tm < 4; tm++) {
                int r = wm + tm * 16 + g;
                uint32_t afr[4];
                afr[0] = lds_frag(sA, r, cb);     afr[1] = lds_frag(sA, r + 8, cb);
                afr[2] = lds_frag(sA, r, cb + 8); afr[3] = lds_frag(sA, r + 8, cb + 8);
#pragma unroll
                for (int tn = 0; tn < 4; tn++)
                    mma16816(acc[tm][tn], afr, bfr[tn]);
            }
        }
        __syncthreads();
    }

#pragma unroll
    for (int tm = 0; tm < 4; tm++) {
        int r = brow + wm + tm * 16 + g;
#pragma unroll
        for (int tn = 0; tn < 4; tn++) {
            int c = bcol + wn + tn * 8 + t4 * 2;
            float v0 = acc[tm][tn][0], v1 = acc[tm][tn][1];
            float v2 = acc[tm][tn][2], v3 = acc[tm][tn][3];
            if (Cf) {
                *(float2*)(Cf + (size_t)r * N + c) = make_float2(v0, v1);
                *(float2*)(Cf + (size_t)(r + 8) * N + c) = make_float2(v2, v3);
            } else {
                if (act) { v0 = gelu_f(v0); v1 = gelu_f(v1); v2 = gelu_f(v2); v3 = gelu_f(v3); }
                *(__half2*)(Ch + (size_t)r * N + c) =
                    __halves2half2(__float2half_rn(v0), __float2half_rn(v1));
                *(__half2*)(Ch + (size_t)(r + 8) * N + c) =
                    __halves2half2(__float2half_rn(v2), __float2half_rn(v3));
            }
        }
    }
}

__global__ void __launch_bounds__(256, 2) gemm_mma(
    const __half* A, const __half* B, float* Cf, __half* Ch,
    int N, int K, long long sA, long long sB, long long sC, int act)
{
    long long z = blockIdx.z;
    gemm_mma_body(A + z * sA, B + z * sB,
                  Cf ? Cf + z * sC : (float*)0,
                  Ch ? Ch + z * sC : (__half*)0, N, K, act);
}

// q,k -> fp32 g_qkv (pre-RoPE); v -> fp16 directly
__global__ void __launch_bounds__(256, 2) gemm_qkv_mma() {
    int z = blockIdx.z, which = z >> 2, g = z & 3;
    size_t ao = (size_t)(2 * g) * CAP_ * D_;
    size_t wo = (size_t)which * 4194304ull + (size_t)g * 1048576ull;
    if (which < 2) {
        gemm_mma_body(g_x + ao, g_wt + wo,
                      g_qkv + ((size_t)which * 4 + g) * CAP_ * D_, (__half*)0, D_, D_, 0);
    } else {
        gemm_mma_body(g_x + ao, g_wt + wo,
                      (float*)0, g_v + (size_t)g * CAP_ * D_, D_, D_, 0);
    }
}

// ---------------- RoPE: fp32 q,k -> rotated fp16 ----------------
__global__ void rope_kernel() {
    int row = blockIdx.x, g = row >> 10, c = row & 1023, tid = threadIdx.x;
    float pos = (float)g_slottok[(2 * g) * CAP_ + c];
    const float* q = g_qkv + (size_t)row * D_;
    const float* k = g_qkv + 4ull * CAP_ * D_ + (size_t)row * D_;
    size_t ob = (size_t)row * D_;
    for (int idx = tid; idx < 512; idx += 256) {
        int hh = idx >> 5, d0 = idx & 31;
        float invf = (float)exp(-(double)(2 * d0) / 64.0 * 9.210340371976184);
        float ang = pos * invf;
        float cs = cosf(ang), sn = sinf(ang);
        int b = hh * 64 + d0;
        float a0 = q[b], a1 = q[b + 32];
        g_q[ob + b]      = __float2half_rn(a0 * cs - a1 * sn);
        g_q[ob + b + 32] = __float2half_rn(a1 * cs + a0 * sn);
        float b0 = k[b], b1 = k[b + 32];
        g_k[ob + b]      = __float2half_rn(b0 * cs - b1 * sn);
        g_k[ob + b + 32] = __float2half_rn(b1 * cs + b0 * sn);
    }
}

// ---------------- HMMA flash attention (fp16, single MMA) ----------------
#define A_Q   0
#define A_K   8192
#define A_V   16384
#define A_P   24576
#define A_VT  32768
#define A_PS  41216
#define A_RM  57856
#define A_RL  58112
#define A_RC  58368
#define ATTN_SMEM 58624

__global__ void __launch_bounds__(256, 2) attn_kernel() {
    int qb = blockIdx.x, hh = blockIdx.y, g = blockIdx.z;
    extern __shared__ char sm[];
    uint32_t sb = smem_u32(sm);
    __half* Qs = (__half*)(sm + A_Q);
    __half* Ks = (__half*)(sm + A_K);
    __half* Vs = (__half*)(sm + A_V);
    __half* Ph = (__half*)(sm + A_P);
    __half* Vt = (__half*)(sm + A_VT);   // [64 d][66 k]
    float* Ps = (float*)(sm + A_PS);     // [64][65]
    float* rm = (float*)(sm + A_RM);
    float* rl = (float*)(sm + A_RL);
    float* rc = (float*)(sm + A_RC);

    int tid = threadIdx.x, lane = tid & 31, warp = tid >> 5;
    int gq = lane >> 2, t4 = lane & 3;
    int wq = (warp & 3) * 16;
    int wx = (warp >> 2) * 32;

    size_t qoff = ((size_t)(g * CAP_ + qb * 64)) * D_ + hh * 64;
#pragma unroll
    for (int it = 0; it < 2; it++) {
        int idx = tid + it * 256;
        int r = idx >> 3, ch = idx & 7, sw = ch ^ (r & 7);
        cp_async16(sb + A_Q + (uint32_t)(r * 64 + sw * 8) * 2,
                   g_q + qoff + (size_t)r * D_ + ch * 8);
    }
    CP_COMMIT();
    if (tid < 64) { rm[tid] = -3.0e38f; rl[tid] = 0.f; }

    float o[4][4];
#pragma unroll
    for (int i = 0; i < 4; i++)
#pragma unroll
        for (int j = 0; j < 4; j++) o[i][j] = 0.f;

    for (int kt = 0; kt < 16; kt++) {
        __syncthreads();
        size_t koff = ((size_t)(g * CAP_ + kt * 64)) * D_ + hh * 64;
#pragma unroll
        for (int it = 0; it < 2; it++) {
            int idx = tid + it * 256;
            int r = idx >> 3, ch = idx & 7, sw = ch ^ (r & 7);
            uint32_t off = (uint32_t)(r * 64 + sw * 8) * 2;
            const size_t gsrc = koff + (size_t)r * D_ + ch * 8;
            cp_async16(sb + A_K + off, g_k + gsrc);
            cp_async16(sb + A_V + off, g_v + gsrc);
        }
        CP_COMMIT();
        CP_WAIT(0);
        __syncthreads();

        // V transpose into Vt (padded 66)
#pragma unroll
        for (int it = 0; it < 2; it++) {
            int idx = tid + it * 256;
            int r = idx >> 3, ch = idx & 7, sw = ch ^ (r & 7);
            uint4 vv = *(const uint4*)(Vs + r * 64 + sw * 8);
            const unsigned short* sv = (const unsigned short*)&vv;
#pragma unroll
            for (int j = 0; j < 8; j++)
                ((unsigned short*)Vt)[(ch * 8 + j) * 66 + r] = sv[j];
        }

        // S = Q K^T * 0.125
        float s[4][4];
#pragma unroll
        for (int i = 0; i < 4; i++)
#pragma unroll
            for (int j = 0; j < 4; j++) s[i][j] = 0.f;
#pragma unroll
        for (int ks = 0; ks < 4; ks++) {
            int cb = ks * 16 + t4 * 2;
            uint32_t afr[4];
            afr[0] = lds_sw64(Qs, wq + gq, cb);     afr[1] = lds_sw64(Qs, wq + gq + 8, cb);
            afr[2] = lds_sw64(Qs, wq + gq, cb + 8); afr[3] = lds_sw64(Qs, wq + gq + 8, cb + 8);
#pragma unroll
            for (int tn = 0; tn < 4; tn++) {
                int n = wx + tn * 8 + gq;
                uint32_t bfr[2];
                bfr[0] = lds_sw64(Ks, n, cb); bfr[1] = lds_sw64(Ks, n, cb + 8);
                mma16816(s[tn], afr, bfr);
            }
        }
#pragma unroll
        for (int tn = 0; tn < 4; tn++) {
            int c = wx + tn * 8 + t4 * 2;
            Ps[(wq + gq) * 65 + c] = s[tn][0] * 0.125f;
            Ps[(wq + gq) * 65 + c + 1] = s[tn][1] * 0.125f;
            Ps[(wq + gq + 8) * 65 + c] = s[tn][2] * 0.125f;
            Ps[(wq + gq + 8) * 65 + c + 1] = s[tn][3] * 0.125f;
        }
        __syncthreads();

        {
            int row = tid >> 2, part = tid & 3;
            float* pr = Ps + row * 65 + part * 16;
            float tmax = pr[0];
#pragma unroll
            for (int i = 1; i < 16; i++) tmax = fmaxf(tmax, pr[i]);
            tmax = fmaxf(tmax, __shfl_xor_sync(0xffffffffu, tmax, 1));
            tmax = fmaxf(tmax, __shfl_xor_sync(0xffffffffu, tmax, 2));
            float mold = rm[row];
            float mnew = fmaxf(mold, tmax);
            float sum = 0.f;
#pragma unroll
            for (int i = 0; i < 16; i += 2) {
                float p0 = expf(pr[i] - mnew);
                float p1 = expf(pr[i + 1] - mnew);
                sum += p0 + p1;
                int c = part * 16 + i;
                int ch = c >> 3, sw = ch ^ (row & 7);
                *(__half2*)(Ph + row * 64 + sw * 8 + (c & 7)) =
                    __halves2half2(__float2half_rn(p0), __float2half_rn(p1));
            }
            sum += __shfl_xor_sync(0xffffffffu, sum, 1);
            sum += __shfl_xor_sync(0xffffffffu, sum, 2);
            __syncwarp();
            if (part == 0) {
                float corr = expf(mold - mnew);
                rc[row] = corr;
                rl[row] = rl[row] * corr + sum;
                rm[row] = mnew;
            }
        }
        __syncthreads();

        float cr0 = rc[wq + gq], cr1 = rc[wq + gq + 8];
#pragma unroll
        for (int tn = 0; tn < 4; tn++) {
            o[tn][0] *= cr0; o[tn][1] *= cr0;
            o[tn][2] *= cr1; o[tn][3] *= cr1;
        }
#pragma unroll
        for (int ks = 0; ks < 4; ks++) {
            int cb = ks * 16 + t4 * 2;
            uint32_t afr[4];
            afr[0] = lds_sw64(Ph, wq + gq, cb);     afr[1] = lds_sw64(Ph, wq + gq + 8, cb);
            afr[2] = lds_sw64(Ph, wq + gq, cb + 8); afr[3] = lds_sw64(Ph, wq + gq + 8, cb + 8);
#pragma unroll
            for (int tn = 0; tn < 4; tn++) {
                int n = wx + tn * 8 + gq;
                uint32_t bfr[2];
                bfr[0] = *(const uint32_t*)(Vt + n * 66 + cb);
                bfr[1] = *(const uint32_t*)(Vt + n * 66 + cb + 8);
                mma16816(o[tn], afr, bfr);
            }
        }
    }
    __syncthreads();

    float inv0 = 1.f / rl[wq + gq], inv1 = 1.f / rl[wq + gq + 8];
    size_t obase = ((size_t)(g * CAP_ + qb * 64)) * D_ + hh * 64;
#pragma unroll
    for (int tn = 0; tn < 4; tn++) {
        int c = wx + tn * 8 + t4 * 2;
        size_t off = obase + (size_t)(wq + gq) * D_ + c;
        *(__half2*)(g_a + off) =
            __halves2half2(__float2half_rn(o[tn][0] * inv0), __float2half_rn(o[tn][1] * inv0));
        off = obase + (size_t)(wq + gq + 8) * D_ + c;
        *(__half2*)(g_a + off) =
            __halves2half2(__float2half_rn(o[tn][2] * inv1), __float2half_rn(o[tn][3] * inv1));
    }
}

// ---------------- combine ----------------
__global__ void combine_kernel() {
    int t = blockIdx.x, tid = threadIdx.x;
    __shared__ float scw[8];
    __shared__ int ssl[8];
    if (tid < 8) { scw[tid] = g_cw[t * 8 + tid]; ssl[tid] = g_slotof[tid * T_ + t]; }
    __syncthreads();
    float4* hr = (float4*)(g_h + (size_t)t * D_);
    float4 hv = hr[tid];
    float rho = 0.f;
    float4 acc = make_float4(0.f, 0.f, 0.f, 0.f);
#pragma unroll
    for (int e = 0; e < 8; e++) {
        int s = ssl[e];
        if (s >= 0) {
            float w = scw[e];
            rho += w;
            float4 ev = ((const float4*)(g_expo + ((size_t)e * CAP_ + s) * D_))[tid];
            acc.x = fmaf(w, ev.x, acc.x); acc.y = fmaf(w, ev.y, acc.y);
            acc.z = fmaf(w, ev.z, acc.z); acc.w = fmaf(w, ev.w, acc.w);
        }
    }
    float om = 1.f - rho;
    hv.x = hv.x * om + acc.x; hv.y = hv.y * om + acc.y;
    hv.z = hv.z * om + acc.z; hv.w = hv.w * om + acc.w;
    hr[tid] = hv;
}

// ---------------- final RMSNorm ----------------
__global__ void rmsnorm_kernel(const float* __restrict__ lnw, float* __restrict__ out) {
    int t = blockIdx.x, tid = threadIdx.x;
    float4 v = ((const float4*)(g_h + (size_t)t * D_))[tid];
    float ss = v.x * v.x + v.y * v.y + v.z * v.z + v.w * v.w;
#pragma unroll
    for (int o = 16; o > 0; o >>= 1) ss += __shfl_xor_sync(0xffffffffu, ss, o);
    __shared__ float red[8];
    if ((tid & 31) == 0) red[tid >> 5] = ss;
    __syncthreads();
    if (tid == 0) {
        float s = 0.f;
        for (int i = 0; i < 8; i++) s += red[i];
        red[0] = rsqrtf(s / (float)D_ + 1e-6f);
    }
    __syncthreads();
    float sc = red[0];
    float4 w = ((const float4*)lnw)[tid];
    float4 o4 = make_float4(v.x * sc * w.x, v.y * sc * w.y, v.z * sc * w.z, v.w * sc * w.w);
    ((float4*)out)[(size_t)t * 256 + tid] = o4;
}

// ---------------- launch ----------------
extern "C" void kernel_launch(void* const* d_in, const int* in_sizes, int n_in,
                              void* d_out, int out_size) {
    const int*   ids      = (const int*)d_in[0];
    const float* embed_w  = (const float*)d_in[1];
    const float* router_w = (const float*)d_in[2];
    const float* wq       = (const float*)d_in[3];
    const float* wk       = (const float*)d_in[4];
    const float* wv       = (const float*)d_in[5];
    const float* wo       = (const float*)d_in[6];
    const float* w1       = (const float*)d_in[7];
    const float* w2       = (const float*)d_in[8];
    const float* lnw      = (const float*)d_in[9];
    float* out = (float*)d_out;

    __half *p_wt, *p_x, *p_a, *p_f;
    float *p_expo;
    cudaGetSymbolAddress((void**)&p_wt, g_wt);
    cudaGetSymbolAddress((void**)&p_x,  g_x);
    cudaGetSymbolAddress((void**)&p_a,  g_a);
    cudaGetSymbolAddress((void**)&p_f,  g_f);
    cudaGetSymbolAddress((void**)&p_expo, g_expo);

    cudaFuncSetAttribute(attn_kernel, cudaFuncAttributeMaxDynamicSharedMemorySize, ATTN_SMEM);
    cudaFuncSetAttribute(gemm_mma, cudaFuncAttributeMaxDynamicSharedMemorySize, GSMEM);
    cudaFuncSetAttribute(gemm_qkv_mma, cudaFuncAttributeMaxDynamicSharedMemorySize, GSMEM);

    wconv_kernel<<<dim3(32, 32, 4), 256>>>(wq, p_wt + WQ_OFF, D_, D_);
    wconv_kernel<<<dim3(32, 32, 4), 256>>>(wk, p_wt + WK_OFF, D_, D_);
    wconv_kernel<<<dim3(32, 32, 4), 256>>>(wv, p_wt + WV_OFF, D_, D_);
    wconv_kernel<<<dim3(32, 32, 4), 256>>>(wo, p_wt + WO_OFF, D_, D_);
    wconv_kernel<<<dim3(128, 32, 4), 256>>>(w1, p_wt + W1_OFF, D_, MLP_);
    wconv_kernel<<<dim3(32, 128, 4), 256>>>(w2, p_wt + W2_OFF, MLP_, D_);

    embed_kernel<<<T_, 256>>>(ids, embed_w);
    for (int hop = 0; hop < 3; hop++) {
        router_kernel<<<T_ / 8, 256>>>(router_w + (size_t)hop * 9 * D_);
        capacity_kernel<<<E_, 1024>>>();
        gather_kernel<<<E_ * CAP_, 256>>>();
        gemm_qkv_mma<<<dim3(8, 8, 12), 256, GSMEM>>>();
        rope_kernel<<<4 * CAP_, 256>>>();
        attn_kernel<<<dim3(16, 16, 4), 256, ATTN_SMEM>>>();
        gemm_mma<<<dim3(8, 8, 4), 256, GSMEM>>>(
            p_a, p_wt + WO_OFF, p_expo, (__half*)0,
            D_, D_, (long long)CAP_ * D_, (long long)D_ * D_, 2LL * CAP_ * D_, 0);
        gemm_mma<<<dim3(32, 8, 4), 256, GSMEM>>>(
            p_x + (size_t)CAP_ * D_, p_wt + W1_OFF, (float*)0, p_f,
            MLP_, D_, 2LL * CAP_ * D_, (long long)D_ * MLP_, (long long)CAP_ * MLP_, 1);
        gemm_mma<<<dim3(8, 8, 4), 256, GSMEM>>>(
            p_f, p_wt + W2_OFF, p_expo + (size_t)CAP_ * D_, (__half*)0,
            D_, MLP_, (long long)CAP_ * MLP_, (long long)MLP_ * D_, 2LL * CAP_ * D_, 0);
        combine_kernel<<<T_, 256>>>();
    }
    rmsnorm_kernel<<<T_, 256>>>(lnw, out);
}

// round 14
// speedup vs baseline: 5.1364x; 1.1730x over previous
#include <cuda_runtime.h>
#include <cuda_fp16.h>
#include <cstdint>
#include <stdint.h>
#include <math.h>

#define T_    4096
#define D_    1024
#define E_    8
#define CAP_  1024
#define MLP_  4096

// ---------------- device scratch ----------------
__device__ float g_h[(size_t)T_ * D_];
__device__ float g_qkv[8ull * CAP_ * D_];          // fp32 q (0-3), k (4-7) pre-RoPE
__device__ float g_expo[(size_t)E_ * CAP_ * D_];
__device__ float g_probs[T_ * 8];
__device__ unsigned char g_maskb[T_];
__device__ int   g_slottok[E_ * CAP_];
__device__ int   g_slotof[E_ * T_];
__device__ float g_cw[T_ * 8];
__device__ int   g_nsel[E_];

__device__ __half g_x[(size_t)E_ * CAP_ * D_];
__device__ __half g_q[4ull * CAP_ * D_];
__device__ __half g_k[4ull * CAP_ * D_];
__device__ __half g_v[4ull * CAP_ * D_];
__device__ __half g_a[4ull * CAP_ * D_];
__device__ __half g_f[4ull * CAP_ * MLP_];

#define WQ_OFF 0ull
#define WK_OFF 4194304ull
#define WV_OFF 8388608ull
#define WO_OFF 12582912ull
#define W1_OFF 16777216ull
#define W2_OFF 33554432ull
#define WT_TOT 50331648ull
__device__ __half g_wt[WT_TOT];

// ---------------- helpers ----------------
__device__ __forceinline__ uint32_t smem_u32(const void* p) {
    uint32_t a;
    asm("{ .reg .u64 t; cvta.to.shared.u64 t, %1; cvt.u32.u64 %0, t; }" : "=r"(a) : "l"(p));
    return a;
}
__device__ __forceinline__ void cp_async16(uint32_t saddr, const void* gptr) {
    asm volatile("cp.async.cg.shared.global [%0], [%1], 16;" :: "r"(saddr), "l"(gptr));
}
#define CP_COMMIT() asm volatile("cp.async.commit_group;")
#define CP_WAIT(n)  asm volatile("cp.async.wait_group %0;" :: "n"(n))

__device__ __forceinline__ uint32_t h2_u32(__half2 h) {
    return *reinterpret_cast<uint32_t*>(&h);
}
__device__ __forceinline__ float gelu_f(float x) {
    float x3 = x * x * x;
    return 0.5f * x * (1.f + tanhf(0.7978845608028654f * (x + 0.044715f * x3)));
}
__device__ __forceinline__ void mma16816(float* d, const uint32_t* a, const uint32_t* b) {
    asm volatile(
        "mma.sync.aligned.m16n8k16.row.col.f32.f16.f16.f32 "
        "{%0,%1,%2,%3}, {%4,%5,%6,%7}, {%8,%9}, {%0,%1,%2,%3};"
        : "+f"(d[0]), "+f"(d[1]), "+f"(d[2]), "+f"(d[3])
        : "r"(a[0]), "r"(a[1]), "r"(a[2]), "r"(a[3]), "r"(b[0]), "r"(b[1]));
}
__device__ __forceinline__ uint32_t lds_frag(const __half* base, int r, int c) {
    int ch = c >> 3;
    int sw = ch ^ ((r >> 1) & 3);
    return *(const uint32_t*)(base + r * 32 + sw * 8 + (c & 7));
}
__device__ __forceinline__ uint32_t lds_sw64(const __half* base, int r, int c) {
    int ch = c >> 3;
    int sw = ch ^ (r & 7);
    return *(const uint32_t*)(base + r * 64 + sw * 8 + (c & 7));
}

// ---------------- embedding ----------------
__global__ void embed_kernel(const int* __restrict__ ids, const float* __restrict__ ew) {
    int t = blockIdx.x, tid = threadIdx.x;
    ((float4*)(g_h + (size_t)t * D_))[tid] =
        ((const float4*)(ew + (size_t)ids[t] * D_))[tid];
}

// ---------------- router ----------------
__global__ void router_kernel(const float* __restrict__ rw) {
    int gw = (blockIdx.x * blockDim.x + threadIdx.x) >> 5;
    int lane = threadIdx.x & 31;
    if (gw >= T_) return;
    const float* hr = g_h + (size_t)gw * D_;
    float acc[9];
#pragma unroll
    for (int e = 0; e < 9; e++) acc[e] = 0.f;
    for (int d = lane; d < D_; d += 32) {
        float hv = hr[d];
#pragma unroll
        for (int e = 0; e < 9; e++) acc[e] = fmaf(hv, rw[e * D_ + d], acc[e]);
    }
#pragma unroll
    for (int e = 0; e < 9; e++)
#pragma unroll
        for (int o = 16; o > 0; o >>= 1) acc[e] += __shfl_xor_sync(0xffffffffu, acc[e], o);
    if (lane == 0) {
        float mx = acc[0];
#pragma unroll
        for (int e = 1; e < 9; e++) mx = fmaxf(mx, acc[e]);
        float ex[9], s = 0.f;
#pragma unroll
        for (int e = 0; e < 9; e++) { ex[e] = expf(acc[e] - mx); s += ex[e]; }
        float inv = 1.f / s;
        int a1 = 0; float v1 = acc[0];
#pragma unroll
        for (int e = 1; e < 9; e++) if (acc[e] > v1) { v1 = acc[e]; a1 = e; }
        int a2 = -1; float v2 = -3.0e38f;
#pragma unroll
        for (int e = 0; e < 9; e++) if (e != a1 && acc[e] > v2) { v2 = acc[e]; a2 = e; }
        unsigned char m = 0;
        if (a1 < 8) m |= (unsigned char)(1 << a1);
        if (a2 < 8) m |= (unsigned char)(1 << a2);
        g_maskb[gw] = m;
#pragma unroll
        for (int e = 0; e < 8; e++) g_probs[gw * 8 + e] = ex[e] * inv;
    }
}

// ---------------- capacity select ----------------
__global__ void __launch_bounds__(1024) capacity_kernel() {
    int e = blockIdx.x, tid = threadIdx.x;
    __shared__ unsigned long long keys[T_];
    __shared__ int s_count;
    if (tid == 0) s_count = 0;
    __syncthreads();
    int local = 0;
    for (int t = tid; t < T_; t += 1024) {
        unsigned long long key = 0ull;
        if (g_maskb[t] & (1 << e)) {
            unsigned pb = __float_as_uint(g_probs[t * 8 + e]);
            key = ((unsigned long long)pb << 32) | (unsigned)(0xFFFFFFFFu - (unsigned)t);
            local++;
        }
        keys[t] = key;
    }
#pragma unroll
    for (int o = 16; o > 0; o >>= 1) local += __shfl_xor_sync(0xffffffffu, local, o);
    if ((tid & 31) == 0) atomicAdd(&s_count, local);
    __syncthreads();
    for (int k = 2; k <= T_; k <<= 1)
        for (int j = k >> 1; j > 0; j >>= 1) {
            for (int i = tid; i < T_; i += 1024) {
                int ixj = i ^ j;
                if (ixj > i) {
                    unsigned long long a = keys[i], b = keys[ixj];
                    bool desc = ((i & k) == 0);
                    if (desc ? (a < b) : (a > b)) { keys[i] = b; keys[ixj] = a; }
                }
            }
            __syncthreads();
        }
    int nsel = min(s_count, CAP_);
    if (tid == 0) g_nsel[e] = nsel;
    for (int t = tid; t < T_; t += 1024) { g_slotof[e * T_ + t] = -1; g_cw[t * 8 + e] = 0.f; }
    __syncthreads();
    int c = tid;
    if (c < nsel) {
        unsigned long long key = keys[c];
        int tok = (int)(0xFFFFFFFFu - (unsigned)(key & 0xFFFFFFFFull));
        g_slottok[e * CAP_ + c] = tok;
        g_slotof[e * T_ + tok] = c;
        g_cw[tok * 8 + e] = __uint_as_float((unsigned)(key >> 32));
    } else if (c < CAP_) {
        g_slottok[e * CAP_ + c] = 0;
    }
}

// ---------------- gather -> fp16 ----------------
__global__ void gather_kernel() {
    int row = blockIdx.x, e = row >> 10, c = row & 1023, tid = threadIdx.x;
    float4 v = make_float4(0.f, 0.f, 0.f, 0.f);
    if (c < g_nsel[e])
        v = ((const float4*)(g_h + (size_t)g_slottok[row] * D_))[tid];
    __half2* d = (__half2*)(g_x + (size_t)row * D_) + 2 * tid;
    d[0] = __halves2half2(__float2half_rn(v.x), __float2half_rn(v.y));
    d[1] = __halves2half2(__float2half_rn(v.z), __float2half_rn(v.w));
}

// ---------------- weight transpose + fp16 ----------------
__global__ void wconv_kernel(const float* __restrict__ W, __half* __restrict__ Th, int K, int N) {
    __shared__ float t[32][33];
    int z = blockIdx.z;
    size_t base = (size_t)z * K * N;
    int n0 = blockIdx.x * 32, k0 = blockIdx.y * 32;
    int tx = threadIdx.x & 31, ty = threadIdx.x >> 5;
#pragma unroll
    for (int r = 0; r < 32; r += 8)
        t[ty + r][tx] = W[base + (size_t)(k0 + ty + r) * N + n0 + tx];
    __syncthreads();
#pragma unroll
    for (int r = 0; r < 32; r += 8)
        Th[base + (size_t)(n0 + ty + r) * K + k0 + tx] = __float2half_rn(t[tx][ty + r]);
}

// ---------------- cp.async 3-stage pipelined fp16 mma.sync GEMM ----------------
#define GSMEM 49152

__device__ __forceinline__ void issue_tile(uint32_t sbase, const __half* __restrict__ g,
                                           int K, int k0, int tid) {
#pragma unroll
    for (int q = 0; q < 2; q++) {
        int i = tid * 2 + q;
        int r = i >> 2, ch = i & 3;
        int sw = ch ^ ((r >> 1) & 3);
        cp_async16(sbase + (uint32_t)(r * 32 + sw * 8) * 2,
                   g + (size_t)r * K + k0 + ch * 8);
    }
}

__device__ __forceinline__ void gemm_mma_body(
    const __half* __restrict__ A, const __half* __restrict__ B,
    float* Cf, __half* Ch, int N, int K, int act)
{
    extern __shared__ char gsm[];
    uint32_t sb = smem_u32(gsm);
    int tid = threadIdx.x, lane = tid & 31, warp = tid >> 5;
    int wm = (warp & 1) * 64, wn = (warp >> 1) * 32;
    int brow = blockIdx.y * 128, bcol = blockIdx.x * 128;
    const __half* pA = A + (size_t)brow * K;
    const __half* pB = B + (size_t)bcol * K;

    float acc[4][4][4];
#pragma unroll
    for (int i = 0; i < 4; i++)
#pragma unroll
        for (int j = 0; j < 4; j++)
#pragma unroll
            for (int d = 0; d < 4; d++) acc[i][j][d] = 0.f;

    int g = lane >> 2, t4 = lane & 3;
    int NC = K >> 5;

    issue_tile(sb,        pA, K, 0, tid);
    issue_tile(sb + 8192, pB, K, 0, tid);
    CP_COMMIT();
    if (NC > 1) {
        issue_tile(sb + 16384,        pA, K, 32, tid);
        issue_tile(sb + 16384 + 8192, pB, K, 32, tid);
    }
    CP_COMMIT();

    for (int c = 0; c < NC; c++) {
        if (c + 2 < NC) {
            uint32_t nb = sb + (uint32_t)((c + 2) % 3) * 16384;
            int k0 = (c + 2) << 5;
            issue_tile(nb,        pA, K, k0, tid);
            issue_tile(nb + 8192, pB, K, k0, tid);
        }
        CP_COMMIT();
        CP_WAIT(2);
        __syncthreads();
        const __half* sA = (const __half*)(gsm + (c % 3) * 16384);
        const __half* sB = sA + 4096;
#pragma unroll
        for (int kc = 0; kc < 2; kc++) {
            int cb = kc * 16 + t4 * 2;
            uint32_t bfr[4][2];
#pragma unroll
            for (int tn = 0; tn < 4; tn++) {
                int n = wn + tn * 8 + g;
                bfr[tn][0] = lds_frag(sB, n, cb);
                bfr[tn][1] = lds_frag(sB, n, cb + 8);
            }
#pragma unroll
            for (int tm = 0; tm < 4; tm++) {
                int r = wm + tm * 16 + g;
                uint32_t afr[4];
                afr[0] = lds_frag(sA, r, cb);     afr[1] = lds_frag(sA, r + 8, cb);
                afr[2] = lds_frag(sA, r, cb + 8); afr[3] = lds_frag(sA, r + 8, cb + 8);
#pragma unroll
                for (int tn = 0; tn < 4; tn++)
                    mma16816(acc[tm][tn], afr, bfr[tn]);
            }
        }
        __syncthreads();
    }

#pragma unroll
    for (int tm = 0; tm < 4; tm++) {
        int r = brow + wm + tm * 16 + g;
#pragma unroll
        for (int tn = 0; tn < 4; tn++) {
            int c = bcol + wn + tn * 8 + t4 * 2;
            float v0 = acc[tm][tn][0], v1 = acc[tm][tn][1];
            float v2 = acc[tm][tn][2], v3 = acc[tm][tn][3];
            if (Cf) {
                *(float2*)(Cf + (size_t)r * N + c) = make_float2(v0, v1);
                *(float2*)(Cf + (size_t)(r + 8) * N + c) = make_float2(v2, v3);
            } else {
                if (act) { v0 = gelu_f(v0); v1 = gelu_f(v1); v2 = gelu_f(v2); v3 = gelu_f(v3); }
                *(__half2*)(Ch + (size_t)r * N + c) =
                    __halves2half2(__float2half_rn(v0), __float2half_rn(v1));
                *(__half2*)(Ch + (size_t)(r + 8) * N + c) =
                    __halves2half2(__float2half_rn(v2), __float2half_rn(v3));
            }
        }
    }
}

__global__ void __launch_bounds__(256, 2) gemm_mma(
    const __half* A, const __half* B, float* Cf, __half* Ch,
    int N, int K, long long sA, long long sB, long long sC, int act)
{
    long long z = blockIdx.z;
    gemm_mma_body(A + z * sA, B + z * sB,
                  Cf ? Cf + z * sC : (float*)0,
                  Ch ? Ch + z * sC : (__half*)0, N, K, act);
}

__global__ void __launch_bounds__(256, 2) gemm_qkv_mma() {
    int z = blockIdx.z, which = z >> 2, g = z & 3;
    size_t ao = (size_t)(2 * g) * CAP_ * D_;
    size_t wo = (size_t)which * 4194304ull + (size_t)g * 1048576ull;
    if (which < 2) {
        gemm_mma_body(g_x + ao, g_wt + wo,
                      g_qkv + ((size_t)which * 4 + g) * CAP_ * D_, (__half*)0, D_, D_, 0);
    } else {
        gemm_mma_body(g_x + ao, g_wt + wo,
                      (float*)0, g_v + (size_t)g * CAP_ * D_, D_, D_, 0);
    }
}

// ---------------- RoPE: fp32 q,k -> rotated fp16 ----------------
__global__ void rope_kernel() {
    int row = blockIdx.x, g = row >> 10, c = row & 1023, tid = threadIdx.x;
    float pos = (float)g_slottok[(2 * g) * CAP_ + c];
    const float* q = g_qkv + (size_t)row * D_;
    const float* k = g_qkv + 4ull * CAP_ * D_ + (size_t)row * D_;
    size_t ob = (size_t)row * D_;
    for (int idx = tid; idx < 512; idx += 256) {
        int hh = idx >> 5, d0 = idx & 31;
        float invf = exp2f(-(float)(2 * d0) * (13.287712379549449f / 64.0f));
        float ang = pos * invf;
        float cs = cosf(ang), sn = sinf(ang);
        int b = hh * 64 + d0;
        float a0 = q[b], a1 = q[b + 32];
        g_q[ob + b]      = __float2half_rn(a0 * cs - a1 * sn);
        g_q[ob + b + 32] = __float2half_rn(a1 * cs + a0 * sn);
        float b0 = k[b], b1 = k[b + 32];
        g_k[ob + b]      = __float2half_rn(b0 * cs - b1 * sn);
        g_k[ob + b + 32] = __float2half_rn(b1 * cs + b0 * sn);
    }
}

// ---------------- register-softmax HMMA flash attention ----------------
// block: 128 q rows x 1 head x group. 8 warps, each warp 16q x all 64 keys.
#define A_Q   0
#define A_K0  16384
#define A_V0  24576
#define A_K1  32768
#define A_V1  40960
#define A_VT  49152
#define ATTN_SMEM 57600

__global__ void __launch_bounds__(256, 2) attn_kernel() {
    int qb = blockIdx.x, hh = blockIdx.y, g = blockIdx.z;
    extern __shared__ char sm[];
    uint32_t sb = smem_u32(sm);
    __half* Qs = (__half*)(sm + A_Q);
    __half* Vt = (__half*)(sm + A_VT);   // [64 d][66 k]

    int tid = threadIdx.x, lane = tid & 31, warp = tid >> 5;
    int gq = lane >> 2, t4 = lane & 3;
    int wq = warp * 16;

    size_t qoff = ((size_t)(g * CAP_ + qb * 128)) * D_ + hh * 64;
#pragma unroll
    for (int it = 0; it < 4; it++) {
        int idx = tid + it * 256;
        int r = idx >> 3, ch = idx & 7, sw = ch ^ (r & 7);
        cp_async16(sb + A_Q + (uint32_t)(r * 64 + sw * 8) * 2,
                   g_q + qoff + (size_t)r * D_ + ch * 8);
    }
    size_t koff0 = ((size_t)(g * CAP_)) * D_ + hh * 64;
#pragma unroll
    for (int it = 0; it < 2; it++) {
        int idx = tid + it * 256;
        int r = idx >> 3, ch = idx & 7, sw = ch ^ (r & 7);
        uint32_t off = (uint32_t)(r * 64 + sw * 8) * 2;
        cp_async16(sb + A_K0 + off, g_k + koff0 + (size_t)r * D_ + ch * 8);
        cp_async16(sb + A_V0 + off, g_v + koff0 + (size_t)r * D_ + ch * 8);
    }
    CP_COMMIT();

    float m0 = -3.0e38f, m1 = -3.0e38f, l0 = 0.f, l1 = 0.f;
    float o[8][4];
#pragma unroll
    for (int i = 0; i < 8; i++)
#pragma unroll
        for (int j = 0; j < 4; j++) o[i][j] = 0.f;

    for (int kt = 0; kt < 16; kt++) {
        __syncthreads();                 // prev compute done (protects alt KV buf + Vt)
        if (kt + 1 < 16) {
            uint32_t kb = sb + (((kt + 1) & 1) ? A_K1 : A_K0);
            uint32_t vb = sb + (((kt + 1) & 1) ? A_V1 : A_V0);
            size_t koff = ((size_t)(g * CAP_ + (kt + 1) * 64)) * D_ + hh * 64;
#pragma unroll
            for (int it = 0; it < 2; it++) {
                int idx = tid + it * 256;
                int r = idx >> 3, ch = idx & 7, sw = ch ^ (r & 7);
                uint32_t off = (uint32_t)(r * 64 + sw * 8) * 2;
                cp_async16(kb + off, g_k + koff + (size_t)r * D_ + ch * 8);
                cp_async16(vb + off, g_v + koff + (size_t)r * D_ + ch * 8);
            }
            CP_COMMIT();
            CP_WAIT(1);
        } else {
            CP_WAIT(0);
        }
        __syncthreads();                 // current KV visible to all
        const __half* Ks = (const __half*)(sm + ((kt & 1) ? A_K1 : A_K0));
        const __half* Vs = (const __half*)(sm + ((kt & 1) ? A_V1 : A_V0));

        // V transpose into Vt: thread handles k-pair (2r2, 2r2+1), 8 d's
        {
            int r2 = tid >> 3, ch = tid & 7;
            int ka = 2 * r2, kb2 = 2 * r2 + 1;
            uint4 va = *(const uint4*)(Vs + ka * 64 + (ch ^ (ka & 7)) * 8);
            uint4 vb2 = *(const uint4*)(Vs + kb2 * 64 + (ch ^ (kb2 & 7)) * 8);
            const __half* ha = (const __half*)&va;
            const __half* hb = (const __half*)&vb2;
#pragma unroll
            for (int j = 0; j < 8; j++)
                *(__half2*)(Vt + (ch * 8 + j) * 66 + ka) = __halves2half2(ha[j], hb[j]);
        }

        // S = Q K^T (registers)
        float s[8][4];
#pragma unroll
        for (int i = 0; i < 8; i++)
#pragma unroll
            for (int j = 0; j < 4; j++) s[i][j] = 0.f;
#pragma unroll
        for (int ks = 0; ks < 4; ks++) {
            int cb = ks * 16 + t4 * 2;
            uint32_t afr[4];
            afr[0] = lds_sw64(Qs, wq + gq, cb);     afr[1] = lds_sw64(Qs, wq + gq + 8, cb);
            afr[2] = lds_sw64(Qs, wq + gq, cb + 8); afr[3] = lds_sw64(Qs, wq + gq + 8, cb + 8);
#pragma unroll
            for (int tn = 0; tn < 8; tn++) {
                int n = tn * 8 + gq;
                uint32_t bfr[2];
                bfr[0] = lds_sw64(Ks, n, cb); bfr[1] = lds_sw64(Ks, n, cb + 8);
                mma16816(s[tn], afr, bfr);
            }
        }

        // register softmax (rows gq -> s[][0..1], gq+8 -> s[][2..3])
        float mx0 = -3.0e38f, mx1 = -3.0e38f;
#pragma unroll
        for (int tn = 0; tn < 8; tn++) {
            s[tn][0] *= 0.125f; s[tn][1] *= 0.125f;
            s[tn][2] *= 0.125f; s[tn][3] *= 0.125f;
            mx0 = fmaxf(mx0, fmaxf(s[tn][0], s[tn][1]));
            mx1 = fmaxf(mx1, fmaxf(s[tn][2], s[tn][3]));
        }
        mx0 = fmaxf(mx0, __shfl_xor_sync(0xffffffffu, mx0, 1));
        mx0 = fmaxf(mx0, __shfl_xor_sync(0xffffffffu, mx0, 2));
        mx1 = fmaxf(mx1, __shfl_xor_sync(0xffffffffu, mx1, 1));
        mx1 = fmaxf(mx1, __shfl_xor_sync(0xffffffffu, mx1, 2));
        float mn0 = fmaxf(m0, mx0), mn1 = fmaxf(m1, mx1);
        float cr0 = __expf(m0 - mn0), cr1 = __expf(m1 - mn1);
        float sum0 = 0.f, sum1 = 0.f;
#pragma unroll
        for (int tn = 0; tn < 8; tn++) {
            s[tn][0] = __expf(s[tn][0] - mn0); s[tn][1] = __expf(s[tn][1] - mn0);
            s[tn][2] = __expf(s[tn][2] - mn1); s[tn][3] = __expf(s[tn][3] - mn1);
            sum0 += s[tn][0] + s[tn][1];
            sum1 += s[tn][2] + s[tn][3];
        }
        sum0 += __shfl_xor_sync(0xffffffffu, sum0, 1);
        sum0 += __shfl_xor_sync(0xffffffffu, sum0, 2);
        sum1 += __shfl_xor_sync(0xffffffffu, sum1, 1);
        sum1 += __shfl_xor_sync(0xffffffffu, sum1, 2);
        l0 = l0 * cr0 + sum0; l1 = l1 * cr1 + sum1;
        m0 = mn0; m1 = mn1;
#pragma unroll
        for (int tn = 0; tn < 8; tn++) {
            o[tn][0] *= cr0; o[tn][1] *= cr0;
            o[tn][2] *= cr1; o[tn][3] *= cr1;
        }

        // pack P into A-frags (registers only)
        uint32_t pf[4][4];
#pragma unroll
        for (int ks = 0; ks < 4; ks++) {
            pf[ks][0] = h2_u32(__floats2half2_rn(s[2 * ks][0], s[2 * ks][1]));
            pf[ks][1] = h2_u32(__floats2half2_rn(s[2 * ks][2], s[2 * ks][3]));
            pf[ks][2] = h2_u32(__floats2half2_rn(s[2 * ks + 1][0], s[2 * ks + 1][1]));
            pf[ks][3] = h2_u32(__floats2half2_rn(s[2 * ks + 1][2], s[2 * ks + 1][3]));
        }
        __syncthreads();                 // Vt complete

        // O += P V
#pragma unroll
        for (int ks = 0; ks < 4; ks++) {
#pragma unroll
            for (int tn = 0; tn < 8; tn++) {
                int n = tn * 8 + gq;     // d index
                int cb = ks * 16 + t4 * 2;
                uint32_t bfr[2];
                bfr[0] = *(const uint32_t*)(Vt + n * 66 + cb);
                bfr[1] = *(const uint32_t*)(Vt + n * 66 + cb + 8);
                mma16816(o[tn], pf[ks], bfr);
            }
        }
    }

    float inv0 = 1.f / l0, inv1 = 1.f / l1;
    size_t obase = ((size_t)(g * CAP_ + qb * 128)) * D_ + hh * 64;
#pragma unroll
    for (int tn = 0; tn < 8; tn++) {
        int c = tn * 8 + t4 * 2;
        size_t off = obase + (size_t)(wq + gq) * D_ + c;
        *(__half2*)(g_a + off) =
            __halves2half2(__float2half_rn(o[tn][0] * inv0), __float2half_rn(o[tn][1] * inv0));
        off = obase + (size_t)(wq + gq + 8) * D_ + c;
        *(__half2*)(g_a + off) =
            __halves2half2(__float2half_rn(o[tn][2] * inv1), __float2half_rn(o[tn][3] * inv1));
    }
}

// ---------------- combine ----------------
__global__ void combine_kernel() {
    int t = blockIdx.x, tid = threadIdx.x;
    __shared__ float scw[8];
    __shared__ int ssl[8];
    if (tid < 8) { scw[tid] = g_cw[t * 8 + tid]; ssl[tid] = g_slotof[tid * T_ + t]; }
    __syncthreads();
    float4* hr = (float4*)(g_h + (size_t)t * D_);
    float4 hv = hr[tid];
    float rho = 0.f;
    float4 acc = make_float4(0.f, 0.f, 0.f, 0.f);
#pragma unroll
    for (int e = 0; e < 8; e++) {
        int s = ssl[e];
        if (s >= 0) {
            float w = scw[e];
            rho += w;
            float4 ev = ((const float4*)(g_expo + ((size_t)e * CAP_ + s) * D_))[tid];
            acc.x = fmaf(w, ev.x, acc.x); acc.y = fmaf(w, ev.y, acc.y);
            acc.z = fmaf(w, ev.z, acc.z); acc.w = fmaf(w, ev.w, acc.w);
        }
    }
    float om = 1.f - rho;
    hv.x = hv.x * om + acc.x; hv.y = hv.y * om + acc.y;
    hv.z = hv.z * om + acc.z; hv.w = hv.w * om + acc.w;
    hr[tid] = hv;
}

// ---------------- final RMSNorm ----------------
__global__ void rmsnorm_kernel(const float* __restrict__ lnw, float* __restrict__ out) {
    int t = blockIdx.x, tid = threadIdx.x;
    float4 v = ((const float4*)(g_h + (size_t)t * D_))[tid];
    float ss = v.x * v.x + v.y * v.y + v.z * v.z + v.w * v.w;
#pragma unroll
    for (int o = 16; o > 0; o >>= 1) ss += __shfl_xor_sync(0xffffffffu, ss, o);
    __shared__ float red[8];
    if ((tid & 31) == 0) red[tid >> 5] = ss;
    __syncthreads();
    if (tid == 0) {
        float s = 0.f;
        for (int i = 0; i < 8; i++) s += red[i];
        red[0] = rsqrtf(s / (float)D_ + 1e-6f);
    }
    __syncthreads();
    float sc = red[0];
    float4 w = ((const float4*)lnw)[tid];
    float4 o4 = make_float4(v.x * sc * w.x, v.y * sc * w.y, v.z * sc * w.z, v.w * sc * w.w);
    ((float4*)out)[(size_t)t * 256 + tid] = o4;
}

// ---------------- launch ----------------
extern "C" void kernel_launch(void* const* d_in, const int* in_sizes, int n_in,
                              void* d_out, int out_size) {
    const int*   ids      = (const int*)d_in[0];
    const float* embed_w  = (const float*)d_in[1];
    const float* router_w = (const float*)d_in[2];
    const float* wq       = (const float*)d_in[3];
    const float* wk       = (const float*)d_in[4];
    const float* wv       = (const float*)d_in[5];
    const float* wo       = (const float*)d_in[6];
    const float* w1       = (const float*)d_in[7];
    const float* w2       = (const float*)d_in[8];
    const float* lnw      = (const float*)d_in[9];
    float* out = (float*)d_out;

    __half *p_wt, *p_x, *p_a, *p_f;
    float *p_expo;
    cudaGetSymbolAddress((void**)&p_wt, g_wt);
    cudaGetSymbolAddress((void**)&p_x,  g_x);
    cudaGetSymbolAddress((void**)&p_a,  g_a);
    cudaGetSymbolAddress((void**)&p_f,  g_f);
    cudaGetSymbolAddress((void**)&p_expo, g_expo);

    cudaFuncSetAttribute(attn_kernel, cudaFuncAttributeMaxDynamicSharedMemorySize, ATTN_SMEM);
    cudaFuncSetAttribute(gemm_mma, cudaFuncAttributeMaxDynamicSharedMemorySize, GSMEM);
    cudaFuncSetAttribute(gemm_qkv_mma, cudaFuncAttributeMaxDynamicSharedMemorySize, GSMEM);

    wconv_kernel<<<dim3(32, 32, 4), 256>>>(wq, p_wt + WQ_OFF, D_, D_);
    wconv_kernel<<<dim3(32, 32, 4), 256>>>(wk, p_wt + WK_OFF, D_, D_);
    wconv_kernel<<<dim3(32, 32, 4), 256>>>(wv, p_wt + WV_OFF, D_, D_);
    wconv_kernel<<<dim3(32, 32, 4), 256>>>(wo, p_wt + WO_OFF, D_, D_);
    wconv_kernel<<<dim3(128, 32, 4), 256>>>(w1, p_wt + W1_OFF, D_, MLP_);
    wconv_kernel<<<dim3(32, 128, 4), 256>>>(w2, p_wt + W2_OFF, MLP_, D_);

    embed_kernel<<<T_, 256>>>(ids, embed_w);
    for (int hop = 0; hop < 3; hop++) {
        router_kernel<<<T_ / 8, 256>>>(router_w + (size_t)hop * 9 * D_);
        capacity_kernel<<<E_, 1024>>>();
        gather_kernel<<<E_ * CAP_, 256>>>();
        gemm_qkv_mma<<<dim3(8, 8, 12), 256, GSMEM>>>();
        rope_kernel<<<4 * CAP_, 256>>>();
        attn_kernel<<<dim3(8, 16, 4), 256, ATTN_SMEM>>>();
        gemm_mma<<<dim3(8, 8, 4), 256, GSMEM>>>(
            p_a, p_wt + WO_OFF, p_expo, (__half*)0,
            D_, D_, (long long)CAP_ * D_, (long long)D_ * D_, 2LL * CAP_ * D_, 0);
        gemm_mma<<<dim3(32, 8, 4), 256, GSMEM>>>(
            p_x + (size_t)CAP_ * D_, p_wt + W1_OFF, (float*)0, p_f,
            MLP_, D_, 2LL * CAP_ * D_, (long long)D_ * MLP_, (long long)CAP_ * MLP_, 1);
        gemm_mma<<<dim3(8, 8, 4), 256, GSMEM>>>(
            p_f, p_wt + W2_OFF, p_expo + (size_t)CAP_ * D_, (__half*)0,
            D_, MLP_, (long long)CAP_ * MLP_, (long long)MLP_ * D_, 2LL * CAP_ * D_, 0);
        combine_kernel<<<T_, 256>>>();
    }
    rmsnorm_kernel<<<T_, 256>>>(lnw, out);
}

// round 15
// speedup vs baseline: 5.3487x; 1.0413x over previous
#include <cuda_runtime.h>
#include <cuda_fp16.h>
#include <cstdint>
#include <stdint.h>
#include <math.h>

#define T_    4096
#define D_    1024
#define E_    8
#define CAP_  1024
#define MLP_  4096

// ---------------- device scratch ----------------
__device__ float g_h[(size_t)T_ * D_];
__device__ float g_expo[(size_t)E_ * CAP_ * D_];
__device__ float g_probs[T_ * 8];
__device__ unsigned char g_maskb[T_];
__device__ int   g_slottok[E_ * CAP_];
__device__ int   g_slotof[E_ * T_];
__device__ float g_cw[T_ * 8];
__device__ int   g_nsel[E_];
__device__ float2 g_csn[4 * CAP_ * 32];   // (cos,sin) per (group,row,j)

__device__ __half g_x[(size_t)E_ * CAP_ * D_];
__device__ __half g_q[4ull * CAP_ * D_];
__device__ __half g_k[4ull * CAP_ * D_];
__device__ __half g_v[4ull * CAP_ * D_];
__device__ __half g_a[4ull * CAP_ * D_];
__device__ __half g_f[4ull * CAP_ * MLP_];

#define WQ_OFF 0ull
#define WK_OFF 4194304ull
#define WV_OFF 8388608ull
#define WO_OFF 12582912ull
#define W1_OFF 16777216ull
#define W2_OFF 33554432ull
#define WT_TOT 50331648ull
__device__ __half g_wt[WT_TOT];

// ---------------- helpers ----------------
__device__ __forceinline__ uint32_t smem_u32(const void* p) {
    uint32_t a;
    asm("{ .reg .u64 t; cvta.to.shared.u64 t, %1; cvt.u32.u64 %0, t; }" : "=r"(a) : "l"(p));
    return a;
}
__device__ __forceinline__ void cp_async16(uint32_t saddr, const void* gptr) {
    asm volatile("cp.async.cg.shared.global [%0], [%1], 16;" :: "r"(saddr), "l"(gptr));
}
#define CP_COMMIT() asm volatile("cp.async.commit_group;")
#define CP_WAIT(n)  asm volatile("cp.async.wait_group %0;" :: "n"(n))

__device__ __forceinline__ uint32_t h2_u32(__half2 h) {
    return *reinterpret_cast<uint32_t*>(&h);
}
__device__ __forceinline__ float gelu_f(float x) {
    float x3 = x * x * x;
    return 0.5f * x * (1.f + tanhf(0.7978845608028654f * (x + 0.044715f * x3)));
}
__device__ __forceinline__ void mma16816(float* d, const uint32_t* a, const uint32_t* b) {
    asm volatile(
        "mma.sync.aligned.m16n8k16.row.col.f32.f16.f16.f32 "
        "{%0,%1,%2,%3}, {%4,%5,%6,%7}, {%8,%9}, {%0,%1,%2,%3};"
        : "+f"(d[0]), "+f"(d[1]), "+f"(d[2]), "+f"(d[3])
        : "r"(a[0]), "r"(a[1]), "r"(a[2]), "r"(a[3]), "r"(b[0]), "r"(b[1]));
}
__device__ __forceinline__ uint32_t lds_frag(const __half* base, int r, int c) {
    int ch = c >> 3;
    int sw = ch ^ ((r >> 1) & 3);
    return *(const uint32_t*)(base + r * 32 + sw * 8 + (c & 7));
}
__device__ __forceinline__ uint32_t lds_sw64(const __half* base, int r, int c) {
    int ch = c >> 3;
    int sw = ch ^ (r & 7);
    return *(const uint32_t*)(base + r * 64 + sw * 8 + (c & 7));
}

// ---------------- embedding ----------------
__global__ void embed_kernel(const int* __restrict__ ids, const float* __restrict__ ew) {
    int t = blockIdx.x, tid = threadIdx.x;
    ((float4*)(g_h + (size_t)t * D_))[tid] =
        ((const float4*)(ew + (size_t)ids[t] * D_))[tid];
}

// ---------------- router ----------------
__global__ void router_kernel(const float* __restrict__ rw) {
    int gw = (blockIdx.x * blockDim.x + threadIdx.x) >> 5;
    int lane = threadIdx.x & 31;
    if (gw >= T_) return;
    const float* hr = g_h + (size_t)gw * D_;
    float acc[9];
#pragma unroll
    for (int e = 0; e < 9; e++) acc[e] = 0.f;
    for (int d = lane; d < D_; d += 32) {
        float hv = hr[d];
#pragma unroll
        for (int e = 0; e < 9; e++) acc[e] = fmaf(hv, rw[e * D_ + d], acc[e]);
    }
#pragma unroll
    for (int e = 0; e < 9; e++)
#pragma unroll
        for (int o = 16; o > 0; o >>= 1) acc[e] += __shfl_xor_sync(0xffffffffu, acc[e], o);
    if (lane == 0) {
        float mx = acc[0];
#pragma unroll
        for (int e = 1; e < 9; e++) mx = fmaxf(mx, acc[e]);
        float ex[9], s = 0.f;
#pragma unroll
        for (int e = 0; e < 9; e++) { ex[e] = expf(acc[e] - mx); s += ex[e]; }
        float inv = 1.f / s;
        int a1 = 0; float v1 = acc[0];
#pragma unroll
        for (int e = 1; e < 9; e++) if (acc[e] > v1) { v1 = acc[e]; a1 = e; }
        int a2 = -1; float v2 = -3.0e38f;
#pragma unroll
        for (int e = 0; e < 9; e++) if (e != a1 && acc[e] > v2) { v2 = acc[e]; a2 = e; }
        unsigned char m = 0;
        if (a1 < 8) m |= (unsigned char)(1 << a1);
        if (a2 < 8) m |= (unsigned char)(1 << a2);
        g_maskb[gw] = m;
#pragma unroll
        for (int e = 0; e < 8; e++) g_probs[gw * 8 + e] = ex[e] * inv;
    }
}

// ---------------- capacity select ----------------
__global__ void __launch_bounds__(1024) capacity_kernel() {
    int e = blockIdx.x, tid = threadIdx.x;
    __shared__ unsigned long long keys[T_];
    __shared__ int s_count;
    if (tid == 0) s_count = 0;
    __syncthreads();
    int local = 0;
    for (int t = tid; t < T_; t += 1024) {
        unsigned long long key = 0ull;
        if (g_maskb[t] & (1 << e)) {
            unsigned pb = __float_as_uint(g_probs[t * 8 + e]);
            key = ((unsigned long long)pb << 32) | (unsigned)(0xFFFFFFFFu - (unsigned)t);
            local++;
        }
        keys[t] = key;
    }
#pragma unroll
    for (int o = 16; o > 0; o >>= 1) local += __shfl_xor_sync(0xffffffffu, local, o);
    if ((tid & 31) == 0) atomicAdd(&s_count, local);
    __syncthreads();
    for (int k = 2; k <= T_; k <<= 1)
        for (int j = k >> 1; j > 0; j >>= 1) {
            for (int i = tid; i < T_; i += 1024) {
                int ixj = i ^ j;
                if (ixj > i) {
                    unsigned long long a = keys[i], b = keys[ixj];
                    bool desc = ((i & k) == 0);
                    if (desc ? (a < b) : (a > b)) { keys[i] = b; keys[ixj] = a; }
                }
            }
            __syncthreads();
        }
    int nsel = min(s_count, CAP_);
    if (tid == 0) g_nsel[e] = nsel;
    for (int t = tid; t < T_; t += 1024) { g_slotof[e * T_ + t] = -1; g_cw[t * 8 + e] = 0.f; }
    __syncthreads();
    int c = tid;
    if (c < nsel) {
        unsigned long long key = keys[c];
        int tok = (int)(0xFFFFFFFFu - (unsigned)(key & 0xFFFFFFFFull));
        g_slottok[e * CAP_ + c] = tok;
        g_slotof[e * T_ + tok] = c;
        g_cw[tok * 8 + e] = __uint_as_float((unsigned)(key >> 32));
    } else if (c < CAP_) {
        g_slottok[e * CAP_ + c] = 0;
    }
}

// ---------------- gather -> fp16 ----------------
__global__ void gather_kernel() {
    int row = blockIdx.x, e = row >> 10, c = row & 1023, tid = threadIdx.x;
    float4 v = make_float4(0.f, 0.f, 0.f, 0.f);
    if (c < g_nsel[e])
        v = ((const float4*)(g_h + (size_t)g_slottok[row] * D_))[tid];
    __half2* d = (__half2*)(g_x + (size_t)row * D_) + 2 * tid;
    d[0] = __halves2half2(__float2half_rn(v.x), __float2half_rn(v.y));
    d[1] = __halves2half2(__float2half_rn(v.z), __float2half_rn(v.w));
}

// ---------------- RoPE angle table: (cos,sin) per (group,row,j) ----------------
__global__ void angles_kernel() {
    int idx = blockIdx.x * 256 + threadIdx.x;   // [0, 4*CAP*32)
    int R = idx >> 5, j = idx & 31;
    int g = R >> 10, r = R & 1023;
    float pos = (float)g_slottok[((2 * g) << 10) | r];
    float invf = exp2f(-(float)(2 * j) * (13.287712379549449f / 64.0f));
    float ang = pos * invf;
    g_csn[idx] = make_float2(cosf(ang), sinf(ang));
}

// ---------------- weight transpose + fp16 (optional RoPE pair-permute) ----------------
__global__ void wconv_kernel(const float* __restrict__ W, __half* __restrict__ Th,
                             int K, int N, int perm) {
    __shared__ float t[32][33];
    int z = blockIdx.z;
    size_t base = (size_t)z * K * N;
    int n0 = blockIdx.x * 32, k0 = blockIdx.y * 32;
    int tx = threadIdx.x & 31, ty = threadIdx.x >> 5;
#pragma unroll
    for (int r = 0; r < 32; r += 8)
        t[ty + r][tx] = W[base + (size_t)(k0 + ty + r) * N + n0 + tx];
    __syncthreads();
#pragma unroll
    for (int r = 0; r < 32; r += 8) {
        int n = n0 + ty + r;
        int nn = n;
        if (perm) {
            int j = n & 63;
            nn = (n & ~63) | (j < 32 ? (j << 1) : (((j - 32) << 1) | 1));
        }
        Th[base + (size_t)nn * K + k0 + tx] = __float2half_rn(t[tx][ty + r]);
    }
}

// ---------------- cp.async 3-stage pipelined fp16 mma.sync GEMM ----------------
#define GSMEM 49152

__device__ __forceinline__ void issue_tile(uint32_t sbase, const __half* __restrict__ g,
                                           int K, int k0, int tid) {
#pragma unroll
    for (int q = 0; q < 2; q++) {
        int i = tid * 2 + q;
        int r = i >> 2, ch = i & 3;
        int sw = ch ^ ((r >> 1) & 3);
        cp_async16(sbase + (uint32_t)(r * 32 + sw * 8) * 2,
                   g + (size_t)r * K + k0 + ch * 8);
    }
}

__device__ __forceinline__ void gemm_mma_body(
    const __half* __restrict__ A, const __half* __restrict__ B,
    float* Cf, __half* Ch, int N, int K, int act, const float2* __restrict__ csn)
{
    extern __shared__ char gsm[];
    uint32_t sb = smem_u32(gsm);
    int tid = threadIdx.x, lane = tid & 31, warp = tid >> 5;
    int wm = (warp & 1) * 64, wn = (warp >> 1) * 32;
    int brow = blockIdx.y * 128, bcol = blockIdx.x * 128;
    const __half* pA = A + (size_t)brow * K;
    const __half* pB = B + (size_t)bcol * K;

    float acc[4][4][4];
#pragma unroll
    for (int i = 0; i < 4; i++)
#pragma unroll
        for (int j = 0; j < 4; j++)
#pragma unroll
            for (int d = 0; d < 4; d++) acc[i][j][d] = 0.f;

    int g = lane >> 2, t4 = lane & 3;
    int NC = K >> 5;

    issue_tile(sb,        pA, K, 0, tid);
    issue_tile(sb + 8192, pB, K, 0, tid);
    CP_COMMIT();
    if (NC > 1) {
        issue_tile(sb + 16384,        pA, K, 32, tid);
        issue_tile(sb + 16384 + 8192, pB, K, 32, tid);
    }
    CP_COMMIT();

    for (int c = 0; c < NC; c++) {
        if (c + 2 < NC) {
            uint32_t nb = sb + (uint32_t)((c + 2) % 3) * 16384;
            int k0 = (c + 2) << 5;
            issue_tile(nb,        pA, K, k0, tid);
            issue_tile(nb + 8192, pB, K, k0, tid);
        }
        CP_COMMIT();
        CP_WAIT(2);
        __syncthreads();
        const __half* sA = (const __half*)(gsm + (c % 3) * 16384);
        const __half* sB = sA + 4096;
#pragma unroll
        for (int kc = 0; kc < 2; kc++) {
            int cb = kc * 16 + t4 * 2;
            uint32_t bfr[4][2];
#pragma unroll
            for (int tn = 0; tn < 4; tn++) {
                int n = wn + tn * 8 + g;
                bfr[tn][0] = lds_frag(sB, n, cb);
                bfr[tn][1] = lds_frag(sB, n, cb + 8);
            }
#pragma unroll
            for (int tm = 0; tm < 4; tm++) {
                int r = wm + tm * 16 + g;
                uint32_t afr[4];
                afr[0] = lds_frag(sA, r, cb);     afr[1] = lds_frag(sA, r + 8, cb);
                afr[2] = lds_frag(sA, r, cb + 8); afr[3] = lds_frag(sA, r + 8, cb + 8);
#pragma unroll
                for (int tn = 0; tn < 4; tn++)
                    mma16816(acc[tm][tn], afr, bfr[tn]);
            }
        }
        __syncthreads();
    }

#pragma unroll
    for (int tm = 0; tm < 4; tm++) {
        int r = brow + wm + tm * 16 + g;
#pragma unroll
        for (int tn = 0; tn < 4; tn++) {
            int c = bcol + wn + tn * 8 + t4 * 2;
            float v0 = acc[tm][tn][0], v1 = acc[tm][tn][1];
            float v2 = acc[tm][tn][2], v3 = acc[tm][tn][3];
            if (Cf) {
                *(float2*)(Cf + (size_t)r * N + c) = make_float2(v0, v1);
                *(float2*)(Cf + (size_t)(r + 8) * N + c) = make_float2(v2, v3);
            } else if (csn) {
                int jj = (c & 63) >> 1;
                float2 csA = csn[r * 32 + jj];
                float2 csB = csn[(r + 8) * 32 + jj];
                float q0 = v0 * csA.x - v1 * csA.y;
                float q1 = v1 * csA.x + v0 * csA.y;
                float q2 = v2 * csB.x - v3 * csB.y;
                float q3 = v3 * csB.x + v2 * csB.y;
                *(__half2*)(Ch + (size_t)r * N + c) =
                    __halves2half2(__float2half_rn(q0), __float2half_rn(q1));
                *(__half2*)(Ch + (size_t)(r + 8) * N + c) =
                    __halves2half2(__float2half_rn(q2), __float2half_rn(q3));
            } else {
                if (act) { v0 = gelu_f(v0); v1 = gelu_f(v1); v2 = gelu_f(v2); v3 = gelu_f(v3); }
                *(__half2*)(Ch + (size_t)r * N + c) =
                    __halves2half2(__float2half_rn(v0), __float2half_rn(v1));
                *(__half2*)(Ch + (size_t)(r + 8) * N + c) =
                    __halves2half2(__float2half_rn(v2), __float2half_rn(v3));
            }
        }
    }
}

// merged QKV (with fused RoPE on Q,K) + FFN1
__global__ void __launch_bounds__(256, 2) gemm_fused1() {
    int z = blockIdx.z;
    if (z < 12) {
        if (blockIdx.x >= 8) return;
        int which = z >> 2, g = z & 3;
        size_t ao = (size_t)(2 * g) * CAP_ * D_;
        size_t wo = (size_t)which * 4194304ull + (size_t)g * 1048576ull;
        if (which == 0)
            gemm_mma_body(g_x + ao, g_wt + wo, (float*)0, g_q + (size_t)g * CAP_ * D_,
                          D_, D_, 0, g_csn + (size_t)g * CAP_ * 32);
        else if (which == 1)
            gemm_mma_body(g_x + ao, g_wt + wo, (float*)0, g_k + (size_t)g * CAP_ * D_,
                          D_, D_, 0, g_csn + (size_t)g * CAP_ * 32);
        else
            gemm_mma_body(g_x + ao, g_wt + wo, (float*)0, g_v + (size_t)g * CAP_ * D_,
                          D_, D_, 0, (const float2*)0);
    } else {
        int g = z - 12;
        gemm_mma_body(g_x + (size_t)(2 * g + 1) * CAP_ * D_,
                      g_wt + W1_OFF + (size_t)g * D_ * MLP_,
                      (float*)0, g_f + (size_t)g * CAP_ * MLP_,
                      MLP_, D_, 1, (const float2*)0);
    }
}

// merged Wo + FFN2
__global__ void __launch_bounds__(256, 2) gemm_fused2() {
    int z = blockIdx.z;
    if (z < 4) {
        int g = z;
        gemm_mma_body(g_a + (size_t)g * CAP_ * D_, g_wt + WO_OFF + (size_t)g * D_ * D_,
                      g_expo + (size_t)(2 * g) * CAP_ * D_, (__half*)0,
                      D_, D_, 0, (const float2*)0);
    } else {
        int g = z - 4;
        gemm_mma_body(g_f + (size_t)g * CAP_ * MLP_, g_wt + W2_OFF + (size_t)g * MLP_ * D_,
                      g_expo + (size_t)(2 * g + 1) * CAP_ * D_, (__half*)0,
                      D_, MLP_, 0, (const float2*)0);
    }
}

// ---------------- register-softmax HMMA flash attention ----------------
#define A_Q   0
#define A_K0  16384
#define A_V0  24576
#define A_K1  32768
#define A_V1  40960
#define A_VT  49152
#define ATTN_SMEM 57600

__global__ void __launch_bounds__(256, 2) attn_kernel() {
    int qb = blockIdx.x, hh = blockIdx.y, g = blockIdx.z;
    extern __shared__ char sm[];
    uint32_t sb = smem_u32(sm);
    __half* Qs = (__half*)(sm + A_Q);
    __half* Vt = (__half*)(sm + A_VT);   // [64 d][66 k]

    int tid = threadIdx.x, lane = tid & 31, warp = tid >> 5;
    int gq = lane >> 2, t4 = lane & 3;
    int wq = warp * 16;

    size_t qoff = ((size_t)(g * CAP_ + qb * 128)) * D_ + hh * 64;
#pragma unroll
    for (int it = 0; it < 4; it++) {
        int idx = tid + it * 256;
        int r = idx >> 3, ch = idx & 7, sw = ch ^ (r & 7);
        cp_async16(sb + A_Q + (uint32_t)(r * 64 + sw * 8) * 2,
                   g_q + qoff + (size_t)r * D_ + ch * 8);
    }
    size_t koff0 = ((size_t)(g * CAP_)) * D_ + hh * 64;
#pragma unroll
    for (int it = 0; it < 2; it++) {
        int idx = tid + it * 256;
        int r = idx >> 3, ch = idx & 7, sw = ch ^ (r & 7);
        uint32_t off = (uint32_t)(r * 64 + sw * 8) * 2;
        cp_async16(sb + A_K0 + off, g_k + koff0 + (size_t)r * D_ + ch * 8);
        cp_async16(sb + A_V0 + off, g_v + koff0 + (size_t)r * D_ + ch * 8);
    }
    CP_COMMIT();

    float m0 = -3.0e38f, m1 = -3.0e38f, l0 = 0.f, l1 = 0.f;
    float o[8][4];
#pragma unroll
    for (int i = 0; i < 8; i++)
#pragma unroll
        for (int j = 0; j < 4; j++) o[i][j] = 0.f;

    for (int kt = 0; kt < 16; kt++) {
        __syncthreads();
        if (kt + 1 < 16) {
            uint32_t kb = sb + (((kt + 1) & 1) ? A_K1 : A_K0);
            uint32_t vb = sb + (((kt + 1) & 1) ? A_V1 : A_V0);
            size_t koff = ((size_t)(g * CAP_ + (kt + 1) * 64)) * D_ + hh * 64;
#pragma unroll
            for (int it = 0; it < 2; it++) {
                int idx = tid + it * 256;
                int r = idx >> 3, ch = idx & 7, sw = ch ^ (r & 7);
                uint32_t off = (uint32_t)(r * 64 + sw * 8) * 2;
                cp_async16(kb + off, g_k + koff + (size_t)r * D_ + ch * 8);
                cp_async16(vb + off, g_v + koff + (size_t)r * D_ + ch * 8);
            }
            CP_COMMIT();
            CP_WAIT(1);
        } else {
            CP_WAIT(0);
        }
        __syncthreads();
        const __half* Ks = (const __half*)(sm + ((kt & 1) ? A_K1 : A_K0));
        const __half* Vs = (const __half*)(sm + ((kt & 1) ? A_V1 : A_V0));

        {
            int r2 = tid >> 3, ch = tid & 7;
            int ka = 2 * r2, kb2 = 2 * r2 + 1;
            uint4 va = *(const uint4*)(Vs + ka * 64 + (ch ^ (ka & 7)) * 8);
            uint4 vb2 = *(const uint4*)(Vs + kb2 * 64 + (ch ^ (kb2 & 7)) * 8);
            const __half* ha = (const __half*)&va;
            const __half* hb = (const __half*)&vb2;
#pragma unroll
            for (int j = 0; j < 8; j++)
                *(__half2*)(Vt + (ch * 8 + j) * 66 + ka) = __halves2half2(ha[j], hb[j]);
        }

        float s[8][4];
#pragma unroll
        for (int i = 0; i < 8; i++)
#pragma unroll
            for (int j = 0; j < 4; j++) s[i][j] = 0.f;
#pragma unroll
        for (int ks = 0; ks < 4; ks++) {
            int cb = ks * 16 + t4 * 2;
            uint32_t afr[4];
            afr[0] = lds_sw64(Qs, wq + gq, cb);     afr[1] = lds_sw64(Qs, wq + gq + 8, cb);
            afr[2] = lds_sw64(Qs, wq + gq, cb + 8); afr[3] = lds_sw64(Qs, wq + gq + 8, cb + 8);
#pragma unroll
            for (int tn = 0; tn < 8; tn++) {
                int n = tn * 8 + gq;
                uint32_t bfr[2];
                bfr[0] = lds_sw64(Ks, n, cb); bfr[1] = lds_sw64(Ks, n, cb + 8);
                mma16816(s[tn], afr, bfr);
            }
        }

        float mx0 = -3.0e38f, mx1 = -3.0e38f;
#pragma unroll
        for (int tn = 0; tn < 8; tn++) {
            s[tn][0] *= 0.125f; s[tn][1] *= 0.125f;
            s[tn][2] *= 0.125f; s[tn][3] *= 0.125f;
            mx0 = fmaxf(mx0, fmaxf(s[tn][0], s[tn][1]));
            mx1 = fmaxf(mx1, fmaxf(s[tn][2], s[tn][3]));
        }
        mx0 = fmaxf(mx0, __shfl_xor_sync(0xffffffffu, mx0, 1));
        mx0 = fmaxf(mx0, __shfl_xor_sync(0xffffffffu, mx0, 2));
        mx1 = fmaxf(mx1, __shfl_xor_sync(0xffffffffu, mx1, 1));
        mx1 = fmaxf(mx1, __shfl_xor_sync(0xffffffffu, mx1, 2));
        float mn0 = fmaxf(m0, mx0), mn1 = fmaxf(m1, mx1);
        float cr0 = __expf(m0 - mn0), cr1 = __expf(m1 - mn1);
        float sum0 = 0.f, sum1 = 0.f;
#pragma unroll
        for (int tn = 0; tn < 8; tn++) {
            s[tn][0] = __expf(s[tn][0] - mn0); s[tn][1] = __expf(s[tn][1] - mn0);
            s[tn][2] = __expf(s[tn][2] - mn1); s[tn][3] = __expf(s[tn][3] - mn1);
            sum0 += s[tn][0] + s[tn][1];
            sum1 += s[tn][2] + s[tn][3];
        }
        sum0 += __shfl_xor_sync(0xffffffffu, sum0, 1);
        sum0 += __shfl_xor_sync(0xffffffffu, sum0, 2);
        sum1 += __shfl_xor_sync(0xffffffffu, sum1, 1);
        sum1 += __shfl_xor_sync(0xffffffffu, sum1, 2);
        l0 = l0 * cr0 + sum0; l1 = l1 * cr1 + sum1;
        m0 = mn0; m1 = mn1;
#pragma unroll
        for (int tn = 0; tn < 8; tn++) {
            o[tn][0] *= cr0; o[tn][1] *= cr0;
            o[tn][2] *= cr1; o[tn][3] *= cr1;
        }

        uint32_t pf[4][4];
#pragma unroll
        for (int ks = 0; ks < 4; ks++) {
            pf[ks][0] = h2_u32(__floats2half2_rn(s[2 * ks][0], s[2 * ks][1]));
            pf[ks][1] = h2_u32(__floats2half2_rn(s[2 * ks][2], s[2 * ks][3]));
            pf[ks][2] = h2_u32(__floats2half2_rn(s[2 * ks + 1][0], s[2 * ks + 1][1]));
            pf[ks][3] = h2_u32(__floats2half2_rn(s[2 * ks + 1][2], s[2 * ks + 1][3]));
        }
        __syncthreads();

#pragma unroll
        for (int ks = 0; ks < 4; ks++) {
#pragma unroll
            for (int tn = 0; tn < 8; tn++) {
                int n = tn * 8 + gq;
                int cb = ks * 16 + t4 * 2;
                uint32_t bfr[2];
                bfr[0] = *(const uint32_t*)(Vt + n * 66 + cb);
                bfr[1] = *(const uint32_t*)(Vt + n * 66 + cb + 8);
                mma16816(o[tn], pf[ks], bfr);
            }
        }
    }

    float inv0 = 1.f / l0, inv1 = 1.f / l1;
    size_t obase = ((size_t)(g * CAP_ + qb * 128)) * D_ + hh * 64;
#pragma unroll
    for (int tn = 0; tn < 8; tn++) {
        int c = tn * 8 + t4 * 2;
        size_t off = obase + (size_t)(wq + gq) * D_ + c;
        *(__half2*)(g_a + off) =
            __halves2half2(__float2half_rn(o[tn][0] * inv0), __float2half_rn(o[tn][1] * inv0));
        off = obase + (size_t)(wq + gq + 8) * D_ + c;
        *(__half2*)(g_a + off) =
            __halves2half2(__float2half_rn(o[tn][2] * inv1), __float2half_rn(o[tn][3] * inv1));
    }
}

// ---------------- combine ----------------
__global__ void combine_kernel() {
    int t = blockIdx.x, tid = threadIdx.x;
    __shared__ float scw[8];
    __shared__ int ssl[8];
    if (tid < 8) { scw[tid] = g_cw[t * 8 + tid]; ssl[tid] = g_slotof[tid * T_ + t]; }
    __syncthreads();
    float4* hr = (float4*)(g_h + (size_t)t * D_);
    float4 hv = hr[tid];
    float rho = 0.f;
    float4 acc = make_float4(0.f, 0.f, 0.f, 0.f);
#pragma unroll
    for (int e = 0; e < 8; e++) {
        int s = ssl[e];
        if (s >= 0) {
            float w = scw[e];
            rho += w;
            float4 ev = ((const float4*)(g_expo + ((size_t)e * CAP_ + s) * D_))[tid];
            acc.x = fmaf(w, ev.x, acc.x); acc.y = fmaf(w, ev.y, acc.y);
            acc.z = fmaf(w, ev.z, acc.z); acc.w = fmaf(w, ev.w, acc.w);
        }
    }
    float om = 1.f - rho;
    hv.x = hv.x * om + acc.x; hv.y = hv.y * om + acc.y;
    hv.z = hv.z * om + acc.z; hv.w = hv.w * om + acc.w;
    hr[tid] = hv;
}

// ---------------- final RMSNorm ----------------
__global__ void rmsnorm_kernel(const float* __restrict__ lnw, float* __restrict__ out) {
    int t = blockIdx.x, tid = threadIdx.x;
    float4 v = ((const float4*)(g_h + (size_t)t * D_))[tid];
    float ss = v.x * v.x + v.y * v.y + v.z * v.z + v.w * v.w;
#pragma unroll
    for (int o = 16; o > 0; o >>= 1) ss += __shfl_xor_sync(0xffffffffu, ss, o);
    __shared__ float red[8];
    if ((tid & 31) == 0) red[tid >> 5] = ss;
    __syncthreads();
    if (tid == 0) {
        float s = 0.f;
        for (int i = 0; i < 8; i++) s += red[i];
        red[0] = rsqrtf(s / (float)D_ + 1e-6f);
    }
    __syncthreads();
    float sc = red[0];
    float4 w = ((const float4*)lnw)[tid];
    float4 o4 = make_float4(v.x * sc * w.x, v.y * sc * w.y, v.z * sc * w.z, v.w * sc * w.w);
    ((float4*)out)[(size_t)t * 256 + tid] = o4;
}

// ---------------- launch ----------------
extern "C" void kernel_launch(void* const* d_in, const int* in_sizes, int n_in,
                              void* d_out, int out_size) {
    const int*   ids      = (const int*)d_in[0];
    const float* embed_w  = (const float*)d_in[1];
    const float* router_w = (const float*)d_in[2];
    const float* wq       = (const float*)d_in[3];
    const float* wk       = (const float*)d_in[4];
    const float* wv       = (const float*)d_in[5];
    const float* wo       = (const float*)d_in[6];
    const float* w1       = (const float*)d_in[7];
    const float* w2       = (const float*)d_in[8];
    const float* lnw      = (const float*)d_in[9];
    float* out = (float*)d_out;

    __half* p_wt;
    cudaGetSymbolAddress((void**)&p_wt, g_wt);

    cudaFuncSetAttribute(attn_kernel, cudaFuncAttributeMaxDynamicSharedMemorySize, ATTN_SMEM);
    cudaFuncSetAttribute(gemm_fused1, cudaFuncAttributeMaxDynamicSharedMemorySize, GSMEM);
    cudaFuncSetAttribute(gemm_fused2, cudaFuncAttributeMaxDynamicSharedMemorySize, GSMEM);

    wconv_kernel<<<dim3(32, 32, 4), 256>>>(wq, p_wt + WQ_OFF, D_, D_, 1);
    wconv_kernel<<<dim3(32, 32, 4), 256>>>(wk, p_wt + WK_OFF, D_, D_, 1);
    wconv_kernel<<<dim3(32, 32, 4), 256>>>(wv, p_wt + WV_OFF, D_, D_, 0);
    wconv_kernel<<<dim3(32, 32, 4), 256>>>(wo, p_wt + WO_OFF, D_, D_, 0);
    wconv_kernel<<<dim3(128, 32, 4), 256>>>(w1, p_wt + W1_OFF, D_, MLP_, 0);
    wconv_kernel<<<dim3(32, 128, 4), 256>>>(w2, p_wt + W2_OFF, MLP_, D_, 0);

    embed_kernel<<<T_, 256>>>(ids, embed_w);
    for (int hop = 0; hop < 3; hop++) {
        router_kernel<<<T_ / 8, 256>>>(router_w + (size_t)hop * 9 * D_);
        capacity_kernel<<<E_, 1024>>>();
        gather_kernel<<<E_ * CAP_, 256>>>();
        angles_kernel<<<512, 256>>>();
        gemm_fused1<<<dim3(32, 8, 16), 256, GSMEM>>>();
        attn_kernel<<<dim3(8, 16, 4), 256, ATTN_SMEM>>>();
        gemm_fused2<<<dim3(8, 8, 8), 256, GSMEM>>>();
        combine_kernel<<<T_, 256>>>();
    }
    rmsnorm_kernel<<<T_, 256>>>(lnw, out);
}

// round 16
// speedup vs baseline: 5.4630x; 1.0214x over previous
#include <cuda_runtime.h>
#include <cuda_fp16.h>
#include <cstdint>
#include <stdint.h>
#include <math.h>

#define T_    4096
#define D_    1024
#define E_    8
#define CAP_  1024
#define MLP_  4096

// ---------------- device scratch ----------------
__device__ float g_h[(size_t)T_ * D_];
__device__ float g_expo[(size_t)E_ * CAP_ * D_];
__device__ float g_probs[T_ * 8];
__device__ unsigned char g_maskb[T_];
__device__ int   g_slottok[E_ * CAP_];
__device__ int   g_slotof[E_ * T_];
__device__ float g_cw[T_ * 8];
__device__ int   g_nsel[E_];
__device__ float2 g_csn[4 * CAP_ * 32];

__device__ __half g_x[(size_t)E_ * CAP_ * D_];
__device__ __half g_q[4ull * CAP_ * D_];
__device__ __half g_k[4ull * CAP_ * D_];
__device__ __half g_v[4ull * CAP_ * D_];
__device__ __half g_a[4ull * CAP_ * D_];
__device__ __half g_f[4ull * CAP_ * MLP_];

#define WQ_OFF 0ull
#define WK_OFF 4194304ull
#define WV_OFF 8388608ull
#define WO_OFF 12582912ull
#define W1_OFF 16777216ull
#define W2_OFF 33554432ull
#define WT_TOT 50331648ull
__device__ __half g_wt[WT_TOT];

// ---------------- helpers ----------------
__device__ __forceinline__ uint32_t smem_u32(const void* p) {
    uint32_t a;
    asm("{ .reg .u64 t; cvta.to.shared.u64 t, %1; cvt.u32.u64 %0, t; }" : "=r"(a) : "l"(p));
    return a;
}
__device__ __forceinline__ void cp_async16(uint32_t saddr, const void* gptr) {
    asm volatile("cp.async.cg.shared.global [%0], [%1], 16;" :: "r"(saddr), "l"(gptr));
}
#define CP_COMMIT() asm volatile("cp.async.commit_group;")
#define CP_WAIT(n)  asm volatile("cp.async.wait_group %0;" :: "n"(n))

__device__ __forceinline__ uint32_t h2_u32(__half2 h) {
    return *reinterpret_cast<uint32_t*>(&h);
}
__device__ __forceinline__ float gelu_f(float x) {
    float x3 = x * x * x;
    return 0.5f * x * (1.f + tanhf(0.7978845608028654f * (x + 0.044715f * x3)));
}
__device__ __forceinline__ void mma16816(float* d, const uint32_t* a, const uint32_t* b) {
    asm volatile(
        "mma.sync.aligned.m16n8k16.row.col.f32.f16.f16.f32 "
        "{%0,%1,%2,%3}, {%4,%5,%6,%7}, {%8,%9}, {%0,%1,%2,%3};"
        : "+f"(d[0]), "+f"(d[1]), "+f"(d[2]), "+f"(d[3])
        : "r"(a[0]), "r"(a[1]), "r"(a[2]), "r"(a[3]), "r"(b[0]), "r"(b[1]));
}
__device__ __forceinline__ uint32_t lds_frag(const __half* base, int r, int c) {
    int ch = c >> 3;
    int sw = ch ^ ((r >> 1) & 3);
    return *(const uint32_t*)(base + r * 32 + sw * 8 + (c & 7));
}
__device__ __forceinline__ uint32_t lds_sw64(const __half* base, int r, int c) {
    int ch = c >> 3;
    int sw = ch ^ (r & 7);
    return *(const uint32_t*)(base + r * 64 + sw * 8 + (c & 7));
}

// ---------------- embedding ----------------
__global__ void embed_kernel(const int* __restrict__ ids, const float* __restrict__ ew) {
    int t = blockIdx.x, tid = threadIdx.x;
    ((float4*)(g_h + (size_t)t * D_))[tid] =
        ((const float4*)(ew + (size_t)ids[t] * D_))[tid];
}

// ---------------- router (hop 0 only) ----------------
__global__ void router_kernel(const float* __restrict__ rw) {
    int gw = (blockIdx.x * blockDim.x + threadIdx.x) >> 5;
    int lane = threadIdx.x & 31;
    if (gw >= T_) return;
    const float* hr = g_h + (size_t)gw * D_;
    float acc[9];
#pragma unroll
    for (int e = 0; e < 9; e++) acc[e] = 0.f;
    for (int d = lane; d < D_; d += 32) {
        float hv = hr[d];
#pragma unroll
        for (int e = 0; e < 9; e++) acc[e] = fmaf(hv, rw[e * D_ + d], acc[e]);
    }
#pragma unroll
    for (int e = 0; e < 9; e++)
#pragma unroll
        for (int o = 16; o > 0; o >>= 1) acc[e] += __shfl_xor_sync(0xffffffffu, acc[e], o);
    if (lane == 0) {
        float mx = acc[0];
#pragma unroll
        for (int e = 1; e < 9; e++) mx = fmaxf(mx, acc[e]);
        float ex[9], s = 0.f;
#pragma unroll
        for (int e = 0; e < 9; e++) { ex[e] = expf(acc[e] - mx); s += ex[e]; }
        float inv = 1.f / s;
        int a1 = 0; float v1 = acc[0];
#pragma unroll
        for (int e = 1; e < 9; e++) if (acc[e] > v1) { v1 = acc[e]; a1 = e; }
        int a2 = -1; float v2 = -3.0e38f;
#pragma unroll
        for (int e = 0; e < 9; e++) if (e != a1 && acc[e] > v2) { v2 = acc[e]; a2 = e; }
        unsigned char m = 0;
        if (a1 < 8) m |= (unsigned char)(1 << a1);
        if (a2 < 8) m |= (unsigned char)(1 << a2);
        g_maskb[gw] = m;
#pragma unroll
        for (int e = 0; e < 8; e++) g_probs[gw * 8 + e] = ex[e] * inv;
    }
}

// ---------------- capacity select ----------------
__global__ void __launch_bounds__(1024) capacity_kernel() {
    int e = blockIdx.x, tid = threadIdx.x;
    __shared__ unsigned long long keys[T_];
    __shared__ int s_count;
    if (tid == 0) s_count = 0;
    __syncthreads();
    int local = 0;
    for (int t = tid; t < T_; t += 1024) {
        unsigned long long key = 0ull;
        if (g_maskb[t] & (1 << e)) {
            unsigned pb = __float_as_uint(g_probs[t * 8 + e]);
            key = ((unsigned long long)pb << 32) | (unsigned)(0xFFFFFFFFu - (unsigned)t);
            local++;
        }
        keys[t] = key;
    }
#pragma unroll
    for (int o = 16; o > 0; o >>= 1) local += __shfl_xor_sync(0xffffffffu, local, o);
    if ((tid & 31) == 0) atomicAdd(&s_count, local);
    __syncthreads();
    for (int k = 2; k <= T_; k <<= 1)
        for (int j = k >> 1; j > 0; j >>= 1) {
            for (int i = tid; i < T_; i += 1024) {
                int ixj = i ^ j;
                if (ixj > i) {
                    unsigned long long a = keys[i], b = keys[ixj];
                    bool desc = ((i & k) == 0);
                    if (desc ? (a < b) : (a > b)) { keys[i] = b; keys[ixj] = a; }
                }
            }
            __syncthreads();
        }
    int nsel = min(s_count, CAP_);
    if (tid == 0) g_nsel[e] = nsel;
    for (int t = tid; t < T_; t += 1024) { g_slotof[e * T_ + t] = -1; g_cw[t * 8 + e] = 0.f; }
    __syncthreads();
    int c = tid;
    if (c < nsel) {
        unsigned long long key = keys[c];
        int tok = (int)(0xFFFFFFFFu - (unsigned)(key & 0xFFFFFFFFull));
        g_slottok[e * CAP_ + c] = tok;
        g_slotof[e * T_ + tok] = c;
        g_cw[tok * 8 + e] = __uint_as_float((unsigned)(key >> 32));
    } else if (c < CAP_) {
        g_slottok[e * CAP_ + c] = 0;
    }
}

// ---------------- gather -> fp16, plus RoPE angle table for attn experts ----------------
__global__ void gather_kernel() {
    int row = blockIdx.x, e = row >> 10, c = row & 1023, tid = threadIdx.x;
    float4 v = make_float4(0.f, 0.f, 0.f, 0.f);
    if (c < g_nsel[e])
        v = ((const float4*)(g_h + (size_t)g_slottok[row] * D_))[tid];
    __half2* d = (__half2*)(g_x + (size_t)row * D_) + 2 * tid;
    d[0] = __halves2half2(__float2half_rn(v.x), __float2half_rn(v.y));
    d[1] = __halves2half2(__float2half_rn(v.z), __float2half_rn(v.w));
    if ((e & 1) == 0 && tid < 32) {
        int g = e >> 1;
        float pos = (float)g_slottok[row];
        float invf = exp2f(-(float)(2 * tid) * (13.287712379549449f / 64.0f));
        float ang = pos * invf;
        g_csn[((size_t)g * CAP_ + c) * 32 + tid] = make_float2(cosf(ang), sinf(ang));
    }
}

// ---------------- weight transpose + fp16: 64x64 vectorized ----------------
__global__ void wconv_kernel(const float* __restrict__ W, __half* __restrict__ Th,
                             int K, int N, int perm) {
    __shared__ float s[64][65];   // s[n][k]
    int z = blockIdx.z;
    size_t base = (size_t)z * K * N;
    int n0 = blockIdx.x * 64, k0 = blockIdx.y * 64;
    int tid = threadIdx.x;
#pragma unroll
    for (int i = 0; i < 4; i++) {
        int linear = tid + i * 256;
        int k = linear >> 4, c4 = (linear & 15) << 2;
        float4 v = *(const float4*)(W + base + (size_t)(k0 + k) * N + n0 + c4);
        s[c4 + 0][k] = v.x; s[c4 + 1][k] = v.y;
        s[c4 + 2][k] = v.z; s[c4 + 3][k] = v.w;
    }
    __syncthreads();
#pragma unroll
    for (int i = 0; i < 2; i++) {
        int linear = tid + i * 256;
        int n = linear >> 3, k8 = (linear & 7) << 3;
        __half hh[8];
#pragma unroll
        for (int j = 0; j < 8; j++) hh[j] = __float2half_rn(s[n][k8 + j]);
        int ng = n0 + n, nn = ng;
        if (perm) {
            int j = ng & 63;
            nn = (ng & ~63) | (j < 32 ? (j << 1) : (((j - 32) << 1) | 1));
        }
        *(uint4*)(Th + base + (size_t)nn * K + k0 + k8) = *(uint4*)hh;
    }
}

// ---------------- cp.async 3-stage pipelined fp16 mma.sync GEMM ----------------
#define GSMEM 49152

__device__ __forceinline__ void issue_tile(uint32_t sbase, const __half* __restrict__ g,
                                           int K, int k0, int tid) {
#pragma unroll
    for (int q = 0; q < 2; q++) {
        int i = tid * 2 + q;
        int r = i >> 2, ch = i & 3;
        int sw = ch ^ ((r >> 1) & 3);
        cp_async16(sbase + (uint32_t)(r * 32 + sw * 8) * 2,
                   g + (size_t)r * K + k0 + ch * 8);
    }
}

__device__ __forceinline__ void gemm_mma_body(
    const __half* __restrict__ A, const __half* __restrict__ B,
    float* Cf, __half* Ch, int N, int K, int act, const float2* __restrict__ csn,
    int bx, int by)
{
    extern __shared__ char gsm[];
    uint32_t sb = smem_u32(gsm);
    int tid = threadIdx.x, lane = tid & 31, warp = tid >> 5;
    int wm = (warp & 1) * 64, wn = (warp >> 1) * 32;
    int brow = by * 128, bcol = bx * 128;
    const __half* pA = A + (size_t)brow * K;
    const __half* pB = B + (size_t)bcol * K;

    float acc[4][4][4];
#pragma unroll
    for (int i = 0; i < 4; i++)
#pragma unroll
        for (int j = 0; j < 4; j++)
#pragma unroll
            for (int d = 0; d < 4; d++) acc[i][j][d] = 0.f;

    int g = lane >> 2, t4 = lane & 3;
    int NC = K >> 5;

    issue_tile(sb,        pA, K, 0, tid);
    issue_tile(sb + 8192, pB, K, 0, tid);
    CP_COMMIT();
    if (NC > 1) {
        issue_tile(sb + 16384,        pA, K, 32, tid);
        issue_tile(sb + 16384 + 8192, pB, K, 32, tid);
    }
    CP_COMMIT();

    for (int c = 0; c < NC; c++) {
        if (c + 2 < NC) {
            uint32_t nb = sb + (uint32_t)((c + 2) % 3) * 16384;
            int k0 = (c + 2) << 5;
            issue_tile(nb,        pA, K, k0, tid);
            issue_tile(nb + 8192, pB, K, k0, tid);
        }
        CP_COMMIT();
        CP_WAIT(2);
        __syncthreads();
        const __half* sA = (const __half*)(gsm + (c % 3) * 16384);
        const __half* sB = sA + 4096;
#pragma unroll
        for (int kc = 0; kc < 2; kc++) {
            int cb = kc * 16 + t4 * 2;
            uint32_t bfr[4][2];
#pragma unroll
            for (int tn = 0; tn < 4; tn++) {
                int n = wn + tn * 8 + g;
                bfr[tn][0] = lds_frag(sB, n, cb);
                bfr[tn][1] = lds_frag(sB, n, cb + 8);
            }
#pragma unroll
            for (int tm = 0; tm < 4; tm++) {
                int r = wm + tm * 16 + g;
                uint32_t afr[4];
                afr[0] = lds_frag(sA, r, cb);     afr[1] = lds_frag(sA, r + 8, cb);
                afr[2] = lds_frag(sA, r, cb + 8); afr[3] = lds_frag(sA, r + 8, cb + 8);
#pragma unroll
                for (int tn = 0; tn < 4; tn++)
                    mma16816(acc[tm][tn], afr, bfr[tn]);
            }
        }
        __syncthreads();
    }

#pragma unroll
    for (int tm = 0; tm < 4; tm++) {
        int r = brow + wm + tm * 16 + g;
#pragma unroll
        for (int tn = 0; tn < 4; tn++) {
            int c = bcol + wn + tn * 8 + t4 * 2;
            float v0 = acc[tm][tn][0], v1 = acc[tm][tn][1];
            float v2 = acc[tm][tn][2], v3 = acc[tm][tn][3];
            if (Cf) {
                *(float2*)(Cf + (size_t)r * N + c) = make_float2(v0, v1);
                *(float2*)(Cf + (size_t)(r + 8) * N + c) = make_float2(v2, v3);
            } else if (csn) {
                int jj = (c & 63) >> 1;
                float2 csA = csn[r * 32 + jj];
                float2 csB = csn[(r + 8) * 32 + jj];
                float q0 = v0 * csA.x - v1 * csA.y;
                float q1 = v1 * csA.x + v0 * csA.y;
                float q2 = v2 * csB.x - v3 * csB.y;
                float q3 = v3 * csB.x + v2 * csB.y;
                *(__half2*)(Ch + (size_t)r * N + c) =
                    __halves2half2(__float2half_rn(q0), __float2half_rn(q1));
                *(__half2*)(Ch + (size_t)(r + 8) * N + c) =
                    __halves2half2(__float2half_rn(q2), __float2half_rn(q3));
            } else {
                if (act) { v0 = gelu_f(v0); v1 = gelu_f(v1); v2 = gelu_f(v2); v3 = gelu_f(v3); }
                *(__half2*)(Ch + (size_t)r * N + c) =
                    __halves2half2(__float2half_rn(v0), __float2half_rn(v1));
                *(__half2*)(Ch + (size_t)(r + 8) * N + c) =
                    __halves2half2(__float2half_rn(v2), __float2half_rn(v3));
            }
        }
    }
}

// merged QKV (fused RoPE) + FFN1; compact grid (8, 8, 28)
__global__ void __launch_bounds__(256, 2) gemm_fused1() {
    int z = blockIdx.z;
    if (z < 12) {
        int which = z >> 2, g = z & 3;
        size_t ao = (size_t)(2 * g) * CAP_ * D_;
        size_t wo = (size_t)which * 4194304ull + (size_t)g * 1048576ull;
        if (which == 0)
            gemm_mma_body(g_x + ao, g_wt + wo, (float*)0, g_q + (size_t)g * CAP_ * D_,
                          D_, D_, 0, g_csn + (size_t)g * CAP_ * 32, blockIdx.x, blockIdx.y);
        else if (which == 1)
            gemm_mma_body(g_x + ao, g_wt + wo, (float*)0, g_k + (size_t)g * CAP_ * D_,
                          D_, D_, 0, g_csn + (size_t)g * CAP_ * 32, blockIdx.x, blockIdx.y);
        else
            gemm_mma_body(g_x + ao, g_wt + wo, (float*)0, g_v + (size_t)g * CAP_ * D_,
                          D_, D_, 0, (const float2*)0, blockIdx.x, blockIdx.y);
    } else {
        int zz = z - 12;
        int g = zz >> 2;
        int bx = ((zz & 3) << 3) + blockIdx.x;
        gemm_mma_body(g_x + (size_t)(2 * g + 1) * CAP_ * D_,
                      g_wt + W1_OFF + (size_t)g * D_ * MLP_,
                      (float*)0, g_f + (size_t)g * CAP_ * MLP_,
                      MLP_, D_, 1, (const float2*)0, bx, blockIdx.y);
    }
}

// merged Wo + FFN2
__global__ void __launch_bounds__(256, 2) gemm_fused2() {
    int z = blockIdx.z;
    if (z < 4) {
        int g = z;
        gemm_mma_body(g_a + (size_t)g * CAP_ * D_, g_wt + WO_OFF + (size_t)g * D_ * D_,
                      g_expo + (size_t)(2 * g) * CAP_ * D_, (__half*)0,
                      D_, D_, 0, (const float2*)0, blockIdx.x, blockIdx.y);
    } else {
        int g = z - 4;
        gemm_mma_body(g_f + (size_t)g * CAP_ * MLP_, g_wt + W2_OFF + (size_t)g * MLP_ * D_,
                      g_expo + (size_t)(2 * g + 1) * CAP_ * D_, (__half*)0,
                      D_, MLP_, 0, (const float2*)0, blockIdx.x, blockIdx.y);
    }
}

// ---------------- register-softmax HMMA flash attention ----------------
#define A_Q   0
#define A_K0  16384
#define A_V0  24576
#define A_K1  32768
#define A_V1  40960
#define A_VT  49152
#define ATTN_SMEM 57600

__global__ void __launch_bounds__(256, 2) attn_kernel() {
    int qb = blockIdx.x, hh = blockIdx.y, g = blockIdx.z;
    extern __shared__ char sm[];
    uint32_t sb = smem_u32(sm);
    __half* Qs = (__half*)(sm + A_Q);
    __half* Vt = (__half*)(sm + A_VT);

    int tid = threadIdx.x, lane = tid & 31, warp = tid >> 5;
    int gq = lane >> 2, t4 = lane & 3;
    int wq = warp * 16;

    size_t qoff = ((size_t)(g * CAP_ + qb * 128)) * D_ + hh * 64;
#pragma unroll
    for (int it = 0; it < 4; it++) {
        int idx = tid + it * 256;
        int r = idx >> 3, ch = idx & 7, sw = ch ^ (r & 7);
        cp_async16(sb + A_Q + (uint32_t)(r * 64 + sw * 8) * 2,
                   g_q + qoff + (size_t)r * D_ + ch * 8);
    }
    size_t koff0 = ((size_t)(g * CAP_)) * D_ + hh * 64;
#pragma unroll
    for (int it = 0; it < 2; it++) {
        int idx = tid + it * 256;
        int r = idx >> 3, ch = idx & 7, sw = ch ^ (r & 7);
        uint32_t off = (uint32_t)(r * 64 + sw * 8) * 2;
        cp_async16(sb + A_K0 + off, g_k + koff0 + (size_t)r * D_ + ch * 8);
        cp_async16(sb + A_V0 + off, g_v + koff0 + (size_t)r * D_ + ch * 8);
    }
    CP_COMMIT();

    float m0 = -3.0e38f, m1 = -3.0e38f, l0 = 0.f, l1 = 0.f;
    float o[8][4];
#pragma unroll
    for (int i = 0; i < 8; i++)
#pragma unroll
        for (int j = 0; j < 4; j++) o[i][j] = 0.f;

    for (int kt = 0; kt < 16; kt++) {
        __syncthreads();
        if (kt + 1 < 16) {
            uint32_t kb = sb + (((kt + 1) & 1) ? A_K1 : A_K0);
            uint32_t vb = sb + (((kt + 1) & 1) ? A_V1 : A_V0);
            size_t koff = ((size_t)(g * CAP_ + (kt + 1) * 64)) * D_ + hh * 64;
#pragma unroll
            for (int it = 0; it < 2; it++) {
                int idx = tid + it * 256;
                int r = idx >> 3, ch = idx & 7, sw = ch ^ (r & 7);
                uint32_t off = (uint32_t)(r * 64 + sw * 8) * 2;
                cp_async16(kb + off, g_k + koff + (size_t)r * D_ + ch * 8);
                cp_async16(vb + off, g_v + koff + (size_t)r * D_ + ch * 8);
            }
            CP_COMMIT();
            CP_WAIT(1);
        } else {
            CP_WAIT(0);
        }
        __syncthreads();
        const __half* Ks = (const __half*)(sm + ((kt & 1) ? A_K1 : A_K0));
        const __half* Vs = (const __half*)(sm + ((kt & 1) ? A_V1 : A_V0));

        {
            int r2 = tid >> 3, ch = tid & 7;
            int ka = 2 * r2, kb2 = 2 * r2 + 1;
            uint4 va = *(const uint4*)(Vs + ka * 64 + (ch ^ (ka & 7)) * 8);
            uint4 vb2 = *(const uint4*)(Vs + kb2 * 64 + (ch ^ (kb2 & 7)) * 8);
            const __half* ha = (const __half*)&va;
            const __half* hb = (const __half*)&vb2;
#pragma unroll
            for (int j = 0; j < 8; j++)
                *(__half2*)(Vt + (ch * 8 + j) * 66 + ka) = __halves2half2(ha[j], hb[j]);
        }

        float s[8][4];
#pragma unroll
        for (int i = 0; i < 8; i++)
#pragma unroll
            for (int j = 0; j < 4; j++) s[i][j] = 0.f;
#pragma unroll
        for (int ks = 0; ks < 4; ks++) {
            int cb = ks * 16 + t4 * 2;
            uint32_t afr[4];
            afr[0] = lds_sw64(Qs, wq + gq, cb);     afr[1] = lds_sw64(Qs, wq + gq + 8, cb);
            afr[2] = lds_sw64(Qs, wq + gq, cb + 8); afr[3] = lds_sw64(Qs, wq + gq + 8, cb + 8);
#pragma unroll
            for (int tn = 0; tn < 8; tn++) {
                int n = tn * 8 + gq;
                uint32_t bfr[2];
                bfr[0] = lds_sw64(Ks, n, cb); bfr[1] = lds_sw64(Ks, n, cb + 8);
                mma16816(s[tn], afr, bfr);
            }
        }

        float mx0 = -3.0e38f, mx1 = -3.0e38f;
#pragma unroll
        for (int tn = 0; tn < 8; tn++) {
            s[tn][0] *= 0.125f; s[tn][1] *= 0.125f;
            s[tn][2] *= 0.125f; s[tn][3] *= 0.125f;
            mx0 = fmaxf(mx0, fmaxf(s[tn][0], s[tn][1]));
            mx1 = fmaxf(mx1, fmaxf(s[tn][2], s[tn][3]));
        }
        mx0 = fmaxf(mx0, __shfl_xor_sync(0xffffffffu, mx0, 1));
        mx0 = fmaxf(mx0, __shfl_xor_sync(0xffffffffu, mx0, 2));
        mx1 = fmaxf(mx1, __shfl_xor_sync(0xffffffffu, mx1, 1));
        mx1 = fmaxf(mx1, __shfl_xor_sync(0xffffffffu, mx1, 2));
        float mn0 = fmaxf(m0, mx0), mn1 = fmaxf(m1, mx1);
        float cr0 = __expf(m0 - mn0), cr1 = __expf(m1 - mn1);
        float sum0 = 0.f, sum1 = 0.f;
#pragma unroll
        for (int tn = 0; tn < 8; tn++) {
            s[tn][0] = __expf(s[tn][0] - mn0); s[tn][1] = __expf(s[tn][1] - mn0);
            s[tn][2] = __expf(s[tn][2] - mn1); s[tn][3] = __expf(s[tn][3] - mn1);
            sum0 += s[tn][0] + s[tn][1];
            sum1 += s[tn][2] + s[tn][3];
        }
        sum0 += __shfl_xor_sync(0xffffffffu, sum0, 1);
        sum0 += __shfl_xor_sync(0xffffffffu, sum0, 2);
        sum1 += __shfl_xor_sync(0xffffffffu, sum1, 1);
        sum1 += __shfl_xor_sync(0xffffffffu, sum1, 2);
        l0 = l0 * cr0 + sum0; l1 = l1 * cr1 + sum1;
        m0 = mn0; m1 = mn1;
#pragma unroll
        for (int tn = 0; tn < 8; tn++) {
            o[tn][0] *= cr0; o[tn][1] *= cr0;
            o[tn][2] *= cr1; o[tn][3] *= cr1;
        }

        uint32_t pf[4][4];
#pragma unroll
        for (int ks = 0; ks < 4; ks++) {
            pf[ks][0] = h2_u32(__floats2half2_rn(s[2 * ks][0], s[2 * ks][1]));
            pf[ks][1] = h2_u32(__floats2half2_rn(s[2 * ks][2], s[2 * ks][3]));
            pf[ks][2] = h2_u32(__floats2half2_rn(s[2 * ks + 1][0], s[2 * ks + 1][1]));
            pf[ks][3] = h2_u32(__floats2half2_rn(s[2 * ks + 1][2], s[2 * ks + 1][3]));
        }
        __syncthreads();

#pragma unroll
        for (int ks = 0; ks < 4; ks++) {
#pragma unroll
            for (int tn = 0; tn < 8; tn++) {
                int n = tn * 8 + gq;
                int cb = ks * 16 + t4 * 2;
                uint32_t bfr[2];
                bfr[0] = *(const uint32_t*)(Vt + n * 66 + cb);
                bfr[1] = *(const uint32_t*)(Vt + n * 66 + cb + 8);
                mma16816(o[tn], pf[ks], bfr);
            }
        }
    }

    float inv0 = 1.f / l0, inv1 = 1.f / l1;
    size_t obase = ((size_t)(g * CAP_ + qb * 128)) * D_ + hh * 64;
#pragma unroll
    for (int tn = 0; tn < 8; tn++) {
        int c = tn * 8 + t4 * 2;
        size_t off = obase + (size_t)(wq + gq) * D_ + c;
        *(__half2*)(g_a + off) =
            __halves2half2(__float2half_rn(o[tn][0] * inv0), __float2half_rn(o[tn][1] * inv0));
        off = obase + (size_t)(wq + gq + 8) * D_ + c;
        *(__half2*)(g_a + off) =
            __halves2half2(__float2half_rn(o[tn][2] * inv1), __float2half_rn(o[tn][3] * inv1));
    }
}

// ---------------- fused combine + (router | rmsnorm) ----------------
// 512 blocks x 256 thr; warp per token; h row held in 32 regs/lane (strided).
__global__ void __launch_bounds__(256) comb_router_kernel(
    const float* __restrict__ rw, const float* __restrict__ lnw,
    float* __restrict__ out, int last)
{
    int warp = threadIdx.x >> 5, lane = threadIdx.x & 31;
    int t = blockIdx.x * 8 + warp;

    float we_l = 0.f; int se_l = -1;
    if (lane < 8) { we_l = g_cw[t * 8 + lane]; se_l = g_slotof[lane * T_ + t]; }

    float hv[32];
#pragma unroll
    for (int i = 0; i < 32; i++) hv[i] = g_h[(size_t)t * D_ + lane + 32 * i];

    float rho = 0.f;
#pragma unroll
    for (int e = 0; e < 8; e++) {
        int se = __shfl_sync(0xffffffffu, se_l, e);
        float we = __shfl_sync(0xffffffffu, we_l, e);
        if (se >= 0) rho += we;
    }
    float om = 1.f - rho;
#pragma unroll
    for (int i = 0; i < 32; i++) hv[i] *= om;
#pragma unroll
    for (int e = 0; e < 8; e++) {
        int se = __shfl_sync(0xffffffffu, se_l, e);
        float we = __shfl_sync(0xffffffffu, we_l, e);
        if (se >= 0) {
            const float* ev = g_expo + ((size_t)e * CAP_ + se) * D_ + lane;
#pragma unroll
            for (int i = 0; i < 32; i++) hv[i] = fmaf(we, ev[32 * i], hv[i]);
        }
    }

    if (!last) {
        // write h, then router on in-register h
#pragma unroll
        for (int i = 0; i < 32; i++) g_h[(size_t)t * D_ + lane + 32 * i] = hv[i];
        float acc[9];
#pragma unroll
        for (int e = 0; e < 9; e++) acc[e] = 0.f;
#pragma unroll
        for (int i = 0; i < 32; i++) {
            float hvv = hv[i];
            int d = lane + 32 * i;
#pragma unroll
            for (int e = 0; e < 9; e++) acc[e] = fmaf(hvv, rw[e * D_ + d], acc[e]);
        }
#pragma unroll
        for (int e = 0; e < 9; e++)
#pragma unroll
            for (int o = 16; o > 0; o >>= 1) acc[e] += __shfl_xor_sync(0xffffffffu, acc[e], o);
        if (lane == 0) {
            float mx = acc[0];
#pragma unroll
            for (int e = 1; e < 9; e++) mx = fmaxf(mx, acc[e]);
            float ex[9], s = 0.f;
#pragma unroll
            for (int e = 0; e < 9; e++) { ex[e] = expf(acc[e] - mx); s += ex[e]; }
            float inv = 1.f / s;
            int a1 = 0; float v1 = acc[0];
#pragma unroll
            for (int e = 1; e < 9; e++) if (acc[e] > v1) { v1 = acc[e]; a1 = e; }
            int a2 = -1; float v2 = -3.0e38f;
#pragma unroll
            for (int e = 0; e < 9; e++) if (e != a1 && acc[e] > v2) { v2 = acc[e]; a2 = e; }
            unsigned char m = 0;
            if (a1 < 8) m |= (unsigned char)(1 << a1);
            if (a2 < 8) m |= (unsigned char)(1 << a2);
            g_maskb[t] = m;
#pragma unroll
            for (int e = 0; e < 8; e++) g_probs[t * 8 + e] = ex[e] * inv;
        }
    } else {
        // rmsnorm epilogue
        float ss = 0.f;
#pragma unroll
        for (int i = 0; i < 32; i++) ss += hv[i] * hv[i];
#pragma unroll
        for (int o = 16; o > 0; o >>= 1) ss += __shfl_xor_sync(0xffffffffu, ss, o);
        float sc = rsqrtf(ss / (float)D_ + 1e-6f);
#pragma unroll
        for (int i = 0; i < 32; i++) {
            int d = lane + 32 * i;
            out[(size_t)t * D_ + d] = hv[i] * sc * lnw[d];
        }
    }
}

// ---------------- launch ----------------
extern "C" void kernel_launch(void* const* d_in, const int* in_sizes, int n_in,
                              void* d_out, int out_size) {
    const int*   ids      = (const int*)d_in[0];
    const float* embed_w  = (const float*)d_in[1];
    const float* router_w = (const float*)d_in[2];
    const float* wq       = (const float*)d_in[3];
    const float* wk       = (const float*)d_in[4];
    const float* wv       = (const float*)d_in[5];
    const float* wo       = (const float*)d_in[6];
    const float* w1       = (const float*)d_in[7];
    const float* w2       = (const float*)d_in[8];
    const float* lnw      = (const float*)d_in[9];
    float* out = (float*)d_out;

    __half* p_wt;
    cudaGetSymbolAddress((void**)&p_wt, g_wt);

    cudaFuncSetAttribute(attn_kernel, cudaFuncAttributeMaxDynamicSharedMemorySize, ATTN_SMEM);
    cudaFuncSetAttribute(gemm_fused1, cudaFuncAttributeMaxDynamicSharedMemorySize, GSMEM);
    cudaFuncSetAttribute(gemm_fused2, cudaFuncAttributeMaxDynamicSharedMemorySize, GSMEM);

    wconv_kernel<<<dim3(16, 16, 4), 256>>>(wq, p_wt + WQ_OFF, D_, D_, 1);
    wconv_kernel<<<dim3(16, 16, 4), 256>>>(wk, p_wt + WK_OFF, D_, D_, 1);
    wconv_kernel<<<dim3(16, 16, 4), 256>>>(wv, p_wt + WV_OFF, D_, D_, 0);
    wconv_kernel<<<dim3(16, 16, 4), 256>>>(wo, p_wt + WO_OFF, D_, D_, 0);
    wconv_kernel<<<dim3(64, 16, 4), 256>>>(w1, p_wt + W1_OFF, D_, MLP_, 0);
    wconv_kernel<<<dim3(16, 64, 4), 256>>>(w2, p_wt + W2_OFF, MLP_, D_, 0);

    embed_kernel<<<T_, 256>>>(ids, embed_w);
    router_kernel<<<T_ / 8, 256>>>(router_w);
    for (int hop = 0; hop < 3; hop++) {
        capacity_kernel<<<E_, 1024>>>();
        gather_kernel<<<E_ * CAP_, 256>>>();
        gemm_fused1<<<dim3(8, 8, 28), 256, GSMEM>>>();
        attn_kernel<<<dim3(8, 16, 4), 256, ATTN_SMEM>>>();
        gemm_fused2<<<dim3(8, 8, 8), 256, GSMEM>>>();
        if (hop < 2)
            comb_router_kernel<<<T_ / 8, 256>>>(
                router_w + (size_t)(hop + 1) * 9 * D_, (const float*)0, (float*)0, 0);
        else
            comb_router_kernel<<<T_ / 8, 256>>>(
                (const float*)0, lnw, out, 1);
    }
}